// round 1
// baseline (speedup 1.0000x reference)
#include <cuda_runtime.h>
#include <cuda_bf16.h>
#include <math_constants.h>

// ---------------------------------------------------------------------------
// GraphTransformerModel: 2x TransformerConv (H=4, C=32, concat=False) + Linear
// N=50000, E=800000, D=128, HID=32, OUT=40  (sizes derived from in_sizes)
// ---------------------------------------------------------------------------

#define NMAX 50000
#define EMAX 800000
#define HEADS 4
#define CPH 32            // channels per head
#define FDIM 128          // HEADS*CPH

// ---- static device scratch (no allocations allowed) ----
__device__ float g_Q[NMAX * FDIM];
__device__ float g_K[NMAX * FDIM];
__device__ float g_V[NMAX * FDIM];
__device__ float g_agg[NMAX * FDIM];
__device__ float g_skip[NMAX * CPH];
__device__ float g_h1[NMAX * CPH];
__device__ float g_h2[NMAX * CPH];
__device__ float g_elog[EMAX * HEADS];
__device__ float g_m[NMAX * HEADS];
__device__ float g_den[NMAX * HEADS];
__device__ int   g_src[EMAX];
__device__ int   g_dst[EMAX];
__device__ int   g_is32;

// ---------------------------------------------------------------------------
// edge_index dtype detection: int64 (lo,hi) pairs have all-zero odd words
// because node ids < 50000. int32 data has random ids at odd positions.
// ---------------------------------------------------------------------------
__global__ void reset_flag_kernel() { g_is32 = 0; }

__global__ void detect_dtype_kernel(const unsigned int* __restrict__ w, int nwords) {
    int i = blockIdx.x * blockDim.x + threadIdx.x;
    if (i < nwords && (i & 1) && w[i] != 0u) g_is32 = 1;
}

__global__ void convert_edges_kernel(const void* __restrict__ ei, int E) {
    int e = blockIdx.x * blockDim.x + threadIdx.x;
    if (e >= E) return;
    if (g_is32) {
        const int* p = (const int*)ei;
        g_src[e] = p[e];
        g_dst[e] = p[E + e];
    } else {
        const long long* p = (const long long*)ei;
        g_src[e] = (int)p[e];
        g_dst[e] = (int)p[E + e];
    }
}

// ---------------------------------------------------------------------------
// Generic SGEMM with bias: C[N,M] = A[N,K] @ B[K,M] + bias[M]
// 64x64 tile, BK=16, 256 threads, 4x4 per-thread microtile.
// K is always a multiple of 16 here (32 or 128).
// ---------------------------------------------------------------------------
#define BM 64
#define BN 64
#define BK 16

__global__ __launch_bounds__(256)
void sgemm_bias_kernel(const float* __restrict__ A, const float* __restrict__ B,
                       const float* __restrict__ bias, float* __restrict__ C,
                       int N, int K, int M) {
    __shared__ float As[BK][BM];
    __shared__ float Bs[BK][BN];

    const int tid  = threadIdx.x;
    const int row0 = blockIdx.x * BM;
    const int col0 = blockIdx.y * BN;
    const int tr   = (tid >> 4) << 2;   // 0..60
    const int tc   = (tid & 15) << 2;   // 0..60

    float acc[4][4] = {};

    for (int k0 = 0; k0 < K; k0 += BK) {
        #pragma unroll
        for (int i = tid; i < BM * BK; i += 256) {
            int r = i / BK, c = i % BK;
            float v = 0.f;
            int gr = row0 + r;
            if (gr < N) v = A[(size_t)gr * K + (k0 + c)];
            As[c][r] = v;
        }
        #pragma unroll
        for (int i = tid; i < BK * BN; i += 256) {
            int r = i / BN, c = i % BN;
            float v = 0.f;
            int gc = col0 + c;
            if (gc < M) v = B[(size_t)(k0 + r) * M + gc];
            Bs[r][c] = v;
        }
        __syncthreads();

        #pragma unroll
        for (int kk = 0; kk < BK; kk++) {
            float a[4], b[4];
            #pragma unroll
            for (int i = 0; i < 4; i++) a[i] = As[kk][tr + i];
            #pragma unroll
            for (int j = 0; j < 4; j++) b[j] = Bs[kk][tc + j];
            #pragma unroll
            for (int i = 0; i < 4; i++)
                #pragma unroll
                for (int j = 0; j < 4; j++)
                    acc[i][j] += a[i] * b[j];
        }
        __syncthreads();
    }

    #pragma unroll
    for (int i = 0; i < 4; i++) {
        int r = row0 + tr + i;
        if (r >= N) continue;
        #pragma unroll
        for (int j = 0; j < 4; j++) {
            int c = col0 + tc + j;
            if (c < M) C[(size_t)r * M + c] = acc[i][j] + bias[c];
        }
    }
}

// ---------------------------------------------------------------------------
// Per-layer attention kernels
// ---------------------------------------------------------------------------
__global__ void init_softmax_state_kernel(int N) {
    int i = blockIdx.x * blockDim.x + threadIdx.x;
    if (i < N * HEADS) {
        g_m[i]   = -CUDART_INF_F;
        g_den[i] = 0.f;
    }
}

__global__ void zero_kernel(float* __restrict__ p, int n) {
    int i = blockIdx.x * blockDim.x + threadIdx.x;
    int stride = gridDim.x * blockDim.x;
    for (; i < n; i += stride) p[i] = 0.f;
}

__device__ __forceinline__ void atomicMaxF(float* addr, float val) {
    if (val >= 0.f) atomicMax((int*)addr, __float_as_int(val));
    else            atomicMin((unsigned int*)addr, __float_as_uint(val));
}

// one warp per edge; 4 head-dots of length 32 via float4 + 8-lane reduce
__global__ __launch_bounds__(256)
void edge_logits_kernel(int E) {
    int warp = (blockIdx.x * blockDim.x + threadIdx.x) >> 5;
    if (warp >= E) return;
    int lane = threadIdx.x & 31;
    int s = g_src[warp];
    int d = g_dst[warp];

    float4 q = *reinterpret_cast<const float4*>(g_Q + (size_t)d * FDIM + lane * 4);
    float4 k = *reinterpret_cast<const float4*>(g_K + (size_t)s * FDIM + lane * 4);
    float p = q.x * k.x + q.y * k.y + q.z * k.z + q.w * k.w;
    p += __shfl_xor_sync(0xffffffffu, p, 4);
    p += __shfl_xor_sync(0xffffffffu, p, 2);
    p += __shfl_xor_sync(0xffffffffu, p, 1);

    if ((lane & 7) == 0) {
        int h = lane >> 3;
        float logit = p * 0.17677669529663687f;  // 1/sqrt(32)
        g_elog[(size_t)warp * HEADS + h] = logit;
        atomicMaxF(&g_m[d * HEADS + h], logit);
    }
}

// one thread per (edge, head)
__global__ void edge_exp_kernel(int E) {
    int i = blockIdx.x * blockDim.x + threadIdx.x;
    if (i >= E * HEADS) return;
    int e = i >> 2;
    int h = i & 3;
    int d = g_dst[e];
    float v = __expf(g_elog[i] - g_m[d * HEADS + h]);
    g_elog[i] = v;
    atomicAdd(&g_den[d * HEADS + h], v);
}

// one warp per edge: agg[dst] += alpha * v[src]  (128 floats)
__global__ __launch_bounds__(256)
void edge_aggregate_kernel(int E) {
    int warp = (blockIdx.x * blockDim.x + threadIdx.x) >> 5;
    if (warp >= E) return;
    int lane = threadIdx.x & 31;
    int s = g_src[warp];
    int d = g_dst[warp];
    int h = lane >> 3;

    float alpha = g_elog[(size_t)warp * HEADS + h] /
                  (g_den[d * HEADS + h] + 1e-16f);
    float4 v = *reinterpret_cast<const float4*>(g_V + (size_t)s * FDIM + lane * 4);
    float* o = g_agg + (size_t)d * FDIM + lane * 4;
    atomicAdd(o + 0, alpha * v.x);
    atomicAdd(o + 1, alpha * v.y);
    atomicAdd(o + 2, alpha * v.z);
    atomicAdd(o + 3, alpha * v.w);
}

// h_out[n,c] = relu( mean_h agg[n,h,c] + skip[n,c] )
__global__ void finalize_kernel(float* __restrict__ out, int N) {
    int i = blockIdx.x * blockDim.x + threadIdx.x;
    if (i >= N * CPH) return;
    int n = i >> 5;
    int c = i & 31;
    const float* a = g_agg + (size_t)n * FDIM;
    float v = (a[c] + a[c + 32] + a[c + 64] + a[c + 96]) * 0.25f
              + g_skip[(size_t)n * CPH + c];
    out[i] = fmaxf(v, 0.f);
}

// ---------------------------------------------------------------------------
// Host orchestration
// ---------------------------------------------------------------------------
static inline unsigned int ceil_div(unsigned int a, unsigned int b) { return (a + b - 1) / b; }

static void run_layer(const float* X, int Kdim,
                      const float* wq, const float* bq,
                      const float* wk, const float* bk,
                      const float* wv, const float* bv,
                      const float* ws, const float* bs,
                      float* Qp, float* Kp, float* Vp, float* skipp,
                      float* aggp, float* hout, int N, int E) {
    dim3 g128(ceil_div(N, BM), ceil_div(FDIM, BN));
    dim3 g32(ceil_div(N, BM), 1);
    sgemm_bias_kernel<<<g128, 256>>>(X, wq, bq, Qp, N, Kdim, FDIM);
    sgemm_bias_kernel<<<g128, 256>>>(X, wk, bk, Kp, N, Kdim, FDIM);
    sgemm_bias_kernel<<<g128, 256>>>(X, wv, bv, Vp, N, Kdim, FDIM);
    sgemm_bias_kernel<<<g32, 256>>>(X, ws, bs, skipp, N, Kdim, CPH);

    init_softmax_state_kernel<<<ceil_div(N * HEADS, 256), 256>>>(N);
    zero_kernel<<<1024, 256>>>(aggp, N * FDIM);

    edge_logits_kernel<<<ceil_div(E, 8), 256>>>(E);        // 8 warps/block
    edge_exp_kernel<<<ceil_div(E * HEADS, 256), 256>>>(E);
    edge_aggregate_kernel<<<ceil_div(E, 8), 256>>>(E);

    finalize_kernel<<<ceil_div(N * CPH, 256), 256>>>(hout, N);
}

extern "C" void kernel_launch(void* const* d_in, const int* in_sizes, int n_in,
                              void* d_out, int out_size) {
    const float* x   = (const float*)d_in[0];
    const void*  ei  = d_in[1];
    const float* wq1 = (const float*)d_in[2];
    const float* bq1 = (const float*)d_in[3];
    const float* wk1 = (const float*)d_in[4];
    const float* bk1 = (const float*)d_in[5];
    const float* wv1 = (const float*)d_in[6];
    const float* bv1 = (const float*)d_in[7];
    const float* ws1 = (const float*)d_in[8];
    const float* bs1 = (const float*)d_in[9];
    const float* wq2 = (const float*)d_in[10];
    const float* bq2 = (const float*)d_in[11];
    const float* wk2 = (const float*)d_in[12];
    const float* bk2 = (const float*)d_in[13];
    const float* wv2 = (const float*)d_in[14];
    const float* bv2 = (const float*)d_in[15];
    const float* ws2 = (const float*)d_in[16];
    const float* bs2 = (const float*)d_in[17];
    const float* wc  = (const float*)d_in[18];
    const float* bc  = (const float*)d_in[19];

    const int N = in_sizes[0] / FDIM;   // x is [N,128]
    const int E = in_sizes[1] / 2;      // edge_index is [2,E]

    // fetch scratch addresses (no allocation; symbols are static)
    float *Qp, *Kp, *Vp, *aggp, *skipp, *h1p, *h2p;
    cudaGetSymbolAddress((void**)&Qp,    g_Q);
    cudaGetSymbolAddress((void**)&Kp,    g_K);
    cudaGetSymbolAddress((void**)&Vp,    g_V);
    cudaGetSymbolAddress((void**)&aggp,  g_agg);
    cudaGetSymbolAddress((void**)&skipp, g_skip);
    cudaGetSymbolAddress((void**)&h1p,   g_h1);
    cudaGetSymbolAddress((void**)&h2p,   g_h2);

    // normalize edge index (handles int32 or int64 storage)
    reset_flag_kernel<<<1, 1>>>();
    detect_dtype_kernel<<<ceil_div(2u * E, 256u), 256>>>((const unsigned int*)ei, 2 * E);
    convert_edges_kernel<<<ceil_div((unsigned)E, 256u), 256>>>(ei, E);

    // layer 1: input x [N,128]
    run_layer(x, FDIM, wq1, bq1, wk1, bk1, wv1, bv1, ws1, bs1,
              Qp, Kp, Vp, skipp, aggp, h1p, N, E);
    // layer 2: input h1 [N,32]
    run_layer(h1p, CPH, wq2, bq2, wk2, bk2, wv2, bv2, ws2, bs2,
              Qp, Kp, Vp, skipp, aggp, h2p, N, E);

    // classifier: out[N,40] = h2 @ wc + bc
    dim3 gc(ceil_div((unsigned)N, BM), 1);
    sgemm_bias_kernel<<<gc, 256>>>(h2p, wc, bc, (float*)d_out, N, CPH, 40);
}

// round 2
// speedup vs baseline: 2.0535x; 2.0535x over previous
#include <cuda_runtime.h>
#include <cuda_bf16.h>
#include <math_constants.h>

// ---------------------------------------------------------------------------
// GraphTransformerModel: 2x TransformerConv (H=4, C=32, concat=False) + Linear
// N=50000, E=800000, D=128, HID=32, OUT=40
// Round 2: CSR-based fused attention (no float atomics), 128x128 QKV GEMM.
// ---------------------------------------------------------------------------

#define NMAX 50000
#define EMAX 800000
#define HEADS 4
#define CPH 32            // channels per head
#define FDIM 128          // HEADS*CPH

// ---- static device scratch (no allocations allowed) ----
__device__ float g_Q[NMAX * FDIM];
__device__ float g_K[NMAX * FDIM];
__device__ float g_V[NMAX * FDIM];
__device__ float g_skip[NMAX * CPH];
__device__ float g_h1[NMAX * CPH];
__device__ float g_h2[NMAX * CPH];
__device__ float g_ew[(size_t)EMAX * HEADS];  // per-edge per-head logits (CSR order)
__device__ int   g_src[EMAX];
__device__ int   g_dst[EMAX];
__device__ int   g_csr_src[EMAX];
__device__ int   g_deg[NMAX];
__device__ int   g_off[NMAX + 1];
__device__ int   g_cur[NMAX];
__device__ int   g_is32;

// ---------------------------------------------------------------------------
// edge_index dtype detection: int64 (lo,hi) pairs have all-zero odd words
// (node ids < 50000); int32 data has random ids at odd positions.
// ---------------------------------------------------------------------------
__global__ void reset_flag_kernel() { g_is32 = 0; }

__global__ void detect_dtype_kernel(const unsigned int* __restrict__ w, int nwords) {
    int i = blockIdx.x * blockDim.x + threadIdx.x;
    if (i < nwords && (i & 1) && w[i] != 0u) g_is32 = 1;
}

__global__ void zero_deg_kernel(int N) {
    int i = blockIdx.x * blockDim.x + threadIdx.x;
    if (i < N) g_deg[i] = 0;
}

// convert to int32 src/dst and histogram destinations
__global__ void convert_edges_kernel(const void* __restrict__ ei, int E) {
    int e = blockIdx.x * blockDim.x + threadIdx.x;
    if (e >= E) return;
    int s, d;
    if (g_is32) {
        const int* p = (const int*)ei;
        s = p[e];
        d = p[E + e];
    } else {
        const long long* p = (const long long*)ei;
        s = (int)p[e];
        d = (int)p[E + e];
    }
    g_src[e] = s;
    g_dst[e] = d;
    atomicAdd(&g_deg[d], 1);
}

// single-block exclusive scan of g_deg -> g_off, g_cur; g_off[N] = total
__global__ __launch_bounds__(1024)
void scan_kernel(int N) {
    __shared__ int sh[1024];
    int t = threadIdx.x;
    int chunk = (N + 1023) >> 10;
    int b = t * chunk;
    int e2 = b + chunk; if (e2 > N) e2 = N;
    int sum = 0;
    for (int i = b; i < e2; i++) sum += g_deg[i];
    sh[t] = sum;
    __syncthreads();
    // Hillis-Steele inclusive scan
    for (int dd = 1; dd < 1024; dd <<= 1) {
        int v = (t >= dd) ? sh[t - dd] : 0;
        __syncthreads();
        sh[t] += v;
        __syncthreads();
    }
    int run = sh[t] - sum;  // exclusive prefix for this chunk
    for (int i = b; i < e2; i++) {
        g_off[i] = run;
        g_cur[i] = run;
        run += g_deg[i];
    }
    if (t == 1023) g_off[N] = sh[1023];
}

__global__ void scatter_kernel(int E) {
    int e = blockIdx.x * blockDim.x + threadIdx.x;
    if (e >= E) return;
    int d = g_dst[e];
    int p = atomicAdd(&g_cur[d], 1);
    g_csr_src[p] = g_src[e];
}

// ---------------------------------------------------------------------------
// QKV GEMM: C[N,128] = A[N,K] @ B[K,128] + bias, three matrices per launch
// (blockIdx.y in {0,1,2}). 128x128 tile, BK=16, 256 threads, 8x8 microtile.
// ---------------------------------------------------------------------------
__global__ __launch_bounds__(256)
void qkv_gemm_kernel(const float* __restrict__ A,
                     const float* __restrict__ Bq, const float* __restrict__ Bk,
                     const float* __restrict__ Bv,
                     const float* __restrict__ bq, const float* __restrict__ bk,
                     const float* __restrict__ bv,
                     float* __restrict__ Cq, float* __restrict__ Ck,
                     float* __restrict__ Cv,
                     int N, int Kdim) {
    const float* B;
    const float* bias;
    float* C;
    if (blockIdx.y == 0)      { B = Bq; bias = bq; C = Cq; }
    else if (blockIdx.y == 1) { B = Bk; bias = bk; C = Ck; }
    else                      { B = Bv; bias = bv; C = Cv; }

    __shared__ float As[16][128];
    __shared__ float Bs[16][128];

    const int tid  = threadIdx.x;
    const int row0 = blockIdx.x * 128;
    const int tx   = tid & 15;
    const int ty   = tid >> 4;

    float acc[8][8] = {};

    for (int k0 = 0; k0 < Kdim; k0 += 16) {
        // A tile: 128 rows x 16 cols -> As[k][m]
        #pragma unroll
        for (int j = 0; j < 2; j++) {
            int f  = tid * 2 + j;      // 0..511
            int r  = f >> 2;           // 0..127
            int kq = f & 3;            // 0..3
            int gr = row0 + r;
            if (gr > N - 1) gr = N - 1;
            float4 a4 = *(const float4*)(A + (size_t)gr * Kdim + k0 + kq * 4);
            As[kq * 4 + 0][r] = a4.x;
            As[kq * 4 + 1][r] = a4.y;
            As[kq * 4 + 2][r] = a4.z;
            As[kq * 4 + 3][r] = a4.w;
        }
        // B tile: 16 rows x 128 cols
        #pragma unroll
        for (int j = 0; j < 2; j++) {
            int f  = tid * 2 + j;
            int kr = f >> 5;           // 0..15
            int c4 = f & 31;           // 0..31
            float4 b4 = *(const float4*)(B + (size_t)(k0 + kr) * 128 + c4 * 4);
            *(float4*)&Bs[kr][c4 * 4] = b4;
        }
        __syncthreads();

        #pragma unroll
        for (int kk = 0; kk < 16; kk++) {
            float a[8], b[8];
            *(float4*)&a[0] = *(const float4*)&As[kk][ty * 8];
            *(float4*)&a[4] = *(const float4*)&As[kk][ty * 8 + 4];
            *(float4*)&b[0] = *(const float4*)&Bs[kk][tx * 8];
            *(float4*)&b[4] = *(const float4*)&Bs[kk][tx * 8 + 4];
            #pragma unroll
            for (int i = 0; i < 8; i++)
                #pragma unroll
                for (int jj = 0; jj < 8; jj++)
                    acc[i][jj] += a[i] * b[jj];
        }
        __syncthreads();
    }

    float bsv[8];
    *(float4*)&bsv[0] = *(const float4*)(bias + tx * 8);
    *(float4*)&bsv[4] = *(const float4*)(bias + tx * 8 + 4);
    #pragma unroll
    for (int i = 0; i < 8; i++) {
        int r = row0 + ty * 8 + i;
        if (r < N) {
            float4 o0, o1;
            o0.x = acc[i][0] + bsv[0];
            o0.y = acc[i][1] + bsv[1];
            o0.z = acc[i][2] + bsv[2];
            o0.w = acc[i][3] + bsv[3];
            o1.x = acc[i][4] + bsv[4];
            o1.y = acc[i][5] + bsv[5];
            o1.z = acc[i][6] + bsv[6];
            o1.w = acc[i][7] + bsv[7];
            *(float4*)(C + (size_t)r * 128 + tx * 8)     = o0;
            *(float4*)(C + (size_t)r * 128 + tx * 8 + 4) = o1;
        }
    }
}

// ---------------------------------------------------------------------------
// Generic small SGEMM with bias (used for skip M=32 and classifier M=40)
// ---------------------------------------------------------------------------
#define BM 64
#define BN 64
#define BK 16

__global__ __launch_bounds__(256)
void sgemm_bias_kernel(const float* __restrict__ A, const float* __restrict__ B,
                       const float* __restrict__ bias, float* __restrict__ C,
                       int N, int K, int M) {
    __shared__ float As[BK][BM];
    __shared__ float Bs[BK][BN];

    const int tid  = threadIdx.x;
    const int row0 = blockIdx.x * BM;
    const int col0 = blockIdx.y * BN;
    const int tr   = (tid >> 4) << 2;
    const int tc   = (tid & 15) << 2;

    float acc[4][4] = {};

    for (int k0 = 0; k0 < K; k0 += BK) {
        #pragma unroll
        for (int i = tid; i < BM * BK; i += 256) {
            int r = i / BK, c = i % BK;
            float v = 0.f;
            int gr = row0 + r;
            if (gr < N) v = A[(size_t)gr * K + (k0 + c)];
            As[c][r] = v;
        }
        #pragma unroll
        for (int i = tid; i < BK * BN; i += 256) {
            int r = i / BN, c = i % BN;
            float v = 0.f;
            int gc = col0 + c;
            if (gc < M) v = B[(size_t)(k0 + r) * M + gc];
            Bs[r][c] = v;
        }
        __syncthreads();

        #pragma unroll
        for (int kk = 0; kk < BK; kk++) {
            float a[4], b[4];
            #pragma unroll
            for (int i = 0; i < 4; i++) a[i] = As[kk][tr + i];
            #pragma unroll
            for (int j = 0; j < 4; j++) b[j] = Bs[kk][tc + j];
            #pragma unroll
            for (int i = 0; i < 4; i++)
                #pragma unroll
                for (int j = 0; j < 4; j++)
                    acc[i][j] += a[i] * b[j];
        }
        __syncthreads();
    }

    #pragma unroll
    for (int i = 0; i < 4; i++) {
        int r = row0 + tr + i;
        if (r >= N) continue;
        #pragma unroll
        for (int j = 0; j < 4; j++) {
            int c = col0 + tc + j;
            if (c < M) C[(size_t)r * M + c] = acc[i][j] + bias[c];
        }
    }
}

// ---------------------------------------------------------------------------
// Fused attention: one warp per destination node.
//   pass1: logits over incoming edges (q in regs, gather K[src]); online
//          softmax max/denominator in registers; store logits.
//   pass2: alpha = exp(logit - m)/den; acc += alpha * V[src]  (regs)
//   epilogue: head-mean + skip + relu -> out[N,32]
// Lane l handles head l/8, channels 4*(l%8)..+3.
// ---------------------------------------------------------------------------
__global__ __launch_bounds__(256)
void attn_fused_kernel(const float* __restrict__ Q, const float* __restrict__ K,
                       const float* __restrict__ V, const float* __restrict__ skip,
                       float* __restrict__ out, int N) {
    int warp = (blockIdx.x * blockDim.x + threadIdx.x) >> 5;
    if (warp >= N) return;
    const int lane = threadIdx.x & 31;
    const int n = warp;
    const int beg = g_off[n];
    const int end = g_off[n + 1];

    const float4 q = *(const float4*)(Q + (size_t)n * FDIM + lane * 4);

    float m = -CUDART_INF_F;
    float den = 0.f;

    for (int p = beg; p < end; p++) {
        int s = g_csr_src[p];
        float4 k4 = *(const float4*)(K + (size_t)s * FDIM + lane * 4);
        float d = q.x * k4.x + q.y * k4.y + q.z * k4.z + q.w * k4.w;
        d += __shfl_xor_sync(0xffffffffu, d, 4);
        d += __shfl_xor_sync(0xffffffffu, d, 2);
        d += __shfl_xor_sync(0xffffffffu, d, 1);
        float logit = d * 0.17677669529663687f;   // 1/sqrt(32)
        if ((lane & 7) == 0)
            g_ew[(size_t)p * HEADS + (lane >> 3)] = logit;
        if (logit > m) {
            den *= __expf(m - logit);  // exp(-inf)=0 on first edge -> den stays 0
            m = logit;
        }
        den += __expf(logit - m);
    }

    const float rden = 1.f / (den + 1e-16f);
    float a0 = 0.f, a1 = 0.f, a2 = 0.f, a3 = 0.f;

    for (int p = beg; p < end; p++) {
        int s = g_csr_src[p];
        float logit = g_ew[(size_t)p * HEADS + (lane >> 3)];
        float alpha = __expf(logit - m) * rden;
        float4 v4 = *(const float4*)(V + (size_t)s * FDIM + lane * 4);
        a0 += alpha * v4.x;
        a1 += alpha * v4.y;
        a2 += alpha * v4.z;
        a3 += alpha * v4.w;
    }

    // head mean: sum over the 4 heads (lanes l, l^8, l^16, l^24 share channels)
    #pragma unroll
    for (int dd = 8; dd <= 16; dd <<= 1) {
        a0 += __shfl_xor_sync(0xffffffffu, a0, dd);
        a1 += __shfl_xor_sync(0xffffffffu, a1, dd);
        a2 += __shfl_xor_sync(0xffffffffu, a2, dd);
        a3 += __shfl_xor_sync(0xffffffffu, a3, dd);
    }

    if (lane < 8) {
        float4 sk = *(const float4*)(skip + (size_t)n * CPH + lane * 4);
        float4 o;
        o.x = fmaxf(a0 * 0.25f + sk.x, 0.f);
        o.y = fmaxf(a1 * 0.25f + sk.y, 0.f);
        o.z = fmaxf(a2 * 0.25f + sk.z, 0.f);
        o.w = fmaxf(a3 * 0.25f + sk.w, 0.f);
        *(float4*)(out + (size_t)n * CPH + lane * 4) = o;
    }
}

// ---------------------------------------------------------------------------
// Host orchestration
// ---------------------------------------------------------------------------
static inline unsigned int ceil_div(unsigned int a, unsigned int b) { return (a + b - 1) / b; }

static void run_layer(const float* X, int Kdim,
                      const float* wq, const float* bq,
                      const float* wk, const float* bk,
                      const float* wv, const float* bv,
                      const float* ws, const float* bs,
                      float* Qp, float* Kp, float* Vp, float* skipp,
                      float* hout, int N, int E) {
    dim3 gq(ceil_div(N, 128), 3);
    qkv_gemm_kernel<<<gq, 256>>>(X, wq, wk, wv, bq, bk, bv, Qp, Kp, Vp, N, Kdim);
    dim3 gs(ceil_div(N, BM), 1);
    sgemm_bias_kernel<<<gs, 256>>>(X, ws, bs, skipp, N, Kdim, CPH);

    attn_fused_kernel<<<ceil_div(N, 8), 256>>>(Qp, Kp, Vp, skipp, hout, N);
}

extern "C" void kernel_launch(void* const* d_in, const int* in_sizes, int n_in,
                              void* d_out, int out_size) {
    const float* x   = (const float*)d_in[0];
    const void*  ei  = d_in[1];
    const float* wq1 = (const float*)d_in[2];
    const float* bq1 = (const float*)d_in[3];
    const float* wk1 = (const float*)d_in[4];
    const float* bk1 = (const float*)d_in[5];
    const float* wv1 = (const float*)d_in[6];
    const float* bv1 = (const float*)d_in[7];
    const float* ws1 = (const float*)d_in[8];
    const float* bs1 = (const float*)d_in[9];
    const float* wq2 = (const float*)d_in[10];
    const float* bq2 = (const float*)d_in[11];
    const float* wk2 = (const float*)d_in[12];
    const float* bk2 = (const float*)d_in[13];
    const float* wv2 = (const float*)d_in[14];
    const float* bv2 = (const float*)d_in[15];
    const float* ws2 = (const float*)d_in[16];
    const float* bs2 = (const float*)d_in[17];
    const float* wc  = (const float*)d_in[18];
    const float* bc  = (const float*)d_in[19];

    const int N = in_sizes[0] / FDIM;   // x is [N,128]
    const int E = in_sizes[1] / 2;      // edge_index is [2,E]

    float *Qp, *Kp, *Vp, *skipp, *h1p, *h2p;
    cudaGetSymbolAddress((void**)&Qp,    g_Q);
    cudaGetSymbolAddress((void**)&Kp,    g_K);
    cudaGetSymbolAddress((void**)&Vp,    g_V);
    cudaGetSymbolAddress((void**)&skipp, g_skip);
    cudaGetSymbolAddress((void**)&h1p,   g_h1);
    cudaGetSymbolAddress((void**)&h2p,   g_h2);

    // normalize edge index (int32 or int64 storage) + build dst-CSR once
    reset_flag_kernel<<<1, 1>>>();
    detect_dtype_kernel<<<ceil_div(2u * E, 256u), 256>>>((const unsigned int*)ei, 2 * E);
    zero_deg_kernel<<<ceil_div((unsigned)N, 256u), 256>>>(N);
    convert_edges_kernel<<<ceil_div((unsigned)E, 256u), 256>>>(ei, E);
    scan_kernel<<<1, 1024>>>(N);
    scatter_kernel<<<ceil_div((unsigned)E, 256u), 256>>>(E);

    // layer 1: input x [N,128]
    run_layer(x, FDIM, wq1, bq1, wk1, bk1, wv1, bv1, ws1, bs1,
              Qp, Kp, Vp, skipp, h1p, N, E);
    // layer 2: input h1 [N,32]
    run_layer(h1p, CPH, wq2, bq2, wk2, bk2, wv2, bv2, ws2, bs2,
              Qp, Kp, Vp, skipp, h2p, N, E);

    // classifier: out[N,40] = h2 @ wc + bc
    dim3 gc(ceil_div((unsigned)N, BM), 1);
    sgemm_bias_kernel<<<gc, 256>>>(h2p, wc, bc, (float*)d_out, N, CPH, 40);
}

// round 3
// speedup vs baseline: 2.3016x; 1.1208x over previous
#include <cuda_runtime.h>
#include <cuda_bf16.h>
#include <math_constants.h>

// ---------------------------------------------------------------------------
// GraphTransformerModel: 2x TransformerConv (H=4, C=32, concat=False) + Linear
// N=50000, E=800000, D=128, HID=32, OUT=40
// Round 3: single-pass flash attention, packed KV, double-buffered QKV GEMM.
// ---------------------------------------------------------------------------

#define NMAX 50000
#define EMAX 800000
#define HEADS 4
#define CPH 32            // channels per head
#define FDIM 128          // HEADS*CPH

// ---- static device scratch (no allocations allowed) ----
__device__ float g_Q[NMAX * FDIM];
__device__ float g_KV[(size_t)NMAX * 256];   // K row (128) | V row (128), packed
__device__ float g_skip[NMAX * CPH];
__device__ float g_h1[NMAX * CPH];
__device__ float g_h2[NMAX * CPH];
__device__ int   g_src[EMAX];
__device__ int   g_dst[EMAX];
__device__ int   g_csr_src[EMAX];
__device__ int   g_deg[NMAX];
__device__ int   g_off[NMAX + 1];
__device__ int   g_cur[NMAX];
__device__ int   g_is32;

// ---------------------------------------------------------------------------
// Preprocessing: edge dtype detect + CSR build (runs every call; deterministic)
// ---------------------------------------------------------------------------
__global__ void init_pre_kernel(int N) {
    int i = blockIdx.x * blockDim.x + threadIdx.x;
    if (i == 0) g_is32 = 0;
    if (i < N) g_deg[i] = 0;
}

// int64 little-endian: odd 32-bit words are zero (ids < 50000); int32: random
__global__ void detect_dtype_kernel(const uint2* __restrict__ w, int npairs) {
    int i = blockIdx.x * blockDim.x + threadIdx.x;
    int stride = gridDim.x * blockDim.x;
    for (; i < npairs; i += stride)
        if (w[i].y != 0u) { g_is32 = 1; break; }
}

__global__ void convert_edges_kernel(const void* __restrict__ ei, int E) {
    int e = blockIdx.x * blockDim.x + threadIdx.x;
    if (e >= E) return;
    int s, d;
    if (g_is32) {
        const int* p = (const int*)ei;
        s = p[e];
        d = p[E + e];
    } else {
        const long long* p = (const long long*)ei;
        s = (int)p[e];
        d = (int)p[E + e];
    }
    g_src[e] = s;
    g_dst[e] = d;
    atomicAdd(&g_deg[d], 1);
}

// single-block exclusive scan of g_deg -> g_off, g_cur; g_off[N] = total
__global__ __launch_bounds__(1024)
void scan_kernel(int N) {
    __shared__ int sh[1024];
    int t = threadIdx.x;
    int chunk = (N + 1023) >> 10;
    int b = t * chunk;
    int e2 = b + chunk; if (e2 > N) e2 = N;
    int sum = 0;
    for (int i = b; i < e2; i++) sum += g_deg[i];
    sh[t] = sum;
    __syncthreads();
    for (int dd = 1; dd < 1024; dd <<= 1) {
        int v = (t >= dd) ? sh[t - dd] : 0;
        __syncthreads();
        sh[t] += v;
        __syncthreads();
    }
    int run = sh[t] - sum;
    for (int i = b; i < e2; i++) {
        g_off[i] = run;
        g_cur[i] = run;
        run += g_deg[i];
    }
    if (t == 1023) g_off[N] = sh[1023];
}

__global__ void scatter_kernel(int E) {
    int e = blockIdx.x * blockDim.x + threadIdx.x;
    if (e >= E) return;
    int d = g_dst[e];
    int p = atomicAdd(&g_cur[d], 1);
    g_csr_src[p] = g_src[e];
}

// ---------------------------------------------------------------------------
// QKV GEMM, double-buffered: 128x128 tile, BK=16, 256 threads, 8x8 microtile.
// blockIdx.y selects Q (stride 128) / K (KV+0, stride 256) / V (KV+128, 256).
// ---------------------------------------------------------------------------
__global__ __launch_bounds__(256)
void qkv_gemm_kernel(const float* __restrict__ A,
                     const float* __restrict__ Bq, const float* __restrict__ Bk,
                     const float* __restrict__ Bv,
                     const float* __restrict__ bq, const float* __restrict__ bk,
                     const float* __restrict__ bv,
                     float* __restrict__ Cq, float* __restrict__ CKV,
                     int N, int Kdim) {
    const float* B;
    const float* bias;
    float* C;
    int ldc;
    if (blockIdx.y == 0)      { B = Bq; bias = bq; C = Cq;        ldc = 128; }
    else if (blockIdx.y == 1) { B = Bk; bias = bk; C = CKV;       ldc = 256; }
    else                      { B = Bv; bias = bv; C = CKV + 128; ldc = 256; }

    __shared__ float As[2][16][128];
    __shared__ float Bs[2][16][128];

    const int tid  = threadIdx.x;
    const int row0 = blockIdx.x * 128;
    const int tx   = tid & 15;
    const int ty   = tid >> 4;

    // per-thread load coordinates (2 float4 each for A and B)
    const int fa0 = tid * 2, fa1 = tid * 2 + 1;
    const int ra0 = fa0 >> 2, ka0 = fa0 & 3;
    const int ra1 = fa1 >> 2, ka1 = fa1 & 3;
    const int gr0 = min(row0 + ra0, N - 1);
    const int gr1 = min(row0 + ra1, N - 1);
    const int kb0 = fa0 >> 5, cb0 = fa0 & 31;
    const int kb1 = fa1 >> 5, cb1 = fa1 & 31;

    float acc[8][8] = {};
    float4 pa0, pa1, pb0, pb1;

    // prologue: load first tile
    pa0 = *(const float4*)(A + (size_t)gr0 * Kdim + ka0 * 4);
    pa1 = *(const float4*)(A + (size_t)gr1 * Kdim + ka1 * 4);
    pb0 = *(const float4*)(B + (size_t)kb0 * 128 + cb0 * 4);
    pb1 = *(const float4*)(B + (size_t)kb1 * 128 + cb1 * 4);
    As[0][ka0 * 4 + 0][ra0] = pa0.x; As[0][ka0 * 4 + 1][ra0] = pa0.y;
    As[0][ka0 * 4 + 2][ra0] = pa0.z; As[0][ka0 * 4 + 3][ra0] = pa0.w;
    As[0][ka1 * 4 + 0][ra1] = pa1.x; As[0][ka1 * 4 + 1][ra1] = pa1.y;
    As[0][ka1 * 4 + 2][ra1] = pa1.z; As[0][ka1 * 4 + 3][ra1] = pa1.w;
    *(float4*)&Bs[0][kb0][cb0 * 4] = pb0;
    *(float4*)&Bs[0][kb1][cb1 * 4] = pb1;
    __syncthreads();

    const int nsteps = Kdim >> 4;
    int cur = 0;
    for (int step = 0; step < nsteps; step++) {
        if (step + 1 < nsteps) {
            int k0 = (step + 1) << 4;
            pa0 = *(const float4*)(A + (size_t)gr0 * Kdim + k0 + ka0 * 4);
            pa1 = *(const float4*)(A + (size_t)gr1 * Kdim + k0 + ka1 * 4);
            pb0 = *(const float4*)(B + (size_t)(k0 + kb0) * 128 + cb0 * 4);
            pb1 = *(const float4*)(B + (size_t)(k0 + kb1) * 128 + cb1 * 4);
        }
        #pragma unroll
        for (int kk = 0; kk < 16; kk++) {
            float a[8], b[8];
            *(float4*)&a[0] = *(const float4*)&As[cur][kk][ty * 8];
            *(float4*)&a[4] = *(const float4*)&As[cur][kk][ty * 8 + 4];
            *(float4*)&b[0] = *(const float4*)&Bs[cur][kk][tx * 8];
            *(float4*)&b[4] = *(const float4*)&Bs[cur][kk][tx * 8 + 4];
            #pragma unroll
            for (int i = 0; i < 8; i++)
                #pragma unroll
                for (int jj = 0; jj < 8; jj++)
                    acc[i][jj] += a[i] * b[jj];
        }
        if (step + 1 < nsteps) {
            int nxt = cur ^ 1;
            As[nxt][ka0 * 4 + 0][ra0] = pa0.x; As[nxt][ka0 * 4 + 1][ra0] = pa0.y;
            As[nxt][ka0 * 4 + 2][ra0] = pa0.z; As[nxt][ka0 * 4 + 3][ra0] = pa0.w;
            As[nxt][ka1 * 4 + 0][ra1] = pa1.x; As[nxt][ka1 * 4 + 1][ra1] = pa1.y;
            As[nxt][ka1 * 4 + 2][ra1] = pa1.z; As[nxt][ka1 * 4 + 3][ra1] = pa1.w;
            *(float4*)&Bs[nxt][kb0][cb0 * 4] = pb0;
            *(float4*)&Bs[nxt][kb1][cb1 * 4] = pb1;
            __syncthreads();
            cur = nxt;
        }
    }

    float bsv[8];
    *(float4*)&bsv[0] = *(const float4*)(bias + tx * 8);
    *(float4*)&bsv[4] = *(const float4*)(bias + tx * 8 + 4);
    #pragma unroll
    for (int i = 0; i < 8; i++) {
        int r = row0 + ty * 8 + i;
        if (r < N) {
            float4 o0, o1;
            o0.x = acc[i][0] + bsv[0]; o0.y = acc[i][1] + bsv[1];
            o0.z = acc[i][2] + bsv[2]; o0.w = acc[i][3] + bsv[3];
            o1.x = acc[i][4] + bsv[4]; o1.y = acc[i][5] + bsv[5];
            o1.z = acc[i][6] + bsv[6]; o1.w = acc[i][7] + bsv[7];
            *(float4*)(C + (size_t)r * ldc + tx * 8)     = o0;
            *(float4*)(C + (size_t)r * ldc + tx * 8 + 4) = o1;
        }
    }
}

// ---------------------------------------------------------------------------
// Generic small SGEMM with bias (skip M=32 and classifier M=40)
// ---------------------------------------------------------------------------
#define BM 64
#define BN 64
#define BK 16

__global__ __launch_bounds__(256)
void sgemm_bias_kernel(const float* __restrict__ A, const float* __restrict__ B,
                       const float* __restrict__ bias, float* __restrict__ C,
                       int N, int K, int M) {
    __shared__ float As[BK][BM];
    __shared__ float Bs[BK][BN];

    const int tid  = threadIdx.x;
    const int row0 = blockIdx.x * BM;
    const int col0 = blockIdx.y * BN;
    const int tr   = (tid >> 4) << 2;
    const int tc   = (tid & 15) << 2;

    float acc[4][4] = {};

    for (int k0 = 0; k0 < K; k0 += BK) {
        #pragma unroll
        for (int i = tid; i < BM * BK; i += 256) {
            int r = i / BK, c = i % BK;
            float v = 0.f;
            int gr = row0 + r;
            if (gr < N) v = A[(size_t)gr * K + (k0 + c)];
            As[c][r] = v;
        }
        #pragma unroll
        for (int i = tid; i < BK * BN; i += 256) {
            int r = i / BN, c = i % BN;
            float v = 0.f;
            int gc = col0 + c;
            if (gc < M) v = B[(size_t)(k0 + r) * M + gc];
            Bs[r][c] = v;
        }
        __syncthreads();

        #pragma unroll
        for (int kk = 0; kk < BK; kk++) {
            float a[4], b[4];
            #pragma unroll
            for (int i = 0; i < 4; i++) a[i] = As[kk][tr + i];
            #pragma unroll
            for (int j = 0; j < 4; j++) b[j] = Bs[kk][tc + j];
            #pragma unroll
            for (int i = 0; i < 4; i++)
                #pragma unroll
                for (int j = 0; j < 4; j++)
                    acc[i][j] += a[i] * b[j];
        }
        __syncthreads();
    }

    #pragma unroll
    for (int i = 0; i < 4; i++) {
        int r = row0 + tr + i;
        if (r >= N) continue;
        #pragma unroll
        for (int j = 0; j < 4; j++) {
            int c = col0 + tc + j;
            if (c < M) C[(size_t)r * M + c] = acc[i][j] + bias[c];
        }
    }
}

// ---------------------------------------------------------------------------
// Single-pass fused attention: one warp per destination node.
// Online softmax with accumulator rescaling (flash style):
//   mn = max(m, logit); sc = exp(m-mn); w = exp(logit-mn)
//   den = den*sc + w;   a = a*sc + w*v;   m = mn
// Lane l: head l/8, channels 4*(l%8)..+3. Index staging: 32 csr entries per
// coalesced load, broadcast via shfl. Edge loop unrolled x2 for MLP.
// ---------------------------------------------------------------------------
__device__ __forceinline__ void attn_update(float logit, const float4& v,
                                            float& m, float& den,
                                            float& a0, float& a1,
                                            float& a2, float& a3) {
    float mn = fmaxf(m, logit);
    float sc = __expf(m - mn);
    float w  = __expf(logit - mn);
    den = den * sc + w;
    a0 = fmaf(a0, sc, w * v.x);
    a1 = fmaf(a1, sc, w * v.y);
    a2 = fmaf(a2, sc, w * v.z);
    a3 = fmaf(a3, sc, w * v.w);
    m = mn;
}

__global__ __launch_bounds__(256)
void attn_fused_kernel(const float* __restrict__ Q, const float* __restrict__ KV,
                       const float* __restrict__ skip,
                       float* __restrict__ out, int N) {
    int n = (blockIdx.x * blockDim.x + threadIdx.x) >> 5;
    if (n >= N) return;
    const int lane = threadIdx.x & 31;
    const int beg = g_off[n];
    const int end = g_off[n + 1];

    const float4 q = *(const float4*)(Q + (size_t)n * FDIM + lane * 4);

    float m = -CUDART_INF_F;
    float den = 0.f;
    float a0 = 0.f, a1 = 0.f, a2 = 0.f, a3 = 0.f;
    const float scale = 0.17677669529663687f;  // 1/sqrt(32)

    for (int base = beg; base < end; base += 32) {
        int myidx = (base + lane < end) ? g_csr_src[base + lane] : 0;
        int rem = end - base;
        int cnt = rem < 32 ? rem : 32;
        int j = 0;
        for (; j + 1 < cnt; j += 2) {
            int s0 = __shfl_sync(0xffffffffu, myidx, j);
            int s1 = __shfl_sync(0xffffffffu, myidx, j + 1);
            const float* kv0 = KV + (size_t)s0 * 256 + lane * 4;
            const float* kv1 = KV + (size_t)s1 * 256 + lane * 4;
            float4 k0 = *(const float4*)kv0;
            float4 v0 = *(const float4*)(kv0 + 128);
            float4 k1 = *(const float4*)kv1;
            float4 v1 = *(const float4*)(kv1 + 128);
            float d0 = q.x * k0.x + q.y * k0.y + q.z * k0.z + q.w * k0.w;
            float d1 = q.x * k1.x + q.y * k1.y + q.z * k1.z + q.w * k1.w;
            d0 += __shfl_xor_sync(0xffffffffu, d0, 4);
            d1 += __shfl_xor_sync(0xffffffffu, d1, 4);
            d0 += __shfl_xor_sync(0xffffffffu, d0, 2);
            d1 += __shfl_xor_sync(0xffffffffu, d1, 2);
            d0 += __shfl_xor_sync(0xffffffffu, d0, 1);
            d1 += __shfl_xor_sync(0xffffffffu, d1, 1);
            attn_update(d0 * scale, v0, m, den, a0, a1, a2, a3);
            attn_update(d1 * scale, v1, m, den, a0, a1, a2, a3);
        }
        if (j < cnt) {
            int s0 = __shfl_sync(0xffffffffu, myidx, j);
            const float* kv0 = KV + (size_t)s0 * 256 + lane * 4;
            float4 k0 = *(const float4*)kv0;
            float4 v0 = *(const float4*)(kv0 + 128);
            float d0 = q.x * k0.x + q.y * k0.y + q.z * k0.z + q.w * k0.w;
            d0 += __shfl_xor_sync(0xffffffffu, d0, 4);
            d0 += __shfl_xor_sync(0xffffffffu, d0, 2);
            d0 += __shfl_xor_sync(0xffffffffu, d0, 1);
            attn_update(d0 * scale, v0, m, den, a0, a1, a2, a3);
        }
    }

    const float rden = 1.f / (den + 1e-16f);
    a0 *= rden; a1 *= rden; a2 *= rden; a3 *= rden;

    // head mean: sum over 4 heads (lanes l, l^8, l^16, l^24 share channels)
    #pragma unroll
    for (int dd = 8; dd <= 16; dd <<= 1) {
        a0 += __shfl_xor_sync(0xffffffffu, a0, dd);
        a1 += __shfl_xor_sync(0xffffffffu, a1, dd);
        a2 += __shfl_xor_sync(0xffffffffu, a2, dd);
        a3 += __shfl_xor_sync(0xffffffffu, a3, dd);
    }

    if (lane < 8) {
        float4 sk = *(const float4*)(skip + (size_t)n * CPH + lane * 4);
        float4 o;
        o.x = fmaxf(a0 * 0.25f + sk.x, 0.f);
        o.y = fmaxf(a1 * 0.25f + sk.y, 0.f);
        o.z = fmaxf(a2 * 0.25f + sk.z, 0.f);
        o.w = fmaxf(a3 * 0.25f + sk.w, 0.f);
        *(float4*)(out + (size_t)n * CPH + lane * 4) = o;
    }
}

// ---------------------------------------------------------------------------
// Host orchestration
// ---------------------------------------------------------------------------
static inline unsigned int ceil_div(unsigned int a, unsigned int b) { return (a + b - 1) / b; }

static void run_layer(const float* X, int Kdim,
                      const float* wq, const float* bq,
                      const float* wk, const float* bk,
                      const float* wv, const float* bv,
                      const float* ws, const float* bs,
                      float* Qp, float* KVp, float* skipp,
                      float* hout, int N) {
    dim3 gq(ceil_div(N, 128), 3);
    qkv_gemm_kernel<<<gq, 256>>>(X, wq, wk, wv, bq, bk, bv, Qp, KVp, N, Kdim);
    dim3 gs(ceil_div(N, BM), 1);
    sgemm_bias_kernel<<<gs, 256>>>(X, ws, bs, skipp, N, Kdim, CPH);

    attn_fused_kernel<<<ceil_div(N, 8), 256>>>(Qp, KVp, skipp, hout, N);
}

extern "C" void kernel_launch(void* const* d_in, const int* in_sizes, int n_in,
                              void* d_out, int out_size) {
    const float* x   = (const float*)d_in[0];
    const void*  ei  = d_in[1];
    const float* wq1 = (const float*)d_in[2];
    const float* bq1 = (const float*)d_in[3];
    const float* wk1 = (const float*)d_in[4];
    const float* bk1 = (const float*)d_in[5];
    const float* wv1 = (const float*)d_in[6];
    const float* bv1 = (const float*)d_in[7];
    const float* ws1 = (const float*)d_in[8];
    const float* bs1 = (const float*)d_in[9];
    const float* wq2 = (const float*)d_in[10];
    const float* bq2 = (const float*)d_in[11];
    const float* wk2 = (const float*)d_in[12];
    const float* bk2 = (const float*)d_in[13];
    const float* wv2 = (const float*)d_in[14];
    const float* bv2 = (const float*)d_in[15];
    const float* ws2 = (const float*)d_in[16];
    const float* bs2 = (const float*)d_in[17];
    const float* wc  = (const float*)d_in[18];
    const float* bc  = (const float*)d_in[19];

    const int N = in_sizes[0] / FDIM;   // x is [N,128]
    const int E = in_sizes[1] / 2;      // edge_index is [2,E]

    float *Qp, *KVp, *skipp, *h1p, *h2p;
    cudaGetSymbolAddress((void**)&Qp,    g_Q);
    cudaGetSymbolAddress((void**)&KVp,   g_KV);
    cudaGetSymbolAddress((void**)&skipp, g_skip);
    cudaGetSymbolAddress((void**)&h1p,   g_h1);
    cudaGetSymbolAddress((void**)&h2p,   g_h2);

    // normalize edge index (int32 or int64 storage) + build dst-CSR
    init_pre_kernel<<<ceil_div((unsigned)N, 256u), 256>>>(N);
    detect_dtype_kernel<<<592, 256>>>((const uint2*)ei, E);
    convert_edges_kernel<<<ceil_div((unsigned)E, 256u), 256>>>(ei, E);
    scan_kernel<<<1, 1024>>>(N);
    scatter_kernel<<<ceil_div((unsigned)E, 256u), 256>>>(E);

    // layer 1: input x [N,128]
    run_layer(x, FDIM, wq1, bq1, wk1, bk1, wv1, bv1, ws1, bs1,
              Qp, KVp, skipp, h1p, N);
    // layer 2: input h1 [N,32]
    run_layer(h1p, CPH, wq2, bq2, wk2, bk2, wv2, bv2, ws2, bs2,
              Qp, KVp, skipp, h2p, N);

    // classifier: out[N,40] = h2 @ wc + bc
    dim3 gc(ceil_div((unsigned)N, BM), 1);
    sgemm_bias_kernel<<<gc, 256>>>(h2p, wc, bc, (float*)d_out, N, CPH, 40);
}

// round 4
// speedup vs baseline: 2.7229x; 1.1830x over previous
#include <cuda_runtime.h>
#include <cuda_bf16.h>
#include <math_constants.h>

// ---------------------------------------------------------------------------
// GraphTransformerModel: 2x TransformerConv (H=4, C=32, concat=False) + Linear
// N=50000, E=800000, D=128, HID=32, OUT=40
// Round 4: multi-block scan, no-max softmax, slimmer CSR build.
// ---------------------------------------------------------------------------

#define NMAX 50000
#define EMAX 800000
#define HEADS 4
#define CPH 32            // channels per head
#define FDIM 128          // HEADS*CPH
#define SCAN_B 256        // scan block size
#define SCAN_NB ((NMAX + SCAN_B - 1) / SCAN_B)   // 196

// ---- static device scratch (no allocations allowed) ----
__device__ float g_Q[NMAX * FDIM];
__device__ float g_KV[(size_t)NMAX * 256];   // K row (128) | V row (128), packed
__device__ float g_skip[NMAX * CPH];
__device__ float g_h1[NMAX * CPH];
__device__ float g_h2[NMAX * CPH];
__device__ int   g_csr_src[EMAX];
__device__ int   g_deg[NMAX];
__device__ int   g_off[NMAX];
__device__ int   g_cur[NMAX];
__device__ int   g_bsum[SCAN_B];
__device__ int   g_boff[SCAN_B];
__device__ int   g_is32;

// ---------------------------------------------------------------------------
// Preprocessing: edge dtype detect + CSR build
// ---------------------------------------------------------------------------
__global__ void init_pre_kernel(int N) {
    int i = blockIdx.x * blockDim.x + threadIdx.x;
    if (i == 0) g_is32 = 0;
    if (i < N) g_deg[i] = 0;
}

// int64 little-endian: odd 32-bit words are zero (ids < 50000); int32: random
__global__ void detect_dtype_kernel(const uint2* __restrict__ w, int npairs) {
    int i = blockIdx.x * blockDim.x + threadIdx.x;
    int stride = gridDim.x * blockDim.x;
    for (; i < npairs; i += stride)
        if (w[i].y != 0u) { g_is32 = 1; break; }
}

// histogram destinations only
__global__ void hist_kernel(const void* __restrict__ ei, int E) {
    int e = blockIdx.x * blockDim.x + threadIdx.x;
    if (e >= E) return;
    int d;
    if (g_is32) d = ((const int*)ei)[E + e];
    else        d = (int)((const long long*)ei)[E + e];
    atomicAdd(&g_deg[d], 1);
}

// scan phase 1: per-block sums of g_deg
__global__ __launch_bounds__(SCAN_B)
void scan_p1_kernel(int N) {
    __shared__ int sh[SCAN_B];
    int t = threadIdx.x;
    int i = blockIdx.x * SCAN_B + t;
    int v = (i < N) ? g_deg[i] : 0;
    sh[t] = v;
    __syncthreads();
    #pragma unroll
    for (int s = SCAN_B / 2; s > 0; s >>= 1) {
        if (t < s) sh[t] += sh[t + s];
        __syncthreads();
    }
    if (t == 0) g_bsum[blockIdx.x] = sh[0];
}

// scan phase 2: single block, exclusive scan of block sums
__global__ __launch_bounds__(SCAN_B)
void scan_p2_kernel(int NB) {
    __shared__ int sh[SCAN_B];
    int t = threadIdx.x;
    int v = (t < NB) ? g_bsum[t] : 0;
    sh[t] = v;
    __syncthreads();
    #pragma unroll
    for (int d = 1; d < SCAN_B; d <<= 1) {
        int u = (t >= d) ? sh[t - d] : 0;
        __syncthreads();
        sh[t] += u;
        __syncthreads();
    }
    if (t < NB) g_boff[t] = sh[t] - v;   // exclusive prefix
}

// scan phase 3: local exclusive scan + block offset -> g_off, g_cur
__global__ __launch_bounds__(SCAN_B)
void scan_p3_kernel(int N) {
    __shared__ int sh[SCAN_B];
    int t = threadIdx.x;
    int i = blockIdx.x * SCAN_B + t;
    int v = (i < N) ? g_deg[i] : 0;
    sh[t] = v;
    __syncthreads();
    #pragma unroll
    for (int d = 1; d < SCAN_B; d <<= 1) {
        int u = (t >= d) ? sh[t - d] : 0;
        __syncthreads();
        sh[t] += u;
        __syncthreads();
    }
    if (i < N) {
        int excl = sh[t] - v + g_boff[blockIdx.x];
        g_off[i] = excl;
        g_cur[i] = excl;
    }
}

// scatter: read edge_index directly, place src at csr position
__global__ void scatter_kernel(const void* __restrict__ ei, int E) {
    int e = blockIdx.x * blockDim.x + threadIdx.x;
    if (e >= E) return;
    int s, d;
    if (g_is32) {
        const int* p = (const int*)ei;
        s = p[e];
        d = p[E + e];
    } else {
        const long long* p = (const long long*)ei;
        s = (int)p[e];
        d = (int)p[E + e];
    }
    int pidx = atomicAdd(&g_cur[d], 1);
    g_csr_src[pidx] = s;
}

// ---------------------------------------------------------------------------
// QKV GEMM, double-buffered: 128x128 tile, BK=16, 256 threads, 8x8 microtile.
// blockIdx.y selects Q (stride 128) / K (KV+0, stride 256) / V (KV+128, 256).
// ---------------------------------------------------------------------------
__global__ __launch_bounds__(256)
void qkv_gemm_kernel(const float* __restrict__ A,
                     const float* __restrict__ Bq, const float* __restrict__ Bk,
                     const float* __restrict__ Bv,
                     const float* __restrict__ bq, const float* __restrict__ bk,
                     const float* __restrict__ bv,
                     float* __restrict__ Cq, float* __restrict__ CKV,
                     int N, int Kdim) {
    const float* B;
    const float* bias;
    float* C;
    int ldc;
    if (blockIdx.y == 0)      { B = Bq; bias = bq; C = Cq;        ldc = 128; }
    else if (blockIdx.y == 1) { B = Bk; bias = bk; C = CKV;       ldc = 256; }
    else                      { B = Bv; bias = bv; C = CKV + 128; ldc = 256; }

    __shared__ float As[2][16][128];
    __shared__ float Bs[2][16][128];

    const int tid  = threadIdx.x;
    const int row0 = blockIdx.x * 128;
    const int tx   = tid & 15;
    const int ty   = tid >> 4;

    const int fa0 = tid * 2, fa1 = tid * 2 + 1;
    const int ra0 = fa0 >> 2, ka0 = fa0 & 3;
    const int ra1 = fa1 >> 2, ka1 = fa1 & 3;
    const int gr0 = min(row0 + ra0, N - 1);
    const int gr1 = min(row0 + ra1, N - 1);
    const int kb0 = fa0 >> 5, cb0 = fa0 & 31;
    const int kb1 = fa1 >> 5, cb1 = fa1 & 31;

    float acc[8][8] = {};
    float4 pa0, pa1, pb0, pb1;

    pa0 = *(const float4*)(A + (size_t)gr0 * Kdim + ka0 * 4);
    pa1 = *(const float4*)(A + (size_t)gr1 * Kdim + ka1 * 4);
    pb0 = *(const float4*)(B + (size_t)kb0 * 128 + cb0 * 4);
    pb1 = *(const float4*)(B + (size_t)kb1 * 128 + cb1 * 4);
    As[0][ka0 * 4 + 0][ra0] = pa0.x; As[0][ka0 * 4 + 1][ra0] = pa0.y;
    As[0][ka0 * 4 + 2][ra0] = pa0.z; As[0][ka0 * 4 + 3][ra0] = pa0.w;
    As[0][ka1 * 4 + 0][ra1] = pa1.x; As[0][ka1 * 4 + 1][ra1] = pa1.y;
    As[0][ka1 * 4 + 2][ra1] = pa1.z; As[0][ka1 * 4 + 3][ra1] = pa1.w;
    *(float4*)&Bs[0][kb0][cb0 * 4] = pb0;
    *(float4*)&Bs[0][kb1][cb1 * 4] = pb1;
    __syncthreads();

    const int nsteps = Kdim >> 4;
    int cur = 0;
    for (int step = 0; step < nsteps; step++) {
        if (step + 1 < nsteps) {
            int k0 = (step + 1) << 4;
            pa0 = *(const float4*)(A + (size_t)gr0 * Kdim + k0 + ka0 * 4);
            pa1 = *(const float4*)(A + (size_t)gr1 * Kdim + k0 + ka1 * 4);
            pb0 = *(const float4*)(B + (size_t)(k0 + kb0) * 128 + cb0 * 4);
            pb1 = *(const float4*)(B + (size_t)(k0 + kb1) * 128 + cb1 * 4);
        }
        #pragma unroll
        for (int kk = 0; kk < 16; kk++) {
            float a[8], b[8];
            *(float4*)&a[0] = *(const float4*)&As[cur][kk][ty * 8];
            *(float4*)&a[4] = *(const float4*)&As[cur][kk][ty * 8 + 4];
            *(float4*)&b[0] = *(const float4*)&Bs[cur][kk][tx * 8];
            *(float4*)&b[4] = *(const float4*)&Bs[cur][kk][tx * 8 + 4];
            #pragma unroll
            for (int i = 0; i < 8; i++)
                #pragma unroll
                for (int jj = 0; jj < 8; jj++)
                    acc[i][jj] += a[i] * b[jj];
        }
        if (step + 1 < nsteps) {
            int nxt = cur ^ 1;
            As[nxt][ka0 * 4 + 0][ra0] = pa0.x; As[nxt][ka0 * 4 + 1][ra0] = pa0.y;
            As[nxt][ka0 * 4 + 2][ra0] = pa0.z; As[nxt][ka0 * 4 + 3][ra0] = pa0.w;
            As[nxt][ka1 * 4 + 0][ra1] = pa1.x; As[nxt][ka1 * 4 + 1][ra1] = pa1.y;
            As[nxt][ka1 * 4 + 2][ra1] = pa1.z; As[nxt][ka1 * 4 + 3][ra1] = pa1.w;
            *(float4*)&Bs[nxt][kb0][cb0 * 4] = pb0;
            *(float4*)&Bs[nxt][kb1][cb1 * 4] = pb1;
            __syncthreads();
            cur = nxt;
        }
    }

    float bsv[8];
    *(float4*)&bsv[0] = *(const float4*)(bias + tx * 8);
    *(float4*)&bsv[4] = *(const float4*)(bias + tx * 8 + 4);
    #pragma unroll
    for (int i = 0; i < 8; i++) {
        int r = row0 + ty * 8 + i;
        if (r < N) {
            float4 o0, o1;
            o0.x = acc[i][0] + bsv[0]; o0.y = acc[i][1] + bsv[1];
            o0.z = acc[i][2] + bsv[2]; o0.w = acc[i][3] + bsv[3];
            o1.x = acc[i][4] + bsv[4]; o1.y = acc[i][5] + bsv[5];
            o1.z = acc[i][6] + bsv[6]; o1.w = acc[i][7] + bsv[7];
            *(float4*)(C + (size_t)r * ldc + tx * 8)     = o0;
            *(float4*)(C + (size_t)r * ldc + tx * 8 + 4) = o1;
        }
    }
}

// ---------------------------------------------------------------------------
// Generic small SGEMM with bias (skip M=32 and classifier M=40)
// ---------------------------------------------------------------------------
#define BM 64
#define BN 64
#define BK 16

__global__ __launch_bounds__(256)
void sgemm_bias_kernel(const float* __restrict__ A, const float* __restrict__ B,
                       const float* __restrict__ bias, float* __restrict__ C,
                       int N, int K, int M) {
    __shared__ float As[BK][BM];
    __shared__ float Bs[BK][BN];

    const int tid  = threadIdx.x;
    const int row0 = blockIdx.x * BM;
    const int col0 = blockIdx.y * BN;
    const int tr   = (tid >> 4) << 2;
    const int tc   = (tid & 15) << 2;

    float acc[4][4] = {};

    for (int k0 = 0; k0 < K; k0 += BK) {
        #pragma unroll
        for (int i = tid; i < BM * BK; i += 256) {
            int r = i / BK, c = i % BK;
            float v = 0.f;
            int gr = row0 + r;
            if (gr < N) v = A[(size_t)gr * K + (k0 + c)];
            As[c][r] = v;
        }
        #pragma unroll
        for (int i = tid; i < BK * BN; i += 256) {
            int r = i / BN, c = i % BN;
            float v = 0.f;
            int gc = col0 + c;
            if (gc < M) v = B[(size_t)(k0 + r) * M + gc];
            Bs[r][c] = v;
        }
        __syncthreads();

        #pragma unroll
        for (int kk = 0; kk < BK; kk++) {
            float a[4], b[4];
            #pragma unroll
            for (int i = 0; i < 4; i++) a[i] = As[kk][tr + i];
            #pragma unroll
            for (int j = 0; j < 4; j++) b[j] = Bs[kk][tc + j];
            #pragma unroll
            for (int i = 0; i < 4; i++)
                #pragma unroll
                for (int j = 0; j < 4; j++)
                    acc[i][j] += a[i] * b[j];
        }
        __syncthreads();
    }

    #pragma unroll
    for (int i = 0; i < 4; i++) {
        int r = row0 + tr + i;
        if (r >= N) continue;
        #pragma unroll
        for (int j = 0; j < 4; j++) {
            int c = col0 + tc + j;
            if (c < M) C[(size_t)r * M + c] = acc[i][j] + bias[c];
        }
    }
}

// ---------------------------------------------------------------------------
// Single-pass fused attention, no-max softmax (logits bounded; softmax is
// shift-invariant so result matches reference). One warp per dst node.
// Lane l: head l/8, channels 4*(l%8)..+3. csr indices staged 32 per coalesced
// load and broadcast via shfl; edge loop unrolled x2.
// ---------------------------------------------------------------------------
__global__ __launch_bounds__(256)
void attn_fused_kernel(const float* __restrict__ Q, const float* __restrict__ KV,
                       const float* __restrict__ skip,
                       float* __restrict__ out, int N, int E) {
    int n = (blockIdx.x * blockDim.x + threadIdx.x) >> 5;
    if (n >= N) return;
    const int lane = threadIdx.x & 31;
    const int beg = g_off[n];
    const int end = (n + 1 < N) ? g_off[n + 1] : E;

    const float4 q = *(const float4*)(Q + (size_t)n * FDIM + lane * 4);

    float den = 0.f;
    float a0 = 0.f, a1 = 0.f, a2 = 0.f, a3 = 0.f;
    const float scale = 0.17677669529663687f;  // 1/sqrt(32)

    for (int base = beg; base < end; base += 32) {
        int myidx = (base + lane < end) ? g_csr_src[base + lane] : 0;
        int rem = end - base;
        int cnt = rem < 32 ? rem : 32;
        int j = 0;
        for (; j + 1 < cnt; j += 2) {
            int s0 = __shfl_sync(0xffffffffu, myidx, j);
            int s1 = __shfl_sync(0xffffffffu, myidx, j + 1);
            const float* kv0 = KV + (size_t)s0 * 256 + lane * 4;
            const float* kv1 = KV + (size_t)s1 * 256 + lane * 4;
            float4 k0 = *(const float4*)kv0;
            float4 v0 = *(const float4*)(kv0 + 128);
            float4 k1 = *(const float4*)kv1;
            float4 v1 = *(const float4*)(kv1 + 128);
            float d0 = q.x * k0.x + q.y * k0.y + q.z * k0.z + q.w * k0.w;
            float d1 = q.x * k1.x + q.y * k1.y + q.z * k1.z + q.w * k1.w;
            d0 += __shfl_xor_sync(0xffffffffu, d0, 4);
            d1 += __shfl_xor_sync(0xffffffffu, d1, 4);
            d0 += __shfl_xor_sync(0xffffffffu, d0, 2);
            d1 += __shfl_xor_sync(0xffffffffu, d1, 2);
            d0 += __shfl_xor_sync(0xffffffffu, d0, 1);
            d1 += __shfl_xor_sync(0xffffffffu, d1, 1);
            float w0 = __expf(d0 * scale);
            float w1 = __expf(d1 * scale);
            den += w0 + w1;
            a0 = fmaf(w0, v0.x, fmaf(w1, v1.x, a0));
            a1 = fmaf(w0, v0.y, fmaf(w1, v1.y, a1));
            a2 = fmaf(w0, v0.z, fmaf(w1, v1.z, a2));
            a3 = fmaf(w0, v0.w, fmaf(w1, v1.w, a3));
        }
        if (j < cnt) {
            int s0 = __shfl_sync(0xffffffffu, myidx, j);
            const float* kv0 = KV + (size_t)s0 * 256 + lane * 4;
            float4 k0 = *(const float4*)kv0;
            float4 v0 = *(const float4*)(kv0 + 128);
            float d0 = q.x * k0.x + q.y * k0.y + q.z * k0.z + q.w * k0.w;
            d0 += __shfl_xor_sync(0xffffffffu, d0, 4);
            d0 += __shfl_xor_sync(0xffffffffu, d0, 2);
            d0 += __shfl_xor_sync(0xffffffffu, d0, 1);
            float w0 = __expf(d0 * scale);
            den += w0;
            a0 = fmaf(w0, v0.x, a0);
            a1 = fmaf(w0, v0.y, a1);
            a2 = fmaf(w0, v0.z, a2);
            a3 = fmaf(w0, v0.w, a3);
        }
    }

    const float rden = 1.f / (den + 1e-16f);
    a0 *= rden; a1 *= rden; a2 *= rden; a3 *= rden;

    // head mean: sum over 4 heads (lanes l, l^8, l^16, l^24 share channels)
    #pragma unroll
    for (int dd = 8; dd <= 16; dd <<= 1) {
        a0 += __shfl_xor_sync(0xffffffffu, a0, dd);
        a1 += __shfl_xor_sync(0xffffffffu, a1, dd);
        a2 += __shfl_xor_sync(0xffffffffu, a2, dd);
        a3 += __shfl_xor_sync(0xffffffffu, a3, dd);
    }

    if (lane < 8) {
        float4 sk = *(const float4*)(skip + (size_t)n * CPH + lane * 4);
        float4 o;
        o.x = fmaxf(a0 * 0.25f + sk.x, 0.f);
        o.y = fmaxf(a1 * 0.25f + sk.y, 0.f);
        o.z = fmaxf(a2 * 0.25f + sk.z, 0.f);
        o.w = fmaxf(a3 * 0.25f + sk.w, 0.f);
        *(float4*)(out + (size_t)n * CPH + lane * 4) = o;
    }
}

// ---------------------------------------------------------------------------
// Host orchestration
// ---------------------------------------------------------------------------
static inline unsigned int ceil_div(unsigned int a, unsigned int b) { return (a + b - 1) / b; }

static void run_layer(const float* X, int Kdim,
                      const float* wq, const float* bq,
                      const float* wk, const float* bk,
                      const float* wv, const float* bv,
                      const float* ws, const float* bs,
                      float* Qp, float* KVp, float* skipp,
                      float* hout, int N, int E) {
    dim3 gq(ceil_div(N, 128), 3);
    qkv_gemm_kernel<<<gq, 256>>>(X, wq, wk, wv, bq, bk, bv, Qp, KVp, N, Kdim);
    dim3 gs(ceil_div(N, BM), 1);
    sgemm_bias_kernel<<<gs, 256>>>(X, ws, bs, skipp, N, Kdim, CPH);

    attn_fused_kernel<<<ceil_div(N, 8), 256>>>(Qp, KVp, skipp, hout, N, E);
}

extern "C" void kernel_launch(void* const* d_in, const int* in_sizes, int n_in,
                              void* d_out, int out_size) {
    const float* x   = (const float*)d_in[0];
    const void*  ei  = d_in[1];
    const float* wq1 = (const float*)d_in[2];
    const float* bq1 = (const float*)d_in[3];
    const float* wk1 = (const float*)d_in[4];
    const float* bk1 = (const float*)d_in[5];
    const float* wv1 = (const float*)d_in[6];
    const float* bv1 = (const float*)d_in[7];
    const float* ws1 = (const float*)d_in[8];
    const float* bs1 = (const float*)d_in[9];
    const float* wq2 = (const float*)d_in[10];
    const float* bq2 = (const float*)d_in[11];
    const float* wk2 = (const float*)d_in[12];
    const float* bk2 = (const float*)d_in[13];
    const float* wv2 = (const float*)d_in[14];
    const float* bv2 = (const float*)d_in[15];
    const float* ws2 = (const float*)d_in[16];
    const float* bs2 = (const float*)d_in[17];
    const float* wc  = (const float*)d_in[18];
    const float* bc  = (const float*)d_in[19];

    const int N = in_sizes[0] / FDIM;   // x is [N,128]
    const int E = in_sizes[1] / 2;      // edge_index is [2,E]

    float *Qp, *KVp, *skipp, *h1p, *h2p;
    cudaGetSymbolAddress((void**)&Qp,    g_Q);
    cudaGetSymbolAddress((void**)&KVp,   g_KV);
    cudaGetSymbolAddress((void**)&skipp, g_skip);
    cudaGetSymbolAddress((void**)&h1p,   g_h1);
    cudaGetSymbolAddress((void**)&h2p,   g_h2);

    const int NB = (N + SCAN_B - 1) / SCAN_B;

    // normalize edge index (int32 or int64 storage) + build dst-CSR
    init_pre_kernel<<<ceil_div((unsigned)N, 256u), 256>>>(N);
    detect_dtype_kernel<<<592, 256>>>((const uint2*)ei, E);
    hist_kernel<<<ceil_div((unsigned)E, 256u), 256>>>(ei, E);
    scan_p1_kernel<<<NB, SCAN_B>>>(N);
    scan_p2_kernel<<<1, SCAN_B>>>(NB);
    scan_p3_kernel<<<NB, SCAN_B>>>(N);
    scatter_kernel<<<ceil_div((unsigned)E, 256u), 256>>>(ei, E);

    // layer 1: input x [N,128]
    run_layer(x, FDIM, wq1, bq1, wk1, bk1, wv1, bv1, ws1, bs1,
              Qp, KVp, skipp, h1p, N, E);
    // layer 2: input h1 [N,32]
    run_layer(h1p, CPH, wq2, bq2, wk2, bk2, wv2, bv2, ws2, bs2,
              Qp, KVp, skipp, h2p, N, E);

    // classifier: out[N,40] = h2 @ wc + bc
    dim3 gc(ceil_div((unsigned)N, BM), 1);
    sgemm_bias_kernel<<<gc, 256>>>(h2p, wc, bc, (float*)d_out, N, CPH, 40);
}

// round 6
// speedup vs baseline: 3.2204x; 1.1827x over previous
#include <cuda_runtime.h>
#include <cuda_fp16.h>
#include <math_constants.h>
#include <cstdint>

// ---------------------------------------------------------------------------
// GraphTransformerModel: 2x TransformerConv (H=4, C=32, concat=False) + Linear
// N=50000, E=800000, D=128, HID=32, OUT=40
// Round 6: HMMA (mma.sync m16n8k16 fp16) QKV GEMMs; V uses hi/lo fp16 split
// for fp32-level accuracy. tcgen05 unavailable (toolchain targets compute_103).
// ---------------------------------------------------------------------------

#define NMAX 50000
#define EMAX 800000
#define HEADS 4
#define CPH 32
#define FDIM 128
#define SCAN_B 256

// ---- static device scratch ----
__device__ float g_Q[NMAX * FDIM];
__device__ float g_KV[(size_t)NMAX * 256];   // K row (128) | V row (128)
__device__ float g_skip[NMAX * CPH];
__device__ float g_h1[NMAX * CPH];
__device__ float g_h2[NMAX * CPH];
__device__ int   g_csr_src[EMAX];
__device__ int   g_deg[NMAX];
__device__ int   g_off[NMAX];
__device__ int   g_cur[NMAX];
__device__ int   g_bsum[SCAN_B];
__device__ int   g_boff[SCAN_B];
__device__ int   g_is32;

// ---------------------------------------------------------------------------
// HMMA GEMM: C[N,128] = A[N,Kdim] @ W[Kdim,128] + bias  via m16n8k16 fp16 mma
// blockIdx.y: 0 -> Q (fp16 single pass), 1 -> K (single), 2 -> V (hi/lo split,
// 3 passes, ~fp32 accuracy). Tile 128x128, BK=16, 256 threads (8 warps, 2x4),
// warp tile 64x32. A,B staged k-contiguous (24-half padded rows) in smem so
// every mma fragment register is one conflict-free 32-bit LDS.
// ---------------------------------------------------------------------------
#define LDH 24   // halves per smem row (16 data + 8 pad) -> 12 u32, conflict-free

__device__ __forceinline__ void mma16816(float* d, const uint32_t* a,
                                         const uint32_t* b) {
    asm volatile(
        "mma.sync.aligned.m16n8k16.row.col.f32.f16.f16.f32 "
        "{%0,%1,%2,%3}, {%4,%5,%6,%7}, {%8,%9}, {%0,%1,%2,%3};"
        : "+f"(d[0]), "+f"(d[1]), "+f"(d[2]), "+f"(d[3])
        : "r"(a[0]), "r"(a[1]), "r"(a[2]), "r"(a[3]), "r"(b[0]), "r"(b[1]));
}

__global__ __launch_bounds__(256)
void hmma_gemm_kernel(const float* __restrict__ A,
                      const float* __restrict__ Wq, const float* __restrict__ Wk,
                      const float* __restrict__ Wv,
                      const float* __restrict__ bq, const float* __restrict__ bk,
                      const float* __restrict__ bv,
                      float* __restrict__ Cq, float* __restrict__ CKV,
                      int N, int Kdim) {
    const float* W;
    const float* bias;
    float* C;
    int ldc;
    bool split;
    if (blockIdx.y == 0)      { W = Wq; bias = bq; C = Cq;        ldc = 128; split = false; }
    else if (blockIdx.y == 1) { W = Wk; bias = bk; C = CKV;       ldc = 256; split = false; }
    else                      { W = Wv; bias = bv; C = CKV + 128; ldc = 256; split = true;  }

    __shared__ __half sAh[128 * LDH];
    __shared__ __half sAl[128 * LDH];
    __shared__ __half sBh[128 * LDH];
    __shared__ __half sBl[128 * LDH];

    const int tid  = threadIdx.x;
    const int wid  = tid >> 5;
    const int lane = tid & 31;
    const int wm   = wid >> 2;          // 0..1
    const int wn   = wid & 3;           // 0..3
    const int row0 = blockIdx.x * 128;
    const int lr   = lane >> 2;         // 0..7
    const int lc   = lane & 3;          // 0..3

    float acc[4][4][4] = {};

    const uint32_t* sAh32 = (const uint32_t*)sAh;
    const uint32_t* sAl32 = (const uint32_t*)sAl;
    const uint32_t* sBh32 = (const uint32_t*)sBh;
    const uint32_t* sBl32 = (const uint32_t*)sBl;

    const int nsteps = Kdim >> 4;
    for (int step = 0; step < nsteps; step++) {
        const int k0 = step << 4;
        __syncthreads();
        // --- stage A: 128 rows x 16 k, fp32 -> fp16 (+lo residual if split) ---
        #pragma unroll
        for (int it = 0; it < 2; it++) {
            int idx = tid + it * 256;           // 0..511
            int r  = idx >> 2;
            int c4 = idx & 3;
            int gr = min(row0 + r, N - 1);
            float4 a = *(const float4*)(A + (size_t)gr * Kdim + k0 + c4 * 4);
            __half2 h0 = __floats2half2_rn(a.x, a.y);
            __half2 h1 = __floats2half2_rn(a.z, a.w);
            __half2* dst = (__half2*)(sAh + r * LDH) + c4 * 2;
            dst[0] = h0; dst[1] = h1;
            if (split) {
                __half2 l0 = __floats2half2_rn(a.x - __low2float(h0),
                                               a.y - __high2float(h0));
                __half2 l1 = __floats2half2_rn(a.z - __low2float(h1),
                                               a.w - __high2float(h1));
                __half2* dl = (__half2*)(sAl + r * LDH) + c4 * 2;
                dl[0] = l0; dl[1] = l1;
            }
        }
        // --- stage B: W[k][n] -> sB[n][k] fp16 (transposed, k-contiguous) ---
        #pragma unroll
        for (int it = 0; it < 2; it++) {
            int idx = tid + it * 256;           // 0..511
            int kk = idx >> 5;                  // 0..15
            int n4 = idx & 31;                  // 0..31
            float4 w = *(const float4*)(W + (size_t)(k0 + kk) * 128 + n4 * 4);
            __half hx = __float2half_rn(w.x), hy = __float2half_rn(w.y);
            __half hz = __float2half_rn(w.z), hw = __float2half_rn(w.w);
            sBh[(n4 * 4 + 0) * LDH + kk] = hx;
            sBh[(n4 * 4 + 1) * LDH + kk] = hy;
            sBh[(n4 * 4 + 2) * LDH + kk] = hz;
            sBh[(n4 * 4 + 3) * LDH + kk] = hw;
            if (split) {
                sBl[(n4 * 4 + 0) * LDH + kk] = __float2half_rn(w.x - __half2float(hx));
                sBl[(n4 * 4 + 1) * LDH + kk] = __float2half_rn(w.y - __half2float(hy));
                sBl[(n4 * 4 + 2) * LDH + kk] = __float2half_rn(w.z - __half2float(hz));
                sBl[(n4 * 4 + 3) * LDH + kk] = __float2half_rn(w.w - __half2float(hw));
            }
        }
        __syncthreads();

        // --- fragments + mma ---
        uint32_t af[4][4], bf[4][2];
        #pragma unroll
        for (int mt = 0; mt < 4; mt++) {
            int rm = wm * 64 + mt * 16;
            #pragma unroll
            for (int j = 0; j < 4; j++)
                af[mt][j] = sAh32[(rm + lr + (j & 1) * 8) * 12 + lc + (j >> 1) * 4];
        }
        #pragma unroll
        for (int nt = 0; nt < 4; nt++) {
            int cn = wn * 32 + nt * 8;
            bf[nt][0] = sBh32[(cn + lr) * 12 + lc];
            bf[nt][1] = sBh32[(cn + lr) * 12 + lc + 4];
        }
        #pragma unroll
        for (int mt = 0; mt < 4; mt++)
            #pragma unroll
            for (int nt = 0; nt < 4; nt++)
                mma16816(acc[mt][nt], af[mt], bf[nt]);

        if (split) {
            // pass 2: Al * Bh (overwrite af with lo-A)
            #pragma unroll
            for (int mt = 0; mt < 4; mt++) {
                int rm = wm * 64 + mt * 16;
                #pragma unroll
                for (int j = 0; j < 4; j++)
                    af[mt][j] = sAl32[(rm + lr + (j & 1) * 8) * 12 + lc + (j >> 1) * 4];
            }
            #pragma unroll
            for (int mt = 0; mt < 4; mt++)
                #pragma unroll
                for (int nt = 0; nt < 4; nt++)
                    mma16816(acc[mt][nt], af[mt], bf[nt]);
            // pass 3: Ah * Bl (reload hi-A, lo-B)
            #pragma unroll
            for (int mt = 0; mt < 4; mt++) {
                int rm = wm * 64 + mt * 16;
                #pragma unroll
                for (int j = 0; j < 4; j++)
                    af[mt][j] = sAh32[(rm + lr + (j & 1) * 8) * 12 + lc + (j >> 1) * 4];
            }
            #pragma unroll
            for (int nt = 0; nt < 4; nt++) {
                int cn = wn * 32 + nt * 8;
                bf[nt][0] = sBl32[(cn + lr) * 12 + lc];
                bf[nt][1] = sBl32[(cn + lr) * 12 + lc + 4];
            }
            #pragma unroll
            for (int mt = 0; mt < 4; mt++)
                #pragma unroll
                for (int nt = 0; nt < 4; nt++)
                    mma16816(acc[mt][nt], af[mt], bf[nt]);
        }
    }

    // --- epilogue: c0,c1 -> (row, col..col+1), c2,c3 -> (row+8, ...) ---
    #pragma unroll
    for (int mt = 0; mt < 4; mt++) {
        int r0 = row0 + wm * 64 + mt * 16 + lr;
        #pragma unroll
        for (int nt = 0; nt < 4; nt++) {
            int gc = wn * 32 + nt * 8 + lc * 2;
            float bx = bias[gc], by = bias[gc + 1];
            if (r0 < N) {
                float2 o = make_float2(acc[mt][nt][0] + bx, acc[mt][nt][1] + by);
                *(float2*)(C + (size_t)r0 * ldc + gc) = o;
            }
            if (r0 + 8 < N) {
                float2 o = make_float2(acc[mt][nt][2] + bx, acc[mt][nt][3] + by);
                *(float2*)(C + (size_t)(r0 + 8) * ldc + gc) = o;
            }
        }
    }
}

// ---------------------------------------------------------------------------
// Preprocessing (unchanged)
// ---------------------------------------------------------------------------
__global__ void init_pre_kernel(int N) {
    int i = blockIdx.x * blockDim.x + threadIdx.x;
    if (i == 0) g_is32 = 0;
    if (i < N) g_deg[i] = 0;
}

__global__ void detect_dtype_kernel(const uint2* __restrict__ w, int npairs) {
    int i = blockIdx.x * blockDim.x + threadIdx.x;
    int stride = gridDim.x * blockDim.x;
    for (; i < npairs; i += stride)
        if (w[i].y != 0u) { g_is32 = 1; break; }
}

__global__ void hist_kernel(const void* __restrict__ ei, int E) {
    int e = blockIdx.x * blockDim.x + threadIdx.x;
    if (e >= E) return;
    int d;
    if (g_is32) d = ((const int*)ei)[E + e];
    else        d = (int)((const long long*)ei)[E + e];
    atomicAdd(&g_deg[d], 1);
}

__global__ __launch_bounds__(SCAN_B)
void scan_p1_kernel(int N) {
    __shared__ int sh[SCAN_B];
    int t = threadIdx.x;
    int i = blockIdx.x * SCAN_B + t;
    int v = (i < N) ? g_deg[i] : 0;
    sh[t] = v;
    __syncthreads();
    #pragma unroll
    for (int s = SCAN_B / 2; s > 0; s >>= 1) {
        if (t < s) sh[t] += sh[t + s];
        __syncthreads();
    }
    if (t == 0) g_bsum[blockIdx.x] = sh[0];
}

__global__ __launch_bounds__(SCAN_B)
void scan_p2_kernel(int NB) {
    __shared__ int sh[SCAN_B];
    int t = threadIdx.x;
    int v = (t < NB) ? g_bsum[t] : 0;
    sh[t] = v;
    __syncthreads();
    #pragma unroll
    for (int d = 1; d < SCAN_B; d <<= 1) {
        int u = (t >= d) ? sh[t - d] : 0;
        __syncthreads();
        sh[t] += u;
        __syncthreads();
    }
    if (t < NB) g_boff[t] = sh[t] - v;
}

__global__ __launch_bounds__(SCAN_B)
void scan_p3_kernel(int N) {
    __shared__ int sh[SCAN_B];
    int t = threadIdx.x;
    int i = blockIdx.x * SCAN_B + t;
    int v = (i < N) ? g_deg[i] : 0;
    sh[t] = v;
    __syncthreads();
    #pragma unroll
    for (int d = 1; d < SCAN_B; d <<= 1) {
        int u = (t >= d) ? sh[t - d] : 0;
        __syncthreads();
        sh[t] += u;
        __syncthreads();
    }
    if (i < N) {
        int excl = sh[t] - v + g_boff[blockIdx.x];
        g_off[i] = excl;
        g_cur[i] = excl;
    }
}

__global__ void scatter_kernel(const void* __restrict__ ei, int E) {
    int e = blockIdx.x * blockDim.x + threadIdx.x;
    if (e >= E) return;
    int s, d;
    if (g_is32) {
        const int* p = (const int*)ei;
        s = p[e];
        d = p[E + e];
    } else {
        const long long* p = (const long long*)ei;
        s = (int)p[e];
        d = (int)p[E + e];
    }
    int pidx = atomicAdd(&g_cur[d], 1);
    g_csr_src[pidx] = s;
}

// ---------------------------------------------------------------------------
// Generic small SGEMM with bias (skip M=32 and classifier M=40), fp32 SIMT
// ---------------------------------------------------------------------------
#define BM 64
#define BN 64
#define BK 16

__global__ __launch_bounds__(256)
void sgemm_bias_kernel(const float* __restrict__ A, const float* __restrict__ B,
                       const float* __restrict__ bias, float* __restrict__ C,
                       int N, int K, int M) {
    __shared__ float As[BK][BM];
    __shared__ float Bs[BK][BN];

    const int tid  = threadIdx.x;
    const int row0 = blockIdx.x * BM;
    const int col0 = blockIdx.y * BN;
    const int tr   = (tid >> 4) << 2;
    const int tc   = (tid & 15) << 2;

    float acc[4][4] = {};

    for (int k0 = 0; k0 < K; k0 += BK) {
        #pragma unroll
        for (int i = tid; i < BM * BK; i += 256) {
            int r = i / BK, c = i % BK;
            float v = 0.f;
            int gr = row0 + r;
            if (gr < N) v = A[(size_t)gr * K + (k0 + c)];
            As[c][r] = v;
        }
        #pragma unroll
        for (int i = tid; i < BK * BN; i += 256) {
            int r = i / BN, c = i % BN;
            float v = 0.f;
            int gc = col0 + c;
            if (gc < M) v = B[(size_t)(k0 + r) * M + gc];
            Bs[r][c] = v;
        }
        __syncthreads();

        #pragma unroll
        for (int kk = 0; kk < BK; kk++) {
            float a[4], b[4];
            #pragma unroll
            for (int i = 0; i < 4; i++) a[i] = As[kk][tr + i];
            #pragma unroll
            for (int j = 0; j < 4; j++) b[j] = Bs[kk][tc + j];
            #pragma unroll
            for (int i = 0; i < 4; i++)
                #pragma unroll
                for (int j = 0; j < 4; j++)
                    acc[i][j] += a[i] * b[j];
        }
        __syncthreads();
    }

    #pragma unroll
    for (int i = 0; i < 4; i++) {
        int r = row0 + tr + i;
        if (r >= N) continue;
        #pragma unroll
        for (int j = 0; j < 4; j++) {
            int c = col0 + tc + j;
            if (c < M) C[(size_t)r * M + c] = acc[i][j] + bias[c];
        }
    }
}

// ---------------------------------------------------------------------------
// Single-pass fused attention (unchanged from round 4)
// ---------------------------------------------------------------------------
__global__ __launch_bounds__(256)
void attn_fused_kernel(const float* __restrict__ Q, const float* __restrict__ KV,
                       const float* __restrict__ skip,
                       float* __restrict__ out, int N, int E) {
    int n = (blockIdx.x * blockDim.x + threadIdx.x) >> 5;
    if (n >= N) return;
    const int lane = threadIdx.x & 31;
    const int beg = g_off[n];
    const int end = (n + 1 < N) ? g_off[n + 1] : E;

    const float4 q = *(const float4*)(Q + (size_t)n * FDIM + lane * 4);

    float den = 0.f;
    float a0 = 0.f, a1 = 0.f, a2 = 0.f, a3 = 0.f;
    const float scale = 0.17677669529663687f;  // 1/sqrt(32)

    for (int base = beg; base < end; base += 32) {
        int myidx = (base + lane < end) ? g_csr_src[base + lane] : 0;
        int rem = end - base;
        int cnt = rem < 32 ? rem : 32;
        int j = 0;
        for (; j + 1 < cnt; j += 2) {
            int s0 = __shfl_sync(0xffffffffu, myidx, j);
            int s1 = __shfl_sync(0xffffffffu, myidx, j + 1);
            const float* kv0 = KV + (size_t)s0 * 256 + lane * 4;
            const float* kv1 = KV + (size_t)s1 * 256 + lane * 4;
            float4 k0 = *(const float4*)kv0;
            float4 v0 = *(const float4*)(kv0 + 128);
            float4 k1 = *(const float4*)kv1;
            float4 v1 = *(const float4*)(kv1 + 128);
            float d0 = q.x * k0.x + q.y * k0.y + q.z * k0.z + q.w * k0.w;
            float d1 = q.x * k1.x + q.y * k1.y + q.z * k1.z + q.w * k1.w;
            d0 += __shfl_xor_sync(0xffffffffu, d0, 4);
            d1 += __shfl_xor_sync(0xffffffffu, d1, 4);
            d0 += __shfl_xor_sync(0xffffffffu, d0, 2);
            d1 += __shfl_xor_sync(0xffffffffu, d1, 2);
            d0 += __shfl_xor_sync(0xffffffffu, d0, 1);
            d1 += __shfl_xor_sync(0xffffffffu, d1, 1);
            float w0 = __expf(d0 * scale);
            float w1 = __expf(d1 * scale);
            den += w0 + w1;
            a0 = fmaf(w0, v0.x, fmaf(w1, v1.x, a0));
            a1 = fmaf(w0, v0.y, fmaf(w1, v1.y, a1));
            a2 = fmaf(w0, v0.z, fmaf(w1, v1.z, a2));
            a3 = fmaf(w0, v0.w, fmaf(w1, v1.w, a3));
        }
        if (j < cnt) {
            int s0 = __shfl_sync(0xffffffffu, myidx, j);
            const float* kv0 = KV + (size_t)s0 * 256 + lane * 4;
            float4 k0 = *(const float4*)kv0;
            float4 v0 = *(const float4*)(kv0 + 128);
            float d0 = q.x * k0.x + q.y * k0.y + q.z * k0.z + q.w * k0.w;
            d0 += __shfl_xor_sync(0xffffffffu, d0, 4);
            d0 += __shfl_xor_sync(0xffffffffu, d0, 2);
            d0 += __shfl_xor_sync(0xffffffffu, d0, 1);
            float w0 = __expf(d0 * scale);
            den += w0;
            a0 = fmaf(w0, v0.x, a0);
            a1 = fmaf(w0, v0.y, a1);
            a2 = fmaf(w0, v0.z, a2);
            a3 = fmaf(w0, v0.w, a3);
        }
    }

    const float rden = 1.f / (den + 1e-16f);
    a0 *= rden; a1 *= rden; a2 *= rden; a3 *= rden;

    #pragma unroll
    for (int dd = 8; dd <= 16; dd <<= 1) {
        a0 += __shfl_xor_sync(0xffffffffu, a0, dd);
        a1 += __shfl_xor_sync(0xffffffffu, a1, dd);
        a2 += __shfl_xor_sync(0xffffffffu, a2, dd);
        a3 += __shfl_xor_sync(0xffffffffu, a3, dd);
    }

    if (lane < 8) {
        float4 sk = *(const float4*)(skip + (size_t)n * CPH + lane * 4);
        float4 o;
        o.x = fmaxf(a0 * 0.25f + sk.x, 0.f);
        o.y = fmaxf(a1 * 0.25f + sk.y, 0.f);
        o.z = fmaxf(a2 * 0.25f + sk.z, 0.f);
        o.w = fmaxf(a3 * 0.25f + sk.w, 0.f);
        *(float4*)(out + (size_t)n * CPH + lane * 4) = o;
    }
}

// ---------------------------------------------------------------------------
// Host orchestration
// ---------------------------------------------------------------------------
static inline unsigned int ceil_div(unsigned int a, unsigned int b) { return (a + b - 1) / b; }

static void run_layer(const float* X, int Kdim,
                      const float* wq, const float* bq,
                      const float* wk, const float* bk,
                      const float* wv, const float* bv,
                      const float* ws, const float* bs,
                      float* Qp, float* KVp, float* skipp,
                      float* hout, int N, int E) {
    dim3 gq(ceil_div(N, 128), 3);
    hmma_gemm_kernel<<<gq, 256>>>(X, wq, wk, wv, bq, bk, bv, Qp, KVp, N, Kdim);
    dim3 gs(ceil_div(N, BM), 1);
    sgemm_bias_kernel<<<gs, 256>>>(X, ws, bs, skipp, N, Kdim, CPH);

    attn_fused_kernel<<<ceil_div(N, 8), 256>>>(Qp, KVp, skipp, hout, N, E);
}

extern "C" void kernel_launch(void* const* d_in, const int* in_sizes, int n_in,
                              void* d_out, int out_size) {
    const float* x   = (const float*)d_in[0];
    const void*  ei  = d_in[1];
    const float* wq1 = (const float*)d_in[2];
    const float* bq1 = (const float*)d_in[3];
    const float* wk1 = (const float*)d_in[4];
    const float* bk1 = (const float*)d_in[5];
    const float* wv1 = (const float*)d_in[6];
    const float* bv1 = (const float*)d_in[7];
    const float* ws1 = (const float*)d_in[8];
    const float* bs1 = (const float*)d_in[9];
    const float* wq2 = (const float*)d_in[10];
    const float* bq2 = (const float*)d_in[11];
    const float* wk2 = (const float*)d_in[12];
    const float* bk2 = (const float*)d_in[13];
    const float* wv2 = (const float*)d_in[14];
    const float* bv2 = (const float*)d_in[15];
    const float* ws2 = (const float*)d_in[16];
    const float* bs2 = (const float*)d_in[17];
    const float* wc  = (const float*)d_in[18];
    const float* bc  = (const float*)d_in[19];

    const int N = in_sizes[0] / FDIM;   // x is [N,128]
    const int E = in_sizes[1] / 2;      // edge_index is [2,E]

    float *Qp, *KVp, *skipp, *h1p, *h2p;
    cudaGetSymbolAddress((void**)&Qp,    g_Q);
    cudaGetSymbolAddress((void**)&KVp,   g_KV);
    cudaGetSymbolAddress((void**)&skipp, g_skip);
    cudaGetSymbolAddress((void**)&h1p,   g_h1);
    cudaGetSymbolAddress((void**)&h2p,   g_h2);

    const int NB = (N + SCAN_B - 1) / SCAN_B;

    init_pre_kernel<<<ceil_div((unsigned)N, 256u), 256>>>(N);
    detect_dtype_kernel<<<592, 256>>>((const uint2*)ei, E);
    hist_kernel<<<ceil_div((unsigned)E, 256u), 256>>>(ei, E);
    scan_p1_kernel<<<NB, SCAN_B>>>(N);
    scan_p2_kernel<<<1, SCAN_B>>>(NB);
    scan_p3_kernel<<<NB, SCAN_B>>>(N);
    scatter_kernel<<<ceil_div((unsigned)E, 256u), 256>>>(ei, E);

    run_layer(x, FDIM, wq1, bq1, wk1, bk1, wv1, bv1, ws1, bs1,
              Qp, KVp, skipp, h1p, N, E);
    run_layer(h1p, CPH, wq2, bq2, wk2, bk2, wv2, bv2, ws2, bs2,
              Qp, KVp, skipp, h2p, N, E);

    dim3 gc(ceil_div((unsigned)N, BM), 1);
    sgemm_bias_kernel<<<gc, 256>>>(h2p, wc, bc, (float*)d_out, N, CPH, 40);
}

// round 7
// speedup vs baseline: 3.7979x; 1.1793x over previous
#include <cuda_runtime.h>
#include <cuda_fp16.h>
#include <math_constants.h>
#include <cstdint>

// ---------------------------------------------------------------------------
// GraphTransformerModel: 2x TransformerConv (H=4, C=32, concat=False) + Linear
// N=50000, E=800000, D=128, HID=32, OUT=40
// Round 7: fp16 KV storage (halves attention gather traffic), single-pass
// HMMA QKV (no V split needed — V output quantized to fp16 anyway).
// ---------------------------------------------------------------------------

#define NMAX 50000
#define EMAX 800000
#define HEADS 4
#define CPH 32
#define FDIM 128
#define SCAN_B 256

// ---- static device scratch ----
__device__ float  g_Q[NMAX * FDIM];
__device__ __half g_KV[(size_t)NMAX * 256];  // K row (128 h) | V row (128 h)
__device__ float  g_skip[NMAX * CPH];
__device__ float  g_h1[NMAX * CPH];
__device__ float  g_h2[NMAX * CPH];
__device__ int    g_csr_src[EMAX];
__device__ int    g_deg[NMAX];
__device__ int    g_off[NMAX];
__device__ int    g_cur[NMAX];
__device__ int    g_bsum[SCAN_B];
__device__ int    g_boff[SCAN_B];
__device__ int    g_is32;

// ---------------------------------------------------------------------------
// HMMA GEMM: one kernel, blockIdx.y: 0 -> Q (fp32 out), 1 -> K, 2 -> V (fp16
// out into packed KV). Tile 128x128, BK=16, 256 threads (8 warps 2x4), warp
// tile 64x32. A,B staged k-contiguous (24-half padded rows): every fragment
// register is one conflict-free 32-bit LDS.
// ---------------------------------------------------------------------------
#define LDH 24   // halves per smem row (16 data + 8 pad) -> 12 u32

__device__ __forceinline__ void mma16816(float* d, const uint32_t* a,
                                         const uint32_t* b) {
    asm volatile(
        "mma.sync.aligned.m16n8k16.row.col.f32.f16.f16.f32 "
        "{%0,%1,%2,%3}, {%4,%5,%6,%7}, {%8,%9}, {%0,%1,%2,%3};"
        : "+f"(d[0]), "+f"(d[1]), "+f"(d[2]), "+f"(d[3])
        : "r"(a[0]), "r"(a[1]), "r"(a[2]), "r"(a[3]), "r"(b[0]), "r"(b[1]));
}

__global__ __launch_bounds__(256)
void hmma_gemm_kernel(const float* __restrict__ A,
                      const float* __restrict__ Wq, const float* __restrict__ Wk,
                      const float* __restrict__ Wv,
                      const float* __restrict__ bq, const float* __restrict__ bk,
                      const float* __restrict__ bv,
                      float* __restrict__ Cq, __half* __restrict__ CKV,
                      int N, int Kdim) {
    const float* W;
    const float* bias;
    int coloff = 0;
    if (blockIdx.y == 0)      { W = Wq; bias = bq; }
    else if (blockIdx.y == 1) { W = Wk; bias = bk; coloff = 0;   }
    else                      { W = Wv; bias = bv; coloff = 128; }
    const bool isQ = (blockIdx.y == 0);

    __shared__ __half sA[128 * LDH];
    __shared__ __half sB[128 * LDH];

    const int tid  = threadIdx.x;
    const int wid  = tid >> 5;
    const int lane = tid & 31;
    const int wm   = wid >> 2;          // 0..1
    const int wn   = wid & 3;           // 0..3
    const int row0 = blockIdx.x * 128;
    const int lr   = lane >> 2;         // 0..7
    const int lc   = lane & 3;          // 0..3

    float acc[4][4][4] = {};

    const uint32_t* sA32 = (const uint32_t*)sA;
    const uint32_t* sB32 = (const uint32_t*)sB;

    const int nsteps = Kdim >> 4;
    for (int step = 0; step < nsteps; step++) {
        const int k0 = step << 4;
        __syncthreads();
        // stage A: 128 rows x 16 k, fp32 -> fp16
        #pragma unroll
        for (int it = 0; it < 2; it++) {
            int idx = tid + it * 256;           // 0..511
            int r  = idx >> 2;
            int c4 = idx & 3;
            int gr = min(row0 + r, N - 1);
            float4 a = *(const float4*)(A + (size_t)gr * Kdim + k0 + c4 * 4);
            __half2* dst = (__half2*)(sA + r * LDH) + c4 * 2;
            dst[0] = __floats2half2_rn(a.x, a.y);
            dst[1] = __floats2half2_rn(a.z, a.w);
        }
        // stage B: W[k][n] -> sB[n][k] fp16 (transposed, k-contiguous)
        #pragma unroll
        for (int it = 0; it < 2; it++) {
            int idx = tid + it * 256;
            int kk = idx >> 5;                  // 0..15
            int n4 = idx & 31;                  // 0..31
            float4 w = *(const float4*)(W + (size_t)(k0 + kk) * 128 + n4 * 4);
            sB[(n4 * 4 + 0) * LDH + kk] = __float2half_rn(w.x);
            sB[(n4 * 4 + 1) * LDH + kk] = __float2half_rn(w.y);
            sB[(n4 * 4 + 2) * LDH + kk] = __float2half_rn(w.z);
            sB[(n4 * 4 + 3) * LDH + kk] = __float2half_rn(w.w);
        }
        __syncthreads();

        uint32_t af[4][4], bf[4][2];
        #pragma unroll
        for (int mt = 0; mt < 4; mt++) {
            int rm = wm * 64 + mt * 16;
            #pragma unroll
            for (int j = 0; j < 4; j++)
                af[mt][j] = sA32[(rm + lr + (j & 1) * 8) * 12 + lc + (j >> 1) * 4];
        }
        #pragma unroll
        for (int nt = 0; nt < 4; nt++) {
            int cn = wn * 32 + nt * 8;
            bf[nt][0] = sB32[(cn + lr) * 12 + lc];
            bf[nt][1] = sB32[(cn + lr) * 12 + lc + 4];
        }
        #pragma unroll
        for (int mt = 0; mt < 4; mt++)
            #pragma unroll
            for (int nt = 0; nt < 4; nt++)
                mma16816(acc[mt][nt], af[mt], bf[nt]);
    }

    // epilogue: c0,c1 -> (row, col..col+1), c2,c3 -> (row+8, ...)
    #pragma unroll
    for (int mt = 0; mt < 4; mt++) {
        int r0 = row0 + wm * 64 + mt * 16 + lr;
        #pragma unroll
        for (int nt = 0; nt < 4; nt++) {
            int gc = wn * 32 + nt * 8 + lc * 2;
            float bx = bias[gc], by = bias[gc + 1];
            if (isQ) {
                if (r0 < N)
                    *(float2*)(Cq + (size_t)r0 * 128 + gc) =
                        make_float2(acc[mt][nt][0] + bx, acc[mt][nt][1] + by);
                if (r0 + 8 < N)
                    *(float2*)(Cq + (size_t)(r0 + 8) * 128 + gc) =
                        make_float2(acc[mt][nt][2] + bx, acc[mt][nt][3] + by);
            } else {
                if (r0 < N)
                    *(__half2*)(CKV + (size_t)r0 * 256 + coloff + gc) =
                        __floats2half2_rn(acc[mt][nt][0] + bx, acc[mt][nt][1] + by);
                if (r0 + 8 < N)
                    *(__half2*)(CKV + (size_t)(r0 + 8) * 256 + coloff + gc) =
                        __floats2half2_rn(acc[mt][nt][2] + bx, acc[mt][nt][3] + by);
            }
        }
    }
}

// ---------------------------------------------------------------------------
// Preprocessing (unchanged)
// ---------------------------------------------------------------------------
__global__ void init_pre_kernel(int N) {
    int i = blockIdx.x * blockDim.x + threadIdx.x;
    if (i == 0) g_is32 = 0;
    if (i < N) g_deg[i] = 0;
}

__global__ void detect_dtype_kernel(const uint2* __restrict__ w, int npairs) {
    int i = blockIdx.x * blockDim.x + threadIdx.x;
    int stride = gridDim.x * blockDim.x;
    for (; i < npairs; i += stride)
        if (w[i].y != 0u) { g_is32 = 1; break; }
}

__global__ void hist_kernel(const void* __restrict__ ei, int E) {
    int e = blockIdx.x * blockDim.x + threadIdx.x;
    if (e >= E) return;
    int d;
    if (g_is32) d = ((const int*)ei)[E + e];
    else        d = (int)((const long long*)ei)[E + e];
    atomicAdd(&g_deg[d], 1);
}

__global__ __launch_bounds__(SCAN_B)
void scan_p1_kernel(int N) {
    __shared__ int sh[SCAN_B];
    int t = threadIdx.x;
    int i = blockIdx.x * SCAN_B + t;
    int v = (i < N) ? g_deg[i] : 0;
    sh[t] = v;
    __syncthreads();
    #pragma unroll
    for (int s = SCAN_B / 2; s > 0; s >>= 1) {
        if (t < s) sh[t] += sh[t + s];
        __syncthreads();
    }
    if (t == 0) g_bsum[blockIdx.x] = sh[0];
}

__global__ __launch_bounds__(SCAN_B)
void scan_p2_kernel(int NB) {
    __shared__ int sh[SCAN_B];
    int t = threadIdx.x;
    int v = (t < NB) ? g_bsum[t] : 0;
    sh[t] = v;
    __syncthreads();
    #pragma unroll
    for (int d = 1; d < SCAN_B; d <<= 1) {
        int u = (t >= d) ? sh[t - d] : 0;
        __syncthreads();
        sh[t] += u;
        __syncthreads();
    }
    if (t < NB) g_boff[t] = sh[t] - v;
}

__global__ __launch_bounds__(SCAN_B)
void scan_p3_kernel(int N) {
    __shared__ int sh[SCAN_B];
    int t = threadIdx.x;
    int i = blockIdx.x * SCAN_B + t;
    int v = (i < N) ? g_deg[i] : 0;
    sh[t] = v;
    __syncthreads();
    #pragma unroll
    for (int d = 1; d < SCAN_B; d <<= 1) {
        int u = (t >= d) ? sh[t - d] : 0;
        __syncthreads();
        sh[t] += u;
        __syncthreads();
    }
    if (i < N) {
        int excl = sh[t] - v + g_boff[blockIdx.x];
        g_off[i] = excl;
        g_cur[i] = excl;
    }
}

__global__ void scatter_kernel(const void* __restrict__ ei, int E) {
    int e = blockIdx.x * blockDim.x + threadIdx.x;
    if (e >= E) return;
    int s, d;
    if (g_is32) {
        const int* p = (const int*)ei;
        s = p[e];
        d = p[E + e];
    } else {
        const long long* p = (const long long*)ei;
        s = (int)p[e];
        d = (int)p[E + e];
    }
    int pidx = atomicAdd(&g_cur[d], 1);
    g_csr_src[pidx] = s;
}

// ---------------------------------------------------------------------------
// Generic small SGEMM with bias (skip M=32 and classifier M=40), fp32 SIMT
// ---------------------------------------------------------------------------
#define BM 64
#define BN 64
#define BK 16

__global__ __launch_bounds__(256)
void sgemm_bias_kernel(const float* __restrict__ A, const float* __restrict__ B,
                       const float* __restrict__ bias, float* __restrict__ C,
                       int N, int K, int M) {
    __shared__ float As[BK][BM];
    __shared__ float Bs[BK][BN];

    const int tid  = threadIdx.x;
    const int row0 = blockIdx.x * BM;
    const int col0 = blockIdx.y * BN;
    const int tr   = (tid >> 4) << 2;
    const int tc   = (tid & 15) << 2;

    float acc[4][4] = {};

    for (int k0 = 0; k0 < K; k0 += BK) {
        #pragma unroll
        for (int i = tid; i < BM * BK; i += 256) {
            int r = i / BK, c = i % BK;
            float v = 0.f;
            int gr = row0 + r;
            if (gr < N) v = A[(size_t)gr * K + (k0 + c)];
            As[c][r] = v;
        }
        #pragma unroll
        for (int i = tid; i < BK * BN; i += 256) {
            int r = i / BN, c = i % BN;
            float v = 0.f;
            int gc = col0 + c;
            if (gc < M) v = B[(size_t)(k0 + r) * M + gc];
            Bs[r][c] = v;
        }
        __syncthreads();

        #pragma unroll
        for (int kk = 0; kk < BK; kk++) {
            float a[4], b[4];
            #pragma unroll
            for (int i = 0; i < 4; i++) a[i] = As[kk][tr + i];
            #pragma unroll
            for (int j = 0; j < 4; j++) b[j] = Bs[kk][tc + j];
            #pragma unroll
            for (int i = 0; i < 4; i++)
                #pragma unroll
                for (int j = 0; j < 4; j++)
                    acc[i][j] += a[i] * b[j];
        }
        __syncthreads();
    }

    #pragma unroll
    for (int i = 0; i < 4; i++) {
        int r = row0 + tr + i;
        if (r >= N) continue;
        #pragma unroll
        for (int j = 0; j < 4; j++) {
            int c = col0 + tc + j;
            if (c < M) C[(size_t)r * M + c] = acc[i][j] + bias[c];
        }
    }
}

// ---------------------------------------------------------------------------
// Single-pass fused attention, fp16 KV gather (half the bytes of round 6).
// One warp per dst node; lane l: head l/8, channels 4*(l%8)..+3.
// ---------------------------------------------------------------------------
__device__ __forceinline__ float4 ld_half4(const __half* p) {
    uint2 u = *(const uint2*)p;
    float2 f0 = __half22float2(*(const __half2*)&u.x);
    float2 f1 = __half22float2(*(const __half2*)&u.y);
    return make_float4(f0.x, f0.y, f1.x, f1.y);
}

__global__ __launch_bounds__(256)
void attn_fused_kernel(const float* __restrict__ Q, const __half* __restrict__ KV,
                       const float* __restrict__ skip,
                       float* __restrict__ out, int N, int E) {
    int n = (blockIdx.x * blockDim.x + threadIdx.x) >> 5;
    if (n >= N) return;
    const int lane = threadIdx.x & 31;
    const int beg = g_off[n];
    const int end = (n + 1 < N) ? g_off[n + 1] : E;

    const float4 q = *(const float4*)(Q + (size_t)n * FDIM + lane * 4);

    float den = 0.f;
    float a0 = 0.f, a1 = 0.f, a2 = 0.f, a3 = 0.f;
    const float scale = 0.17677669529663687f;  // 1/sqrt(32)

    for (int base = beg; base < end; base += 32) {
        int myidx = (base + lane < end) ? g_csr_src[base + lane] : 0;
        int rem = end - base;
        int cnt = rem < 32 ? rem : 32;
        int j = 0;
        for (; j + 1 < cnt; j += 2) {
            int s0 = __shfl_sync(0xffffffffu, myidx, j);
            int s1 = __shfl_sync(0xffffffffu, myidx, j + 1);
            const __half* kv0 = KV + (size_t)s0 * 256 + lane * 4;
            const __half* kv1 = KV + (size_t)s1 * 256 + lane * 4;
            float4 k0 = ld_half4(kv0);
            float4 v0 = ld_half4(kv0 + 128);
            float4 k1 = ld_half4(kv1);
            float4 v1 = ld_half4(kv1 + 128);
            float d0 = q.x * k0.x + q.y * k0.y + q.z * k0.z + q.w * k0.w;
            float d1 = q.x * k1.x + q.y * k1.y + q.z * k1.z + q.w * k1.w;
            d0 += __shfl_xor_sync(0xffffffffu, d0, 4);
            d1 += __shfl_xor_sync(0xffffffffu, d1, 4);
            d0 += __shfl_xor_sync(0xffffffffu, d0, 2);
            d1 += __shfl_xor_sync(0xffffffffu, d1, 2);
            d0 += __shfl_xor_sync(0xffffffffu, d0, 1);
            d1 += __shfl_xor_sync(0xffffffffu, d1, 1);
            float w0 = __expf(d0 * scale);
            float w1 = __expf(d1 * scale);
            den += w0 + w1;
            a0 = fmaf(w0, v0.x, fmaf(w1, v1.x, a0));
            a1 = fmaf(w0, v0.y, fmaf(w1, v1.y, a1));
            a2 = fmaf(w0, v0.z, fmaf(w1, v1.z, a2));
            a3 = fmaf(w0, v0.w, fmaf(w1, v1.w, a3));
        }
        if (j < cnt) {
            int s0 = __shfl_sync(0xffffffffu, myidx, j);
            const __half* kv0 = KV + (size_t)s0 * 256 + lane * 4;
            float4 k0 = ld_half4(kv0);
            float4 v0 = ld_half4(kv0 + 128);
            float d0 = q.x * k0.x + q.y * k0.y + q.z * k0.z + q.w * k0.w;
            d0 += __shfl_xor_sync(0xffffffffu, d0, 4);
            d0 += __shfl_xor_sync(0xffffffffu, d0, 2);
            d0 += __shfl_xor_sync(0xffffffffu, d0, 1);
            float w0 = __expf(d0 * scale);
            den += w0;
            a0 = fmaf(w0, v0.x, a0);
            a1 = fmaf(w0, v0.y, a1);
            a2 = fmaf(w0, v0.z, a2);
            a3 = fmaf(w0, v0.w, a3);
        }
    }

    const float rden = 1.f / (den + 1e-16f);
    a0 *= rden; a1 *= rden; a2 *= rden; a3 *= rden;

    #pragma unroll
    for (int dd = 8; dd <= 16; dd <<= 1) {
        a0 += __shfl_xor_sync(0xffffffffu, a0, dd);
        a1 += __shfl_xor_sync(0xffffffffu, a1, dd);
        a2 += __shfl_xor_sync(0xffffffffu, a2, dd);
        a3 += __shfl_xor_sync(0xffffffffu, a3, dd);
    }

    if (lane < 8) {
        float4 sk = *(const float4*)(skip + (size_t)n * CPH + lane * 4);
        float4 o;
        o.x = fmaxf(a0 * 0.25f + sk.x, 0.f);
        o.y = fmaxf(a1 * 0.25f + sk.y, 0.f);
        o.z = fmaxf(a2 * 0.25f + sk.z, 0.f);
        o.w = fmaxf(a3 * 0.25f + sk.w, 0.f);
        *(float4*)(out + (size_t)n * CPH + lane * 4) = o;
    }
}

// ---------------------------------------------------------------------------
// Host orchestration
// ---------------------------------------------------------------------------
static inline unsigned int ceil_div(unsigned int a, unsigned int b) { return (a + b - 1) / b; }

static void run_layer(const float* X, int Kdim,
                      const float* wq, const float* bq,
                      const float* wk, const float* bk,
                      const float* wv, const float* bv,
                      const float* ws, const float* bs,
                      float* Qp, __half* KVp, float* skipp,
                      float* hout, int N, int E) {
    dim3 gq(ceil_div(N, 128), 3);
    hmma_gemm_kernel<<<gq, 256>>>(X, wq, wk, wv, bq, bk, bv, Qp, KVp, N, Kdim);
    dim3 gs(ceil_div(N, BM), 1);
    sgemm_bias_kernel<<<gs, 256>>>(X, ws, bs, skipp, N, Kdim, CPH);

    attn_fused_kernel<<<ceil_div(N, 8), 256>>>(Qp, KVp, skipp, hout, N, E);
}

extern "C" void kernel_launch(void* const* d_in, const int* in_sizes, int n_in,
                              void* d_out, int out_size) {
    const float* x   = (const float*)d_in[0];
    const void*  ei  = d_in[1];
    const float* wq1 = (const float*)d_in[2];
    const float* bq1 = (const float*)d_in[3];
    const float* wk1 = (const float*)d_in[4];
    const float* bk1 = (const float*)d_in[5];
    const float* wv1 = (const float*)d_in[6];
    const float* bv1 = (const float*)d_in[7];
    const float* ws1 = (const float*)d_in[8];
    const float* bs1 = (const float*)d_in[9];
    const float* wq2 = (const float*)d_in[10];
    const float* bq2 = (const float*)d_in[11];
    const float* wk2 = (const float*)d_in[12];
    const float* bk2 = (const float*)d_in[13];
    const float* wv2 = (const float*)d_in[14];
    const float* bv2 = (const float*)d_in[15];
    const float* ws2 = (const float*)d_in[16];
    const float* bs2 = (const float*)d_in[17];
    const float* wc  = (const float*)d_in[18];
    const float* bc  = (const float*)d_in[19];

    const int N = in_sizes[0] / FDIM;   // x is [N,128]
    const int E = in_sizes[1] / 2;      // edge_index is [2,E]

    float  *Qp, *skipp, *h1p, *h2p;
    __half *KVp;
    cudaGetSymbolAddress((void**)&Qp,    g_Q);
    cudaGetSymbolAddress((void**)&KVp,   g_KV);
    cudaGetSymbolAddress((void**)&skipp, g_skip);
    cudaGetSymbolAddress((void**)&h1p,   g_h1);
    cudaGetSymbolAddress((void**)&h2p,   g_h2);

    const int NB = (N + SCAN_B - 1) / SCAN_B;

    init_pre_kernel<<<ceil_div((unsigned)N, 256u), 256>>>(N);
    detect_dtype_kernel<<<592, 256>>>((const uint2*)ei, E);
    hist_kernel<<<ceil_div((unsigned)E, 256u), 256>>>(ei, E);
    scan_p1_kernel<<<NB, SCAN_B>>>(N);
    scan_p2_kernel<<<1, SCAN_B>>>(NB);
    scan_p3_kernel<<<NB, SCAN_B>>>(N);
    scatter_kernel<<<ceil_div((unsigned)E, 256u), 256>>>(ei, E);

    run_layer(x, FDIM, wq1, bq1, wk1, bk1, wv1, bv1, ws1, bs1,
              Qp, KVp, skipp, h1p, N, E);
    run_layer(h1p, CPH, wq2, bq2, wk2, bk2, wv2, bv2, ws2, bs2,
              Qp, KVp, skipp, h2p, N, E);

    dim3 gc(ceil_div((unsigned)N, BM), 1);
    sgemm_bias_kernel<<<gc, 256>>>(h2p, wc, bc, (float*)d_out, N, CPH, 40);
}

// round 8
// speedup vs baseline: 4.0702x; 1.0717x over previous
#include <cuda_runtime.h>
#include <cuda_fp16.h>
#include <math_constants.h>
#include <cstdint>

// ---------------------------------------------------------------------------
// GraphTransformerModel: 2x TransformerConv (H=4, C=32, concat=False) + Linear
// N=50000, E=800000, D=128, HID=32, OUT=40
// Round 8: single fused QKV+skip HMMA kernel per layer (A staged once),
// fp16 KV storage, single-pass flash attention.
// ---------------------------------------------------------------------------

#define NMAX 50000
#define EMAX 800000
#define HEADS 4
#define CPH 32
#define FDIM 128
#define SCAN_B 256

// ---- static device scratch ----
__device__ float  g_Q[NMAX * FDIM];
__device__ __half g_KV[(size_t)NMAX * 256];  // K row (128 h) | V row (128 h)
__device__ float  g_skip[NMAX * CPH];
__device__ float  g_h1[NMAX * CPH];
__device__ float  g_h2[NMAX * CPH];
__device__ int    g_csr_src[EMAX];
__device__ int    g_deg[NMAX];
__device__ int    g_off[NMAX];
__device__ int    g_cur[NMAX];
__device__ int    g_bsum[SCAN_B];
__device__ int    g_boff[SCAN_B];
__device__ int    g_is32;

// ---------------------------------------------------------------------------
// Fused QKV+skip HMMA GEMM. One CTA = 128 rows. A tile staged ONCE (full K),
// then 4 weight matrices consumed: Q (fp32 out), K, V (fp16 out, packed KV),
// S=skip (M=32, fp32 out). 256 threads.
// QKV: 8 warps as 2x4, warp tile 64x32.  S: 8 warps as 8x1, warp tile 16x32.
// A layout: [row][k] halves, row stride Kdim+8 (bank-conflict-free fragment
// loads: ((Kdim+8)/2 mod 32) in {4,20} spreads 8 rows over distinct banks).
// B layout: [n][k] halves, row stride 24.
// ---------------------------------------------------------------------------
#define LDH 24   // B smem row halves (16 data + 8 pad) -> 12 u32

__device__ __forceinline__ void mma16816(float* d, const uint32_t* a,
                                         const uint32_t* b) {
    asm volatile(
        "mma.sync.aligned.m16n8k16.row.col.f32.f16.f16.f32 "
        "{%0,%1,%2,%3}, {%4,%5,%6,%7}, {%8,%9}, {%0,%1,%2,%3};"
        : "+f"(d[0]), "+f"(d[1]), "+f"(d[2]), "+f"(d[3])
        : "r"(a[0]), "r"(a[1]), "r"(a[2]), "r"(a[3]), "r"(b[0]), "r"(b[1]));
}

__global__ __launch_bounds__(256)
void hmma_qkvs_kernel(const float* __restrict__ A,
                      const float* __restrict__ Wq, const float* __restrict__ Wk,
                      const float* __restrict__ Wv, const float* __restrict__ Ws,
                      const float* __restrict__ bq, const float* __restrict__ bk,
                      const float* __restrict__ bv, const float* __restrict__ bs,
                      float* __restrict__ Cq, __half* __restrict__ CKV,
                      float* __restrict__ Cs,
                      int N, int Kdim) {
    __shared__ __half sA[128 * 136];   // sized for Kdim=128 (+8 pad)
    __shared__ __half sB[128 * LDH];

    const int tid  = threadIdx.x;
    const int wid  = tid >> 5;
    const int lane = tid & 31;
    const int wm   = wid >> 2;          // 0..1 (QKV layout)
    const int wn   = wid & 3;           // 0..3
    const int row0 = blockIdx.x * 128;
    const int lr   = lane >> 2;         // 0..7
    const int lc   = lane & 3;          // 0..3

    const int ldwh  = Kdim + 8;         // A row stride in halves
    const int ldw32 = ldwh >> 1;        // in u32
    const uint32_t* sA32 = (const uint32_t*)sA;
    const uint32_t* sB32 = (const uint32_t*)sB;

    // ---- stage FULL A tile once: 128 rows x Kdim, fp32 -> fp16 ----
    {
        const int kd4 = Kdim >> 2;
        for (int idx = tid; idx < 128 * kd4; idx += 256) {
            int r  = idx / kd4;
            int c4 = idx - r * kd4;
            int gr = min(row0 + r, N - 1);
            float4 a = *(const float4*)(A + (size_t)gr * Kdim + c4 * 4);
            __half2* dst = (__half2*)(sA + r * ldwh) + c4 * 2;
            dst[0] = __floats2half2_rn(a.x, a.y);
            dst[1] = __floats2half2_rn(a.z, a.w);
        }
    }

    const int nsteps = Kdim >> 4;

    // ---- matrices 0..3: Q, K, V, S ----
    #pragma unroll 1
    for (int m = 0; m < 4; m++) {
        const float* W;
        const float* bias;
        int Mcols;
        if (m == 0)      { W = Wq; bias = bq; Mcols = 128; }
        else if (m == 1) { W = Wk; bias = bk; Mcols = 128; }
        else if (m == 2) { W = Wv; bias = bv; Mcols = 128; }
        else             { W = Ws; bias = bs; Mcols = 32;  }

        float acc[4][4][4] = {};
        const int nb4 = Mcols * 4;      // float4s per 16-k B slab

        for (int step = 0; step < nsteps; step++) {
            const int k0  = step << 4;
            const int kw0 = step << 3;  // u32 offset into A row
            __syncthreads();
            for (int idx = tid; idx < nb4; idx += 256) {
                int kk = idx / (Mcols >> 2);
                int n4 = idx - kk * (Mcols >> 2);
                float4 w = *(const float4*)(W + (size_t)(k0 + kk) * Mcols + n4 * 4);
                sB[(n4 * 4 + 0) * LDH + kk] = __float2half_rn(w.x);
                sB[(n4 * 4 + 1) * LDH + kk] = __float2half_rn(w.y);
                sB[(n4 * 4 + 2) * LDH + kk] = __float2half_rn(w.z);
                sB[(n4 * 4 + 3) * LDH + kk] = __float2half_rn(w.w);
            }
            __syncthreads();

            if (m < 3) {
                uint32_t af[4][4], bf[4][2];
                #pragma unroll
                for (int mt = 0; mt < 4; mt++) {
                    int rm = wm * 64 + mt * 16;
                    #pragma unroll
                    for (int j = 0; j < 4; j++)
                        af[mt][j] = sA32[(rm + lr + (j & 1) * 8) * ldw32 +
                                         kw0 + lc + (j >> 1) * 4];
                }
                #pragma unroll
                for (int nt = 0; nt < 4; nt++) {
                    int cn = wn * 32 + nt * 8;
                    bf[nt][0] = sB32[(cn + lr) * 12 + lc];
                    bf[nt][1] = sB32[(cn + lr) * 12 + lc + 4];
                }
                #pragma unroll
                for (int mt = 0; mt < 4; mt++)
                    #pragma unroll
                    for (int nt = 0; nt < 4; nt++)
                        mma16816(acc[mt][nt], af[mt], bf[nt]);
            } else {
                // skip matrix: 8 warps x (16 rows), 32 cols; use acc[0][nt]
                uint32_t af[4], bf[4][2];
                int rm = wid * 16;
                #pragma unroll
                for (int j = 0; j < 4; j++)
                    af[j] = sA32[(rm + lr + (j & 1) * 8) * ldw32 +
                                 kw0 + lc + (j >> 1) * 4];
                #pragma unroll
                for (int nt = 0; nt < 4; nt++) {
                    int cn = nt * 8;
                    bf[nt][0] = sB32[(cn + lr) * 12 + lc];
                    bf[nt][1] = sB32[(cn + lr) * 12 + lc + 4];
                }
                #pragma unroll
                for (int nt = 0; nt < 4; nt++)
                    mma16816(acc[0][nt], af, bf[nt]);
            }
        }

        // ---- epilogue ----
        if (m < 3) {
            #pragma unroll
            for (int mt = 0; mt < 4; mt++) {
                int r0 = row0 + wm * 64 + mt * 16 + lr;
                #pragma unroll
                for (int nt = 0; nt < 4; nt++) {
                    int gc = wn * 32 + nt * 8 + lc * 2;
                    float bx = bias[gc], by = bias[gc + 1];
                    if (m == 0) {
                        if (r0 < N)
                            *(float2*)(Cq + (size_t)r0 * 128 + gc) =
                                make_float2(acc[mt][nt][0] + bx, acc[mt][nt][1] + by);
                        if (r0 + 8 < N)
                            *(float2*)(Cq + (size_t)(r0 + 8) * 128 + gc) =
                                make_float2(acc[mt][nt][2] + bx, acc[mt][nt][3] + by);
                    } else {
                        int coloff = (m == 2) ? 128 : 0;
                        if (r0 < N)
                            *(__half2*)(CKV + (size_t)r0 * 256 + coloff + gc) =
                                __floats2half2_rn(acc[mt][nt][0] + bx, acc[mt][nt][1] + by);
                        if (r0 + 8 < N)
                            *(__half2*)(CKV + (size_t)(r0 + 8) * 256 + coloff + gc) =
                                __floats2half2_rn(acc[mt][nt][2] + bx, acc[mt][nt][3] + by);
                    }
                }
            }
        } else {
            int r0 = row0 + wid * 16 + lr;
            #pragma unroll
            for (int nt = 0; nt < 4; nt++) {
                int gc = nt * 8 + lc * 2;
                float bx = bias[gc], by = bias[gc + 1];
                if (r0 < N)
                    *(float2*)(Cs + (size_t)r0 * 32 + gc) =
                        make_float2(acc[0][nt][0] + bx, acc[0][nt][1] + by);
                if (r0 + 8 < N)
                    *(float2*)(Cs + (size_t)(r0 + 8) * 32 + gc) =
                        make_float2(acc[0][nt][2] + bx, acc[0][nt][3] + by);
            }
        }
    }
}

// ---------------------------------------------------------------------------
// Preprocessing (unchanged)
// ---------------------------------------------------------------------------
__global__ void init_pre_kernel(int N) {
    int i = blockIdx.x * blockDim.x + threadIdx.x;
    if (i == 0) g_is32 = 0;
    if (i < N) g_deg[i] = 0;
}

__global__ void detect_dtype_kernel(const uint2* __restrict__ w, int npairs) {
    int i = blockIdx.x * blockDim.x + threadIdx.x;
    int stride = gridDim.x * blockDim.x;
    for (; i < npairs; i += stride)
        if (w[i].y != 0u) { g_is32 = 1; break; }
}

__global__ void hist_kernel(const void* __restrict__ ei, int E) {
    int e = blockIdx.x * blockDim.x + threadIdx.x;
    if (e >= E) return;
    int d;
    if (g_is32) d = ((const int*)ei)[E + e];
    else        d = (int)((const long long*)ei)[E + e];
    atomicAdd(&g_deg[d], 1);
}

__global__ __launch_bounds__(SCAN_B)
void scan_p1_kernel(int N) {
    __shared__ int sh[SCAN_B];
    int t = threadIdx.x;
    int i = blockIdx.x * SCAN_B + t;
    int v = (i < N) ? g_deg[i] : 0;
    sh[t] = v;
    __syncthreads();
    #pragma unroll
    for (int s = SCAN_B / 2; s > 0; s >>= 1) {
        if (t < s) sh[t] += sh[t + s];
        __syncthreads();
    }
    if (t == 0) g_bsum[blockIdx.x] = sh[0];
}

__global__ __launch_bounds__(SCAN_B)
void scan_p2_kernel(int NB) {
    __shared__ int sh[SCAN_B];
    int t = threadIdx.x;
    int v = (t < NB) ? g_bsum[t] : 0;
    sh[t] = v;
    __syncthreads();
    #pragma unroll
    for (int d = 1; d < SCAN_B; d <<= 1) {
        int u = (t >= d) ? sh[t - d] : 0;
        __syncthreads();
        sh[t] += u;
        __syncthreads();
    }
    if (t < NB) g_boff[t] = sh[t] - v;
}

__global__ __launch_bounds__(SCAN_B)
void scan_p3_kernel(int N) {
    __shared__ int sh[SCAN_B];
    int t = threadIdx.x;
    int i = blockIdx.x * SCAN_B + t;
    int v = (i < N) ? g_deg[i] : 0;
    sh[t] = v;
    __syncthreads();
    #pragma unroll
    for (int d = 1; d < SCAN_B; d <<= 1) {
        int u = (t >= d) ? sh[t - d] : 0;
        __syncthreads();
        sh[t] += u;
        __syncthreads();
    }
    if (i < N) {
        int excl = sh[t] - v + g_boff[blockIdx.x];
        g_off[i] = excl;
        g_cur[i] = excl;
    }
}

__global__ void scatter_kernel(const void* __restrict__ ei, int E) {
    int e = blockIdx.x * blockDim.x + threadIdx.x;
    if (e >= E) return;
    int s, d;
    if (g_is32) {
        const int* p = (const int*)ei;
        s = p[e];
        d = p[E + e];
    } else {
        const long long* p = (const long long*)ei;
        s = (int)p[e];
        d = (int)p[E + e];
    }
    int pidx = atomicAdd(&g_cur[d], 1);
    g_csr_src[pidx] = s;
}

// ---------------------------------------------------------------------------
// fp32 SIMT SGEMM with bias (classifier only: M=40, K=32)
// ---------------------------------------------------------------------------
#define BM 64
#define BN 64
#define BK 16

__global__ __launch_bounds__(256)
void sgemm_bias_kernel(const float* __restrict__ A, const float* __restrict__ B,
                       const float* __restrict__ bias, float* __restrict__ C,
                       int N, int K, int M) {
    __shared__ float As[BK][BM];
    __shared__ float Bs[BK][BN];

    const int tid  = threadIdx.x;
    const int row0 = blockIdx.x * BM;
    const int col0 = blockIdx.y * BN;
    const int tr   = (tid >> 4) << 2;
    const int tc   = (tid & 15) << 2;

    float acc[4][4] = {};

    for (int k0 = 0; k0 < K; k0 += BK) {
        #pragma unroll
        for (int i = tid; i < BM * BK; i += 256) {
            int r = i / BK, c = i % BK;
            float v = 0.f;
            int gr = row0 + r;
            if (gr < N) v = A[(size_t)gr * K + (k0 + c)];
            As[c][r] = v;
        }
        #pragma unroll
        for (int i = tid; i < BK * BN; i += 256) {
            int r = i / BN, c = i % BN;
            float v = 0.f;
            int gc = col0 + c;
            if (gc < M) v = B[(size_t)(k0 + r) * M + gc];
            Bs[r][c] = v;
        }
        __syncthreads();

        #pragma unroll
        for (int kk = 0; kk < BK; kk++) {
            float a[4], b[4];
            #pragma unroll
            for (int i = 0; i < 4; i++) a[i] = As[kk][tr + i];
            #pragma unroll
            for (int j = 0; j < 4; j++) b[j] = Bs[kk][tc + j];
            #pragma unroll
            for (int i = 0; i < 4; i++)
                #pragma unroll
                for (int j = 0; j < 4; j++)
                    acc[i][j] += a[i] * b[j];
        }
        __syncthreads();
    }

    #pragma unroll
    for (int i = 0; i < 4; i++) {
        int r = row0 + tr + i;
        if (r >= N) continue;
        #pragma unroll
        for (int j = 0; j < 4; j++) {
            int c = col0 + tc + j;
            if (c < M) C[(size_t)r * M + c] = acc[i][j] + bias[c];
        }
    }
}

// ---------------------------------------------------------------------------
// Single-pass fused attention, fp16 KV gather (unchanged from round 7)
// ---------------------------------------------------------------------------
__device__ __forceinline__ float4 ld_half4(const __half* p) {
    uint2 u = *(const uint2*)p;
    float2 f0 = __half22float2(*(const __half2*)&u.x);
    float2 f1 = __half22float2(*(const __half2*)&u.y);
    return make_float4(f0.x, f0.y, f1.x, f1.y);
}

__global__ __launch_bounds__(256)
void attn_fused_kernel(const float* __restrict__ Q, const __half* __restrict__ KV,
                       const float* __restrict__ skip,
                       float* __restrict__ out, int N, int E) {
    int n = (blockIdx.x * blockDim.x + threadIdx.x) >> 5;
    if (n >= N) return;
    const int lane = threadIdx.x & 31;
    const int beg = g_off[n];
    const int end = (n + 1 < N) ? g_off[n + 1] : E;

    const float4 q = *(const float4*)(Q + (size_t)n * FDIM + lane * 4);

    float den = 0.f;
    float a0 = 0.f, a1 = 0.f, a2 = 0.f, a3 = 0.f;
    const float scale = 0.17677669529663687f;  // 1/sqrt(32)

    for (int base = beg; base < end; base += 32) {
        int myidx = (base + lane < end) ? g_csr_src[base + lane] : 0;
        int rem = end - base;
        int cnt = rem < 32 ? rem : 32;
        int j = 0;
        for (; j + 1 < cnt; j += 2) {
            int s0 = __shfl_sync(0xffffffffu, myidx, j);
            int s1 = __shfl_sync(0xffffffffu, myidx, j + 1);
            const __half* kv0 = KV + (size_t)s0 * 256 + lane * 4;
            const __half* kv1 = KV + (size_t)s1 * 256 + lane * 4;
            float4 k0 = ld_half4(kv0);
            float4 v0 = ld_half4(kv0 + 128);
            float4 k1 = ld_half4(kv1);
            float4 v1 = ld_half4(kv1 + 128);
            float d0 = q.x * k0.x + q.y * k0.y + q.z * k0.z + q.w * k0.w;
            float d1 = q.x * k1.x + q.y * k1.y + q.z * k1.z + q.w * k1.w;
            d0 += __shfl_xor_sync(0xffffffffu, d0, 4);
            d1 += __shfl_xor_sync(0xffffffffu, d1, 4);
            d0 += __shfl_xor_sync(0xffffffffu, d0, 2);
            d1 += __shfl_xor_sync(0xffffffffu, d1, 2);
            d0 += __shfl_xor_sync(0xffffffffu, d0, 1);
            d1 += __shfl_xor_sync(0xffffffffu, d1, 1);
            float w0 = __expf(d0 * scale);
            float w1 = __expf(d1 * scale);
            den += w0 + w1;
            a0 = fmaf(w0, v0.x, fmaf(w1, v1.x, a0));
            a1 = fmaf(w0, v0.y, fmaf(w1, v1.y, a1));
            a2 = fmaf(w0, v0.z, fmaf(w1, v1.z, a2));
            a3 = fmaf(w0, v0.w, fmaf(w1, v1.w, a3));
        }
        if (j < cnt) {
            int s0 = __shfl_sync(0xffffffffu, myidx, j);
            const __half* kv0 = KV + (size_t)s0 * 256 + lane * 4;
            float4 k0 = ld_half4(kv0);
            float4 v0 = ld_half4(kv0 + 128);
            float d0 = q.x * k0.x + q.y * k0.y + q.z * k0.z + q.w * k0.w;
            d0 += __shfl_xor_sync(0xffffffffu, d0, 4);
            d0 += __shfl_xor_sync(0xffffffffu, d0, 2);
            d0 += __shfl_xor_sync(0xffffffffu, d0, 1);
            float w0 = __expf(d0 * scale);
            den += w0;
            a0 = fmaf(w0, v0.x, a0);
            a1 = fmaf(w0, v0.y, a1);
            a2 = fmaf(w0, v0.z, a2);
            a3 = fmaf(w0, v0.w, a3);
        }
    }

    const float rden = 1.f / (den + 1e-16f);
    a0 *= rden; a1 *= rden; a2 *= rden; a3 *= rden;

    #pragma unroll
    for (int dd = 8; dd <= 16; dd <<= 1) {
        a0 += __shfl_xor_sync(0xffffffffu, a0, dd);
        a1 += __shfl_xor_sync(0xffffffffu, a1, dd);
        a2 += __shfl_xor_sync(0xffffffffu, a2, dd);
        a3 += __shfl_xor_sync(0xffffffffu, a3, dd);
    }

    if (lane < 8) {
        float4 sk = *(const float4*)(skip + (size_t)n * CPH + lane * 4);
        float4 o;
        o.x = fmaxf(a0 * 0.25f + sk.x, 0.f);
        o.y = fmaxf(a1 * 0.25f + sk.y, 0.f);
        o.z = fmaxf(a2 * 0.25f + sk.z, 0.f);
        o.w = fmaxf(a3 * 0.25f + sk.w, 0.f);
        *(float4*)(out + (size_t)n * CPH + lane * 4) = o;
    }
}

// ---------------------------------------------------------------------------
// Host orchestration
// ---------------------------------------------------------------------------
static inline unsigned int ceil_div(unsigned int a, unsigned int b) { return (a + b - 1) / b; }

static void run_layer(const float* X, int Kdim,
                      const float* wq, const float* bq,
                      const float* wk, const float* bk,
                      const float* wv, const float* bv,
                      const float* ws, const float* bs,
                      float* Qp, __half* KVp, float* skipp,
                      float* hout, int N, int E) {
    hmma_qkvs_kernel<<<ceil_div(N, 128), 256>>>(
        X, wq, wk, wv, ws, bq, bk, bv, bs, Qp, KVp, skipp, N, Kdim);
    attn_fused_kernel<<<ceil_div(N, 8), 256>>>(Qp, KVp, skipp, hout, N, E);
}

extern "C" void kernel_launch(void* const* d_in, const int* in_sizes, int n_in,
                              void* d_out, int out_size) {
    const float* x   = (const float*)d_in[0];
    const void*  ei  = d_in[1];
    const float* wq1 = (const float*)d_in[2];
    const float* bq1 = (const float*)d_in[3];
    const float* wk1 = (const float*)d_in[4];
    const float* bk1 = (const float*)d_in[5];
    const float* wv1 = (const float*)d_in[6];
    const float* bv1 = (const float*)d_in[7];
    const float* ws1 = (const float*)d_in[8];
    const float* bs1 = (const float*)d_in[9];
    const float* wq2 = (const float*)d_in[10];
    const float* bq2 = (const float*)d_in[11];
    const float* wk2 = (const float*)d_in[12];
    const float* bk2 = (const float*)d_in[13];
    const float* wv2 = (const float*)d_in[14];
    const float* bv2 = (const float*)d_in[15];
    const float* ws2 = (const float*)d_in[16];
    const float* bs2 = (const float*)d_in[17];
    const float* wc  = (const float*)d_in[18];
    const float* bc  = (const float*)d_in[19];

    const int N = in_sizes[0] / FDIM;   // x is [N,128]
    const int E = in_sizes[1] / 2;      // edge_index is [2,E]

    float  *Qp, *skipp, *h1p, *h2p;
    __half *KVp;
    cudaGetSymbolAddress((void**)&Qp,    g_Q);
    cudaGetSymbolAddress((void**)&KVp,   g_KV);
    cudaGetSymbolAddress((void**)&skipp, g_skip);
    cudaGetSymbolAddress((void**)&h1p,   g_h1);
    cudaGetSymbolAddress((void**)&h2p,   g_h2);

    const int NB = (N + SCAN_B - 1) / SCAN_B;

    init_pre_kernel<<<ceil_div((unsigned)N, 256u), 256>>>(N);
    detect_dtype_kernel<<<592, 256>>>((const uint2*)ei, E);
    hist_kernel<<<ceil_div((unsigned)E, 256u), 256>>>(ei, E);
    scan_p1_kernel<<<NB, SCAN_B>>>(N);
    scan_p2_kernel<<<1, SCAN_B>>>(NB);
    scan_p3_kernel<<<NB, SCAN_B>>>(N);
    scatter_kernel<<<ceil_div((unsigned)E, 256u), 256>>>(ei, E);

    run_layer(x, FDIM, wq1, bq1, wk1, bk1, wv1, bv1, ws1, bs1,
              Qp, KVp, skipp, h1p, N, E);
    run_layer(h1p, CPH, wq2, bq2, wk2, bk2, wv2, bv2, ws2, bs2,
              Qp, KVp, skipp, h2p, N, E);

    dim3 gc(ceil_div((unsigned)N, BM), 1);
    sgemm_bias_kernel<<<gc, 256>>>(h2p, wc, bc, (float*)d_out, N, CPH, 40);
}

// round 9
// speedup vs baseline: 4.1622x; 1.0226x over previous
#include <cuda_runtime.h>
#include <cuda_fp16.h>
#include <math_constants.h>
#include <cstdint>

// ---------------------------------------------------------------------------
// GraphTransformerModel: 2x TransformerConv (H=4, C=32, concat=False) + Linear
// N=50000, E=800000, D=128, HID=32, OUT=40
// Round 9: classifier fused into layer-2 attention epilogue; CSR preprocessing
// overlapped with layer-1 GEMM on a forked stream. Precision unchanged.
// ---------------------------------------------------------------------------

#define NMAX 50000
#define EMAX 800000
#define HEADS 4
#define CPH 32
#define FDIM 128
#define OUTC 40
#define SCAN_B 256

// ---- static device scratch ----
__device__ float  g_Q[NMAX * FDIM];
__device__ __half g_KV[(size_t)NMAX * 256];  // K row (128 h) | V row (128 h)
__device__ float  g_skip[NMAX * CPH];
__device__ float  g_h1[NMAX * CPH];
__device__ int    g_csr_src[EMAX];
__device__ int    g_deg[NMAX];
__device__ int    g_off[NMAX];
__device__ int    g_cur[NMAX];
__device__ int    g_bsum[SCAN_B];
__device__ int    g_boff[SCAN_B];
__device__ int    g_is32;

// ---------------------------------------------------------------------------
// Fused QKV+skip HMMA GEMM (unchanged from round 8).
// ---------------------------------------------------------------------------
#define LDH 24   // B smem row halves (16 data + 8 pad) -> 12 u32

__device__ __forceinline__ void mma16816(float* d, const uint32_t* a,
                                         const uint32_t* b) {
    asm volatile(
        "mma.sync.aligned.m16n8k16.row.col.f32.f16.f16.f32 "
        "{%0,%1,%2,%3}, {%4,%5,%6,%7}, {%8,%9}, {%0,%1,%2,%3};"
        : "+f"(d[0]), "+f"(d[1]), "+f"(d[2]), "+f"(d[3])
        : "r"(a[0]), "r"(a[1]), "r"(a[2]), "r"(a[3]), "r"(b[0]), "r"(b[1]));
}

__global__ __launch_bounds__(256)
void hmma_qkvs_kernel(const float* __restrict__ A,
                      const float* __restrict__ Wq, const float* __restrict__ Wk,
                      const float* __restrict__ Wv, const float* __restrict__ Ws,
                      const float* __restrict__ bq, const float* __restrict__ bk,
                      const float* __restrict__ bv, const float* __restrict__ bs,
                      float* __restrict__ Cq, __half* __restrict__ CKV,
                      float* __restrict__ Cs,
                      int N, int Kdim) {
    __shared__ __half sA[128 * 136];   // sized for Kdim=128 (+8 pad)
    __shared__ __half sB[128 * LDH];

    const int tid  = threadIdx.x;
    const int wid  = tid >> 5;
    const int lane = tid & 31;
    const int wm   = wid >> 2;
    const int wn   = wid & 3;
    const int row0 = blockIdx.x * 128;
    const int lr   = lane >> 2;
    const int lc   = lane & 3;

    const int ldwh  = Kdim + 8;
    const int ldw32 = ldwh >> 1;
    const uint32_t* sA32 = (const uint32_t*)sA;
    const uint32_t* sB32 = (const uint32_t*)sB;

    // stage FULL A tile once: 128 rows x Kdim, fp32 -> fp16
    {
        const int kd4 = Kdim >> 2;
        for (int idx = tid; idx < 128 * kd4; idx += 256) {
            int r  = idx / kd4;
            int c4 = idx - r * kd4;
            int gr = min(row0 + r, N - 1);
            float4 a = *(const float4*)(A + (size_t)gr * Kdim + c4 * 4);
            __half2* dst = (__half2*)(sA + r * ldwh) + c4 * 2;
            dst[0] = __floats2half2_rn(a.x, a.y);
            dst[1] = __floats2half2_rn(a.z, a.w);
        }
    }

    const int nsteps = Kdim >> 4;

    #pragma unroll 1
    for (int m = 0; m < 4; m++) {
        const float* W;
        const float* bias;
        int Mcols;
        if (m == 0)      { W = Wq; bias = bq; Mcols = 128; }
        else if (m == 1) { W = Wk; bias = bk; Mcols = 128; }
        else if (m == 2) { W = Wv; bias = bv; Mcols = 128; }
        else             { W = Ws; bias = bs; Mcols = 32;  }

        float acc[4][4][4] = {};
        const int nb4 = Mcols * 4;

        for (int step = 0; step < nsteps; step++) {
            const int k0  = step << 4;
            const int kw0 = step << 3;
            __syncthreads();
            for (int idx = tid; idx < nb4; idx += 256) {
                int kk = idx / (Mcols >> 2);
                int n4 = idx - kk * (Mcols >> 2);
                float4 w = *(const float4*)(W + (size_t)(k0 + kk) * Mcols + n4 * 4);
                sB[(n4 * 4 + 0) * LDH + kk] = __float2half_rn(w.x);
                sB[(n4 * 4 + 1) * LDH + kk] = __float2half_rn(w.y);
                sB[(n4 * 4 + 2) * LDH + kk] = __float2half_rn(w.z);
                sB[(n4 * 4 + 3) * LDH + kk] = __float2half_rn(w.w);
            }
            __syncthreads();

            if (m < 3) {
                uint32_t af[4][4], bf[4][2];
                #pragma unroll
                for (int mt = 0; mt < 4; mt++) {
                    int rm = wm * 64 + mt * 16;
                    #pragma unroll
                    for (int j = 0; j < 4; j++)
                        af[mt][j] = sA32[(rm + lr + (j & 1) * 8) * ldw32 +
                                         kw0 + lc + (j >> 1) * 4];
                }
                #pragma unroll
                for (int nt = 0; nt < 4; nt++) {
                    int cn = wn * 32 + nt * 8;
                    bf[nt][0] = sB32[(cn + lr) * 12 + lc];
                    bf[nt][1] = sB32[(cn + lr) * 12 + lc + 4];
                }
                #pragma unroll
                for (int mt = 0; mt < 4; mt++)
                    #pragma unroll
                    for (int nt = 0; nt < 4; nt++)
                        mma16816(acc[mt][nt], af[mt], bf[nt]);
            } else {
                uint32_t af[4], bf[4][2];
                int rm = wid * 16;
                #pragma unroll
                for (int j = 0; j < 4; j++)
                    af[j] = sA32[(rm + lr + (j & 1) * 8) * ldw32 +
                                 kw0 + lc + (j >> 1) * 4];
                #pragma unroll
                for (int nt = 0; nt < 4; nt++) {
                    int cn = nt * 8;
                    bf[nt][0] = sB32[(cn + lr) * 12 + lc];
                    bf[nt][1] = sB32[(cn + lr) * 12 + lc + 4];
                }
                #pragma unroll
                for (int nt = 0; nt < 4; nt++)
                    mma16816(acc[0][nt], af, bf[nt]);
            }
        }

        if (m < 3) {
            #pragma unroll
            for (int mt = 0; mt < 4; mt++) {
                int r0 = row0 + wm * 64 + mt * 16 + lr;
                #pragma unroll
                for (int nt = 0; nt < 4; nt++) {
                    int gc = wn * 32 + nt * 8 + lc * 2;
                    float bx = bias[gc], by = bias[gc + 1];
                    if (m == 0) {
                        if (r0 < N)
                            *(float2*)(Cq + (size_t)r0 * 128 + gc) =
                                make_float2(acc[mt][nt][0] + bx, acc[mt][nt][1] + by);
                        if (r0 + 8 < N)
                            *(float2*)(Cq + (size_t)(r0 + 8) * 128 + gc) =
                                make_float2(acc[mt][nt][2] + bx, acc[mt][nt][3] + by);
                    } else {
                        int coloff = (m == 2) ? 128 : 0;
                        if (r0 < N)
                            *(__half2*)(CKV + (size_t)r0 * 256 + coloff + gc) =
                                __floats2half2_rn(acc[mt][nt][0] + bx, acc[mt][nt][1] + by);
                        if (r0 + 8 < N)
                            *(__half2*)(CKV + (size_t)(r0 + 8) * 256 + coloff + gc) =
                                __floats2half2_rn(acc[mt][nt][2] + bx, acc[mt][nt][3] + by);
                    }
                }
            }
        } else {
            int r0 = row0 + wid * 16 + lr;
            #pragma unroll
            for (int nt = 0; nt < 4; nt++) {
                int gc = nt * 8 + lc * 2;
                float bx = bias[gc], by = bias[gc + 1];
                if (r0 < N)
                    *(float2*)(Cs + (size_t)r0 * 32 + gc) =
                        make_float2(acc[0][nt][0] + bx, acc[0][nt][1] + by);
                if (r0 + 8 < N)
                    *(float2*)(Cs + (size_t)(r0 + 8) * 32 + gc) =
                        make_float2(acc[0][nt][2] + bx, acc[0][nt][3] + by);
            }
        }
    }
}

// ---------------------------------------------------------------------------
// Preprocessing (unchanged)
// ---------------------------------------------------------------------------
__global__ void init_pre_kernel(int N) {
    int i = blockIdx.x * blockDim.x + threadIdx.x;
    if (i == 0) g_is32 = 0;
    if (i < N) g_deg[i] = 0;
}

__global__ void detect_dtype_kernel(const uint2* __restrict__ w, int npairs) {
    int i = blockIdx.x * blockDim.x + threadIdx.x;
    int stride = gridDim.x * blockDim.x;
    for (; i < npairs; i += stride)
        if (w[i].y != 0u) { g_is32 = 1; break; }
}

__global__ void hist_kernel(const void* __restrict__ ei, int E) {
    int e = blockIdx.x * blockDim.x + threadIdx.x;
    if (e >= E) return;
    int d;
    if (g_is32) d = ((const int*)ei)[E + e];
    else        d = (int)((const long long*)ei)[E + e];
    atomicAdd(&g_deg[d], 1);
}

__global__ __launch_bounds__(SCAN_B)
void scan_p1_kernel(int N) {
    __shared__ int sh[SCAN_B];
    int t = threadIdx.x;
    int i = blockIdx.x * SCAN_B + t;
    int v = (i < N) ? g_deg[i] : 0;
    sh[t] = v;
    __syncthreads();
    #pragma unroll
    for (int s = SCAN_B / 2; s > 0; s >>= 1) {
        if (t < s) sh[t] += sh[t + s];
        __syncthreads();
    }
    if (t == 0) g_bsum[blockIdx.x] = sh[0];
}

__global__ __launch_bounds__(SCAN_B)
void scan_p2_kernel(int NB) {
    __shared__ int sh[SCAN_B];
    int t = threadIdx.x;
    int v = (t < NB) ? g_bsum[t] : 0;
    sh[t] = v;
    __syncthreads();
    #pragma unroll
    for (int d = 1; d < SCAN_B; d <<= 1) {
        int u = (t >= d) ? sh[t - d] : 0;
        __syncthreads();
        sh[t] += u;
        __syncthreads();
    }
    if (t < NB) g_boff[t] = sh[t] - v;
}

__global__ __launch_bounds__(SCAN_B)
void scan_p3_kernel(int N) {
    __shared__ int sh[SCAN_B];
    int t = threadIdx.x;
    int i = blockIdx.x * SCAN_B + t;
    int v = (i < N) ? g_deg[i] : 0;
    sh[t] = v;
    __syncthreads();
    #pragma unroll
    for (int d = 1; d < SCAN_B; d <<= 1) {
        int u = (t >= d) ? sh[t - d] : 0;
        __syncthreads();
        sh[t] += u;
        __syncthreads();
    }
    if (i < N) {
        int excl = sh[t] - v + g_boff[blockIdx.x];
        g_off[i] = excl;
        g_cur[i] = excl;
    }
}

__global__ void scatter_kernel(const void* __restrict__ ei, int E) {
    int e = blockIdx.x * blockDim.x + threadIdx.x;
    if (e >= E) return;
    int s, d;
    if (g_is32) {
        const int* p = (const int*)ei;
        s = p[e];
        d = p[E + e];
    } else {
        const long long* p = (const long long*)ei;
        s = (int)p[e];
        d = (int)p[E + e];
    }
    int pidx = atomicAdd(&g_cur[d], 1);
    g_csr_src[pidx] = s;
}

// ---------------------------------------------------------------------------
// Single-pass fused attention, fp16 KV gather. One warp per dst node.
// do_cls=0: out[n,32] = relu(attn + skip).
// do_cls=1: classifier fused — out[n,40] = relu(attn + skip) @ wc + bc.
// ---------------------------------------------------------------------------
__device__ __forceinline__ float4 ld_half4(const __half* p) {
    uint2 u = *(const uint2*)p;
    float2 f0 = __half22float2(*(const __half2*)&u.x);
    float2 f1 = __half22float2(*(const __half2*)&u.y);
    return make_float4(f0.x, f0.y, f1.x, f1.y);
}

__global__ __launch_bounds__(256)
void attn_fused_kernel(const float* __restrict__ Q, const __half* __restrict__ KV,
                       const float* __restrict__ skip,
                       float* __restrict__ out,
                       const float* __restrict__ wc, const float* __restrict__ bc,
                       int do_cls, int N, int E) {
    __shared__ float s_wc[CPH * OUTC];
    __shared__ float s_bc[OUTC];
    __shared__ float s_h[8][CPH];

    const int tid  = threadIdx.x;
    const int wid  = tid >> 5;
    const int lane = tid & 31;

    if (do_cls) {
        for (int i = tid; i < CPH * OUTC; i += 256) s_wc[i] = wc[i];
        if (tid < OUTC) s_bc[tid] = bc[tid];
        __syncthreads();
    }

    int n = (blockIdx.x * blockDim.x + tid) >> 5;
    if (n >= N) return;
    const int beg = g_off[n];
    const int end = (n + 1 < N) ? g_off[n + 1] : E;

    const float4 q = *(const float4*)(Q + (size_t)n * FDIM + lane * 4);

    float den = 0.f;
    float a0 = 0.f, a1 = 0.f, a2 = 0.f, a3 = 0.f;
    const float scale = 0.17677669529663687f;  // 1/sqrt(32)

    for (int base = beg; base < end; base += 32) {
        int myidx = (base + lane < end) ? g_csr_src[base + lane] : 0;
        int rem = end - base;
        int cnt = rem < 32 ? rem : 32;
        int j = 0;
        for (; j + 1 < cnt; j += 2) {
            int s0 = __shfl_sync(0xffffffffu, myidx, j);
            int s1 = __shfl_sync(0xffffffffu, myidx, j + 1);
            const __half* kv0 = KV + (size_t)s0 * 256 + lane * 4;
            const __half* kv1 = KV + (size_t)s1 * 256 + lane * 4;
            float4 k0 = ld_half4(kv0);
            float4 v0 = ld_half4(kv0 + 128);
            float4 k1 = ld_half4(kv1);
            float4 v1 = ld_half4(kv1 + 128);
            float d0 = q.x * k0.x + q.y * k0.y + q.z * k0.z + q.w * k0.w;
            float d1 = q.x * k1.x + q.y * k1.y + q.z * k1.z + q.w * k1.w;
            d0 += __shfl_xor_sync(0xffffffffu, d0, 4);
            d1 += __shfl_xor_sync(0xffffffffu, d1, 4);
            d0 += __shfl_xor_sync(0xffffffffu, d0, 2);
            d1 += __shfl_xor_sync(0xffffffffu, d1, 2);
            d0 += __shfl_xor_sync(0xffffffffu, d0, 1);
            d1 += __shfl_xor_sync(0xffffffffu, d1, 1);
            float w0 = __expf(d0 * scale);
            float w1 = __expf(d1 * scale);
            den += w0 + w1;
            a0 = fmaf(w0, v0.x, fmaf(w1, v1.x, a0));
            a1 = fmaf(w0, v0.y, fmaf(w1, v1.y, a1));
            a2 = fmaf(w0, v0.z, fmaf(w1, v1.z, a2));
            a3 = fmaf(w0, v0.w, fmaf(w1, v1.w, a3));
        }
        if (j < cnt) {
            int s0 = __shfl_sync(0xffffffffu, myidx, j);
            const __half* kv0 = KV + (size_t)s0 * 256 + lane * 4;
            float4 k0 = ld_half4(kv0);
            float4 v0 = ld_half4(kv0 + 128);
            float d0 = q.x * k0.x + q.y * k0.y + q.z * k0.z + q.w * k0.w;
            d0 += __shfl_xor_sync(0xffffffffu, d0, 4);
            d0 += __shfl_xor_sync(0xffffffffu, d0, 2);
            d0 += __shfl_xor_sync(0xffffffffu, d0, 1);
            float w0 = __expf(d0 * scale);
            den += w0;
            a0 = fmaf(w0, v0.x, a0);
            a1 = fmaf(w0, v0.y, a1);
            a2 = fmaf(w0, v0.z, a2);
            a3 = fmaf(w0, v0.w, a3);
        }
    }

    const float rden = 1.f / (den + 1e-16f);
    a0 *= rden; a1 *= rden; a2 *= rden; a3 *= rden;

    // head mean: sum over 4 heads (lanes l, l^8, l^16, l^24 share channels)
    #pragma unroll
    for (int dd = 8; dd <= 16; dd <<= 1) {
        a0 += __shfl_xor_sync(0xffffffffu, a0, dd);
        a1 += __shfl_xor_sync(0xffffffffu, a1, dd);
        a2 += __shfl_xor_sync(0xffffffffu, a2, dd);
        a3 += __shfl_xor_sync(0xffffffffu, a3, dd);
    }

    if (lane < 8) {
        float4 sk = *(const float4*)(skip + (size_t)n * CPH + lane * 4);
        float4 o;
        o.x = fmaxf(a0 * 0.25f + sk.x, 0.f);
        o.y = fmaxf(a1 * 0.25f + sk.y, 0.f);
        o.z = fmaxf(a2 * 0.25f + sk.z, 0.f);
        o.w = fmaxf(a3 * 0.25f + sk.w, 0.f);
        if (!do_cls) {
            *(float4*)(out + (size_t)n * CPH + lane * 4) = o;
        } else {
            *(float4*)&s_h[wid][lane * 4] = o;
        }
    }

    if (do_cls) {
        __syncwarp();
        const float* h = s_h[wid];
        int c2 = 32 + (lane & 7);
        float acc1 = s_bc[lane];
        float acc2 = s_bc[c2];
        #pragma unroll 8
        for (int j = 0; j < CPH; j++) {
            float hv = h[j];
            acc1 = fmaf(hv, s_wc[j * OUTC + lane], acc1);
            acc2 = fmaf(hv, s_wc[j * OUTC + c2], acc2);
        }
        out[(size_t)n * OUTC + lane] = acc1;
        if (lane < 8) out[(size_t)n * OUTC + c2] = acc2;
    }
}

// ---------------------------------------------------------------------------
// Host orchestration
// ---------------------------------------------------------------------------
static inline unsigned int ceil_div(unsigned int a, unsigned int b) { return (a + b - 1) / b; }

extern "C" void kernel_launch(void* const* d_in, const int* in_sizes, int n_in,
                              void* d_out, int out_size) {
    const float* x   = (const float*)d_in[0];
    const void*  ei  = d_in[1];
    const float* wq1 = (const float*)d_in[2];
    const float* bq1 = (const float*)d_in[3];
    const float* wk1 = (const float*)d_in[4];
    const float* bk1 = (const float*)d_in[5];
    const float* wv1 = (const float*)d_in[6];
    const float* bv1 = (const float*)d_in[7];
    const float* ws1 = (const float*)d_in[8];
    const float* bs1 = (const float*)d_in[9];
    const float* wq2 = (const float*)d_in[10];
    const float* bq2 = (const float*)d_in[11];
    const float* wk2 = (const float*)d_in[12];
    const float* bk2 = (const float*)d_in[13];
    const float* wv2 = (const float*)d_in[14];
    const float* bv2 = (const float*)d_in[15];
    const float* ws2 = (const float*)d_in[16];
    const float* bs2 = (const float*)d_in[17];
    const float* wc  = (const float*)d_in[18];
    const float* bc  = (const float*)d_in[19];

    const int N = in_sizes[0] / FDIM;   // x is [N,128]
    const int E = in_sizes[1] / 2;      // edge_index is [2,E]

    float  *Qp, *skipp, *h1p;
    __half *KVp;
    cudaGetSymbolAddress((void**)&Qp,    g_Q);
    cudaGetSymbolAddress((void**)&KVp,   g_KV);
    cudaGetSymbolAddress((void**)&skipp, g_skip);
    cudaGetSymbolAddress((void**)&h1p,   g_h1);

    // one-time stream/event creation (resource init only; all WORK below is
    // launched every call — deterministic)
    static cudaStream_t s_pre = nullptr;
    static cudaEvent_t  ev_fork = nullptr, ev_join = nullptr;
    if (s_pre == nullptr) {
        cudaStreamCreate(&s_pre);
        cudaEventCreateWithFlags(&ev_fork, cudaEventDisableTiming);
        cudaEventCreateWithFlags(&ev_join, cudaEventDisableTiming);
    }

    const int NB = (N + SCAN_B - 1) / SCAN_B;

    // fork: CSR build on s_pre, concurrent with layer-1 GEMM on default stream
    cudaEventRecord(ev_fork, 0);
    cudaStreamWaitEvent(s_pre, ev_fork, 0);
    init_pre_kernel<<<ceil_div((unsigned)N, 256u), 256, 0, s_pre>>>(N);
    detect_dtype_kernel<<<592, 256, 0, s_pre>>>((const uint2*)ei, E);
    hist_kernel<<<ceil_div((unsigned)E, 256u), 256, 0, s_pre>>>(ei, E);
    scan_p1_kernel<<<NB, SCAN_B, 0, s_pre>>>(N);
    scan_p2_kernel<<<1, SCAN_B, 0, s_pre>>>(NB);
    scan_p3_kernel<<<NB, SCAN_B, 0, s_pre>>>(N);
    scatter_kernel<<<ceil_div((unsigned)E, 256u), 256, 0, s_pre>>>(ei, E);
    cudaEventRecord(ev_join, s_pre);

    // layer-1 projections (no CSR dependency) overlap with prepro
    hmma_qkvs_kernel<<<ceil_div((unsigned)N, 128u), 256>>>(
        x, wq1, wk1, wv1, ws1, bq1, bk1, bv1, bs1, Qp, KVp, skipp, N, FDIM);

    // join before attention needs the CSR
    cudaStreamWaitEvent(0, ev_join, 0);
    attn_fused_kernel<<<ceil_div((unsigned)N, 8u), 256>>>(
        Qp, KVp, skipp, h1p, wc, bc, 0, N, E);

    // layer 2 (input h1 [N,32]); classifier fused into attention epilogue
    hmma_qkvs_kernel<<<ceil_div((unsigned)N, 128u), 256>>>(
        h1p, wq2, wk2, wv2, ws2, bq2, bk2, bv2, bs2, Qp, KVp, skipp, N, CPH);
    attn_fused_kernel<<<ceil_div((unsigned)N, 8u), 256>>>(
        Qp, KVp, skipp, (float*)d_out, wc, bc, 1, N, E);
}

// round 10
// speedup vs baseline: 4.7145x; 1.1327x over previous
#include <cuda_runtime.h>
#include <cuda_fp16.h>
#include <math_constants.h>
#include <cstdint>

// ---------------------------------------------------------------------------
// GraphTransformerModel: 2x TransformerConv (H=4, C=32, concat=False) + Linear
// N=50000, E=800000, D=128, HID=32, OUT=40
// Round 10: lane-interleaved KV layout (1 LDG.128/edge/lane), x4-unrolled
// attention gather, double-buffered GEMM B staging.
// KV row layout (256 halves): lane l owns halves [l*8, l*8+8):
//   [l*8 .. l*8+3] = K channels l*4..l*4+3,  [l*8+4 .. l*8+7] = V channels.
// ---------------------------------------------------------------------------

#define NMAX 50000
#define EMAX 800000
#define HEADS 4
#define CPH 32
#define FDIM 128
#define OUTC 40
#define SCAN_B 256

// ---- static device scratch ----
__device__ float  g_Q[NMAX * FDIM];
__device__ __half g_KV[(size_t)NMAX * 256];
__device__ float  g_skip[NMAX * CPH];
__device__ float  g_h1[NMAX * CPH];
__device__ int    g_csr_src[EMAX];
__device__ int    g_deg[NMAX];
__device__ int    g_off[NMAX];
__device__ int    g_cur[NMAX];
__device__ int    g_bsum[SCAN_B];
__device__ int    g_boff[SCAN_B];
__device__ int    g_is32;

// ---------------------------------------------------------------------------
// Fused QKV+skip HMMA GEMM, double-buffered B staging.
// ---------------------------------------------------------------------------
#define LDH 24   // B smem row halves (16 data + 8 pad) -> 12 u32

__device__ __forceinline__ void mma16816(float* d, const uint32_t* a,
                                         const uint32_t* b) {
    asm volatile(
        "mma.sync.aligned.m16n8k16.row.col.f32.f16.f16.f32 "
        "{%0,%1,%2,%3}, {%4,%5,%6,%7}, {%8,%9}, {%0,%1,%2,%3};"
        : "+f"(d[0]), "+f"(d[1]), "+f"(d[2]), "+f"(d[3])
        : "r"(a[0]), "r"(a[1]), "r"(a[2]), "r"(a[3]), "r"(b[0]), "r"(b[1]));
}

__global__ __launch_bounds__(256)
void hmma_qkvs_kernel(const float* __restrict__ A,
                      const float* __restrict__ Wq, const float* __restrict__ Wk,
                      const float* __restrict__ Wv, const float* __restrict__ Ws,
                      const float* __restrict__ bq, const float* __restrict__ bk,
                      const float* __restrict__ bv, const float* __restrict__ bs,
                      float* __restrict__ Cq, __half* __restrict__ CKV,
                      float* __restrict__ Cs,
                      int N, int Kdim) {
    __shared__ __half sA[128 * 136];        // Kdim<=128 (+8 pad)
    __shared__ __half sB[2][128 * LDH];

    const int tid  = threadIdx.x;
    const int wid  = tid >> 5;
    const int lane = tid & 31;
    const int wm   = wid >> 2;
    const int wn   = wid & 3;
    const int row0 = blockIdx.x * 128;
    const int lr   = lane >> 2;
    const int lc   = lane & 3;

    const int ldwh  = Kdim + 8;
    const int ldw32 = ldwh >> 1;
    const uint32_t* sA32 = (const uint32_t*)sA;

    // stage FULL A tile once: 128 rows x Kdim, fp32 -> fp16
    {
        const int kd4 = Kdim >> 2;
        for (int idx = tid; idx < 128 * kd4; idx += 256) {
            int r  = idx / kd4;
            int c4 = idx - r * kd4;
            int gr = min(row0 + r, N - 1);
            float4 a = *(const float4*)(A + (size_t)gr * Kdim + c4 * 4);
            __half2* dst = (__half2*)(sA + r * ldwh) + c4 * 2;
            dst[0] = __floats2half2_rn(a.x, a.y);
            dst[1] = __floats2half2_rn(a.z, a.w);
        }
    }

    const int nsteps = Kdim >> 4;

    #pragma unroll 1
    for (int m = 0; m < 4; m++) {
        const float* W;
        const float* bias;
        int Mcols;
        if (m == 0)      { W = Wq; bias = bq; Mcols = 128; }
        else if (m == 1) { W = Wk; bias = bk; Mcols = 128; }
        else if (m == 2) { W = Wv; bias = bv; Mcols = 128; }
        else             { W = Ws; bias = bs; Mcols = 32;  }

        float acc[4][4][4] = {};
        const int nb4   = Mcols * 4;        // float4s per 16-k B slab
        const int mc4   = Mcols >> 2;

        // protect sB[0] from previous matrix's reads, then stage slab 0
        __syncthreads();
        for (int idx = tid; idx < nb4; idx += 256) {
            int kk = idx / mc4;
            int n4 = idx - kk * mc4;
            float4 w = *(const float4*)(W + (size_t)kk * Mcols + n4 * 4);
            __half* d = sB[0];
            d[(n4 * 4 + 0) * LDH + kk] = __float2half_rn(w.x);
            d[(n4 * 4 + 1) * LDH + kk] = __float2half_rn(w.y);
            d[(n4 * 4 + 2) * LDH + kk] = __float2half_rn(w.z);
            d[(n4 * 4 + 3) * LDH + kk] = __float2half_rn(w.w);
        }
        __syncthreads();

        int cur = 0;
        for (int step = 0; step < nsteps; step++) {
            const int kw0 = step << 3;
            // prefetch next slab into registers
            float4 wreg[2];
            int pk[2], pn[2], npre = 0;
            if (step + 1 < nsteps) {
                const int k0n = (step + 1) << 4;
                for (int idx = tid; idx < nb4; idx += 256) {
                    int kk = idx / mc4;
                    int n4 = idx - kk * mc4;
                    wreg[npre] = *(const float4*)(W + (size_t)(k0n + kk) * Mcols + n4 * 4);
                    pk[npre] = kk; pn[npre] = n4;
                    npre++;
                }
            }

            const uint32_t* sBc = (const uint32_t*)sB[cur];
            if (m < 3) {
                uint32_t af[4][4], bf[4][2];
                #pragma unroll
                for (int mt = 0; mt < 4; mt++) {
                    int rm = wm * 64 + mt * 16;
                    #pragma unroll
                    for (int j = 0; j < 4; j++)
                        af[mt][j] = sA32[(rm + lr + (j & 1) * 8) * ldw32 +
                                         kw0 + lc + (j >> 1) * 4];
                }
                #pragma unroll
                for (int nt = 0; nt < 4; nt++) {
                    int cn = wn * 32 + nt * 8;
                    bf[nt][0] = sBc[(cn + lr) * 12 + lc];
                    bf[nt][1] = sBc[(cn + lr) * 12 + lc + 4];
                }
                #pragma unroll
                for (int mt = 0; mt < 4; mt++)
                    #pragma unroll
                    for (int nt = 0; nt < 4; nt++)
                        mma16816(acc[mt][nt], af[mt], bf[nt]);
            } else {
                uint32_t af[4], bf[4][2];
                int rm = wid * 16;
                #pragma unroll
                for (int j = 0; j < 4; j++)
                    af[j] = sA32[(rm + lr + (j & 1) * 8) * ldw32 +
                                 kw0 + lc + (j >> 1) * 4];
                #pragma unroll
                for (int nt = 0; nt < 4; nt++) {
                    int cn = nt * 8;
                    bf[nt][0] = sBc[(cn + lr) * 12 + lc];
                    bf[nt][1] = sBc[(cn + lr) * 12 + lc + 4];
                }
                #pragma unroll
                for (int nt = 0; nt < 4; nt++)
                    mma16816(acc[0][nt], af, bf[nt]);
            }

            if (step + 1 < nsteps) {
                __half* d = sB[cur ^ 1];
                for (int p = 0; p < npre; p++) {
                    d[(pn[p] * 4 + 0) * LDH + pk[p]] = __float2half_rn(wreg[p].x);
                    d[(pn[p] * 4 + 1) * LDH + pk[p]] = __float2half_rn(wreg[p].y);
                    d[(pn[p] * 4 + 2) * LDH + pk[p]] = __float2half_rn(wreg[p].z);
                    d[(pn[p] * 4 + 3) * LDH + pk[p]] = __float2half_rn(wreg[p].w);
                }
                __syncthreads();
                cur ^= 1;
            }
        }

        // ---- epilogue ----
        if (m == 0) {
            #pragma unroll
            for (int mt = 0; mt < 4; mt++) {
                int r0 = row0 + wm * 64 + mt * 16 + lr;
                #pragma unroll
                for (int nt = 0; nt < 4; nt++) {
                    int gc = wn * 32 + nt * 8 + lc * 2;
                    float bx = bias[gc], by = bias[gc + 1];
                    if (r0 < N)
                        *(float2*)(Cq + (size_t)r0 * 128 + gc) =
                            make_float2(acc[mt][nt][0] + bx, acc[mt][nt][1] + by);
                    if (r0 + 8 < N)
                        *(float2*)(Cq + (size_t)(r0 + 8) * 128 + gc) =
                            make_float2(acc[mt][nt][2] + bx, acc[mt][nt][3] + by);
                }
            }
        } else if (m < 3) {
            // interleaved KV layout: channel c -> (c>>2)*8 + (c&3) (+4 for V)
            const int voff = (m == 2) ? 4 : 0;
            #pragma unroll
            for (int mt = 0; mt < 4; mt++) {
                int r0 = row0 + wm * 64 + mt * 16 + lr;
                #pragma unroll
                for (int nt = 0; nt < 4; nt++) {
                    int gc = wn * 32 + nt * 8 + lc * 2;
                    int ioff = ((gc >> 2) << 3) + (gc & 3) + voff;
                    float bx = bias[gc], by = bias[gc + 1];
                    if (r0 < N)
                        *(__half2*)(CKV + (size_t)r0 * 256 + ioff) =
                            __floats2half2_rn(acc[mt][nt][0] + bx, acc[mt][nt][1] + by);
                    if (r0 + 8 < N)
                        *(__half2*)(CKV + (size_t)(r0 + 8) * 256 + ioff) =
                            __floats2half2_rn(acc[mt][nt][2] + bx, acc[mt][nt][3] + by);
                }
            }
        } else {
            int r0 = row0 + wid * 16 + lr;
            #pragma unroll
            for (int nt = 0; nt < 4; nt++) {
                int gc = nt * 8 + lc * 2;
                float bx = bias[gc], by = bias[gc + 1];
                if (r0 < N)
                    *(float2*)(Cs + (size_t)r0 * 32 + gc) =
                        make_float2(acc[0][nt][0] + bx, acc[0][nt][1] + by);
                if (r0 + 8 < N)
                    *(float2*)(Cs + (size_t)(r0 + 8) * 32 + gc) =
                        make_float2(acc[0][nt][2] + bx, acc[0][nt][3] + by);
            }
        }
    }
}

// ---------------------------------------------------------------------------
// Preprocessing (unchanged)
// ---------------------------------------------------------------------------
__global__ void init_pre_kernel(int N) {
    int i = blockIdx.x * blockDim.x + threadIdx.x;
    if (i == 0) g_is32 = 0;
    if (i < N) g_deg[i] = 0;
}

__global__ void detect_dtype_kernel(const uint2* __restrict__ w, int npairs) {
    int i = blockIdx.x * blockDim.x + threadIdx.x;
    int stride = gridDim.x * blockDim.x;
    for (; i < npairs; i += stride)
        if (w[i].y != 0u) { g_is32 = 1; break; }
}

__global__ void hist_kernel(const void* __restrict__ ei, int E) {
    int e = blockIdx.x * blockDim.x + threadIdx.x;
    if (e >= E) return;
    int d;
    if (g_is32) d = ((const int*)ei)[E + e];
    else        d = (int)((const long long*)ei)[E + e];
    atomicAdd(&g_deg[d], 1);
}

__global__ __launch_bounds__(SCAN_B)
void scan_p1_kernel(int N) {
    __shared__ int sh[SCAN_B];
    int t = threadIdx.x;
    int i = blockIdx.x * SCAN_B + t;
    int v = (i < N) ? g_deg[i] : 0;
    sh[t] = v;
    __syncthreads();
    #pragma unroll
    for (int s = SCAN_B / 2; s > 0; s >>= 1) {
        if (t < s) sh[t] += sh[t + s];
        __syncthreads();
    }
    if (t == 0) g_bsum[blockIdx.x] = sh[0];
}

__global__ __launch_bounds__(SCAN_B)
void scan_p2_kernel(int NB) {
    __shared__ int sh[SCAN_B];
    int t = threadIdx.x;
    int v = (t < NB) ? g_bsum[t] : 0;
    sh[t] = v;
    __syncthreads();
    #pragma unroll
    for (int d = 1; d < SCAN_B; d <<= 1) {
        int u = (t >= d) ? sh[t - d] : 0;
        __syncthreads();
        sh[t] += u;
        __syncthreads();
    }
    if (t < NB) g_boff[t] = sh[t] - v;
}

__global__ __launch_bounds__(SCAN_B)
void scan_p3_kernel(int N) {
    __shared__ int sh[SCAN_B];
    int t = threadIdx.x;
    int i = blockIdx.x * SCAN_B + t;
    int v = (i < N) ? g_deg[i] : 0;
    sh[t] = v;
    __syncthreads();
    #pragma unroll
    for (int d = 1; d < SCAN_B; d <<= 1) {
        int u = (t >= d) ? sh[t - d] : 0;
        __syncthreads();
        sh[t] += u;
        __syncthreads();
    }
    if (i < N) {
        int excl = sh[t] - v + g_boff[blockIdx.x];
        g_off[i] = excl;
        g_cur[i] = excl;
    }
}

__global__ void scatter_kernel(const void* __restrict__ ei, int E) {
    int e = blockIdx.x * blockDim.x + threadIdx.x;
    if (e >= E) return;
    int s, d;
    if (g_is32) {
        const int* p = (const int*)ei;
        s = p[e];
        d = p[E + e];
    } else {
        const long long* p = (const long long*)ei;
        s = (int)p[e];
        d = (int)p[E + e];
    }
    int pidx = atomicAdd(&g_cur[d], 1);
    g_csr_src[pidx] = s;
}

// ---------------------------------------------------------------------------
// Single-pass fused attention, interleaved fp16 KV: ONE uint4 load per edge
// per lane. Edge loop unrolled x4 (4 gathers in flight).
// Lane l: head l/8, channels 4*(l%8)..+3 (K at halves l*8..+3, V at +4..+7).
// do_cls=1: classifier fused into epilogue.
// ---------------------------------------------------------------------------
__device__ __forceinline__ float4 unpack_lo(const uint4& r) {
    float2 a = __half22float2(*(const __half2*)&r.x);
    float2 b = __half22float2(*(const __half2*)&r.y);
    return make_float4(a.x, a.y, b.x, b.y);
}
__device__ __forceinline__ float4 unpack_hi(const uint4& r) {
    float2 a = __half22float2(*(const __half2*)&r.z);
    float2 b = __half22float2(*(const __half2*)&r.w);
    return make_float4(a.x, a.y, b.x, b.y);
}

__global__ __launch_bounds__(256)
void attn_fused_kernel(const float* __restrict__ Q, const __half* __restrict__ KV,
                       const float* __restrict__ skip,
                       float* __restrict__ out,
                       const float* __restrict__ wc, const float* __restrict__ bc,
                       int do_cls, int N, int E) {
    __shared__ float s_wc[CPH * OUTC];
    __shared__ float s_bc[OUTC];
    __shared__ float s_h[8][CPH];

    const int tid  = threadIdx.x;
    const int wid  = tid >> 5;
    const int lane = tid & 31;

    if (do_cls) {
        for (int i = tid; i < CPH * OUTC; i += 256) s_wc[i] = wc[i];
        if (tid < OUTC) s_bc[tid] = bc[tid];
        __syncthreads();
    }

    int n = (blockIdx.x * blockDim.x + tid) >> 5;
    if (n >= N) return;
    const int beg = g_off[n];
    const int end = (n + 1 < N) ? g_off[n + 1] : E;

    const float4 q = *(const float4*)(Q + (size_t)n * FDIM + lane * 4);

    float den = 0.f;
    float a0 = 0.f, a1 = 0.f, a2 = 0.f, a3 = 0.f;
    const float scale = 0.17677669529663687f;  // 1/sqrt(32)

    for (int base = beg; base < end; base += 32) {
        int myidx = (base + lane < end) ? g_csr_src[base + lane] : 0;
        int rem = end - base;
        int cnt = rem < 32 ? rem : 32;
        int j = 0;
        for (; j + 3 < cnt; j += 4) {
            int s0 = __shfl_sync(0xffffffffu, myidx, j);
            int s1 = __shfl_sync(0xffffffffu, myidx, j + 1);
            int s2 = __shfl_sync(0xffffffffu, myidx, j + 2);
            int s3 = __shfl_sync(0xffffffffu, myidx, j + 3);
            uint4 r0 = *(const uint4*)(KV + (size_t)s0 * 256 + lane * 8);
            uint4 r1 = *(const uint4*)(KV + (size_t)s1 * 256 + lane * 8);
            uint4 r2 = *(const uint4*)(KV + (size_t)s2 * 256 + lane * 8);
            uint4 r3 = *(const uint4*)(KV + (size_t)s3 * 256 + lane * 8);
            float4 k0 = unpack_lo(r0), k1 = unpack_lo(r1);
            float4 k2 = unpack_lo(r2), k3 = unpack_lo(r3);
            float d0 = q.x * k0.x + q.y * k0.y + q.z * k0.z + q.w * k0.w;
            float d1 = q.x * k1.x + q.y * k1.y + q.z * k1.z + q.w * k1.w;
            float d2 = q.x * k2.x + q.y * k2.y + q.z * k2.z + q.w * k2.w;
            float d3 = q.x * k3.x + q.y * k3.y + q.z * k3.z + q.w * k3.w;
            d0 += __shfl_xor_sync(0xffffffffu, d0, 4);
            d1 += __shfl_xor_sync(0xffffffffu, d1, 4);
            d2 += __shfl_xor_sync(0xffffffffu, d2, 4);
            d3 += __shfl_xor_sync(0xffffffffu, d3, 4);
            d0 += __shfl_xor_sync(0xffffffffu, d0, 2);
            d1 += __shfl_xor_sync(0xffffffffu, d1, 2);
            d2 += __shfl_xor_sync(0xffffffffu, d2, 2);
            d3 += __shfl_xor_sync(0xffffffffu, d3, 2);
            d0 += __shfl_xor_sync(0xffffffffu, d0, 1);
            d1 += __shfl_xor_sync(0xffffffffu, d1, 1);
            d2 += __shfl_xor_sync(0xffffffffu, d2, 1);
            d3 += __shfl_xor_sync(0xffffffffu, d3, 1);
            float w0 = __expf(d0 * scale);
            float w1 = __expf(d1 * scale);
            float w2 = __expf(d2 * scale);
            float w3 = __expf(d3 * scale);
            den += (w0 + w1) + (w2 + w3);
            float4 v0 = unpack_hi(r0), v1 = unpack_hi(r1);
            float4 v2 = unpack_hi(r2), v3 = unpack_hi(r3);
            a0 = fmaf(w0, v0.x, fmaf(w1, v1.x, fmaf(w2, v2.x, fmaf(w3, v3.x, a0))));
            a1 = fmaf(w0, v0.y, fmaf(w1, v1.y, fmaf(w2, v2.y, fmaf(w3, v3.y, a1))));
            a2 = fmaf(w0, v0.z, fmaf(w1, v1.z, fmaf(w2, v2.z, fmaf(w3, v3.z, a2))));
            a3 = fmaf(w0, v0.w, fmaf(w1, v1.w, fmaf(w2, v2.w, fmaf(w3, v3.w, a3))));
        }
        for (; j < cnt; j++) {
            int s0 = __shfl_sync(0xffffffffu, myidx, j);
            uint4 r0 = *(const uint4*)(KV + (size_t)s0 * 256 + lane * 8);
            float4 k0 = unpack_lo(r0);
            float4 v0 = unpack_hi(r0);
            float d0 = q.x * k0.x + q.y * k0.y + q.z * k0.z + q.w * k0.w;
            d0 += __shfl_xor_sync(0xffffffffu, d0, 4);
            d0 += __shfl_xor_sync(0xffffffffu, d0, 2);
            d0 += __shfl_xor_sync(0xffffffffu, d0, 1);
            float w0 = __expf(d0 * scale);
            den += w0;
            a0 = fmaf(w0, v0.x, a0);
            a1 = fmaf(w0, v0.y, a1);
            a2 = fmaf(w0, v0.z, a2);
            a3 = fmaf(w0, v0.w, a3);
        }
    }

    const float rden = 1.f / (den + 1e-16f);
    a0 *= rden; a1 *= rden; a2 *= rden; a3 *= rden;

    // head mean: sum over 4 heads (lanes l, l^8, l^16, l^24 share channels)
    #pragma unroll
    for (int dd = 8; dd <= 16; dd <<= 1) {
        a0 += __shfl_xor_sync(0xffffffffu, a0, dd);
        a1 += __shfl_xor_sync(0xffffffffu, a1, dd);
        a2 += __shfl_xor_sync(0xffffffffu, a2, dd);
        a3 += __shfl_xor_sync(0xffffffffu, a3, dd);
    }

    if (lane < 8) {
        float4 sk = *(const float4*)(skip + (size_t)n * CPH + lane * 4);
        float4 o;
        o.x = fmaxf(a0 * 0.25f + sk.x, 0.f);
        o.y = fmaxf(a1 * 0.25f + sk.y, 0.f);
        o.z = fmaxf(a2 * 0.25f + sk.z, 0.f);
        o.w = fmaxf(a3 * 0.25f + sk.w, 0.f);
        if (!do_cls) {
            *(float4*)(out + (size_t)n * CPH + lane * 4) = o;
        } else {
            *(float4*)&s_h[wid][lane * 4] = o;
        }
    }

    if (do_cls) {
        __syncwarp();
        const float* h = s_h[wid];
        int c2 = 32 + (lane & 7);
        float acc1 = s_bc[lane];
        float acc2 = s_bc[c2];
        #pragma unroll 8
        for (int j = 0; j < CPH; j++) {
            float hv = h[j];
            acc1 = fmaf(hv, s_wc[j * OUTC + lane], acc1);
            acc2 = fmaf(hv, s_wc[j * OUTC + c2], acc2);
        }
        out[(size_t)n * OUTC + lane] = acc1;
        if (lane < 8) out[(size_t)n * OUTC + c2] = acc2;
    }
}

// ---------------------------------------------------------------------------
// Host orchestration
// ---------------------------------------------------------------------------
static inline unsigned int ceil_div(unsigned int a, unsigned int b) { return (a + b - 1) / b; }

extern "C" void kernel_launch(void* const* d_in, const int* in_sizes, int n_in,
                              void* d_out, int out_size) {
    const float* x   = (const float*)d_in[0];
    const void*  ei  = d_in[1];
    const float* wq1 = (const float*)d_in[2];
    const float* bq1 = (const float*)d_in[3];
    const float* wk1 = (const float*)d_in[4];
    const float* bk1 = (const float*)d_in[5];
    const float* wv1 = (const float*)d_in[6];
    const float* bv1 = (const float*)d_in[7];
    const float* ws1 = (const float*)d_in[8];
    const float* bs1 = (const float*)d_in[9];
    const float* wq2 = (const float*)d_in[10];
    const float* bq2 = (const float*)d_in[11];
    const float* wk2 = (const float*)d_in[12];
    const float* bk2 = (const float*)d_in[13];
    const float* wv2 = (const float*)d_in[14];
    const float* bv2 = (const float*)d_in[15];
    const float* ws2 = (const float*)d_in[16];
    const float* bs2 = (const float*)d_in[17];
    const float* wc  = (const float*)d_in[18];
    const float* bc  = (const float*)d_in[19];

    const int N = in_sizes[0] / FDIM;   // x is [N,128]
    const int E = in_sizes[1] / 2;      // edge_index is [2,E]

    float  *Qp, *skipp, *h1p;
    __half *KVp;
    cudaGetSymbolAddress((void**)&Qp,    g_Q);
    cudaGetSymbolAddress((void**)&KVp,   g_KV);
    cudaGetSymbolAddress((void**)&skipp, g_skip);
    cudaGetSymbolAddress((void**)&h1p,   g_h1);

    // one-time stream/event creation (resource init only)
    static cudaStream_t s_pre = nullptr;
    static cudaEvent_t  ev_fork = nullptr, ev_join = nullptr;
    if (s_pre == nullptr) {
        cudaStreamCreate(&s_pre);
        cudaEventCreateWithFlags(&ev_fork, cudaEventDisableTiming);
        cudaEventCreateWithFlags(&ev_join, cudaEventDisableTiming);
    }

    const int NB = (N + SCAN_B - 1) / SCAN_B;

    // fork: CSR build on s_pre, concurrent with layer-1 GEMM on default stream
    cudaEventRecord(ev_fork, 0);
    cudaStreamWaitEvent(s_pre, ev_fork, 0);
    init_pre_kernel<<<ceil_div((unsigned)N, 256u), 256, 0, s_pre>>>(N);
    detect_dtype_kernel<<<592, 256, 0, s_pre>>>((const uint2*)ei, E);
    hist_kernel<<<ceil_div((unsigned)E, 256u), 256, 0, s_pre>>>(ei, E);
    scan_p1_kernel<<<NB, SCAN_B, 0, s_pre>>>(N);
    scan_p2_kernel<<<1, SCAN_B, 0, s_pre>>>(NB);
    scan_p3_kernel<<<NB, SCAN_B, 0, s_pre>>>(N);
    scatter_kernel<<<ceil_div((unsigned)E, 256u), 256, 0, s_pre>>>(ei, E);
    cudaEventRecord(ev_join, s_pre);

    // layer-1 projections (no CSR dependency) overlap with prepro
    hmma_qkvs_kernel<<<ceil_div((unsigned)N, 128u), 256>>>(
        x, wq1, wk1, wv1, ws1, bq1, bk1, bv1, bs1, Qp, KVp, skipp, N, FDIM);

    // join before attention needs the CSR
    cudaStreamWaitEvent(0, ev_join, 0);
    attn_fused_kernel<<<ceil_div((unsigned)N, 8u), 256>>>(
        Qp, KVp, skipp, h1p, wc, bc, 0, N, E);

    // layer 2 (input h1 [N,32]); classifier fused into attention epilogue
    hmma_qkvs_kernel<<<ceil_div((unsigned)N, 128u), 256>>>(
        h1p, wq2, wk2, wv2, ws2, bq2, bk2, bv2, bs2, Qp, KVp, skipp, N, CPH);
    attn_fused_kernel<<<ceil_div((unsigned)N, 8u), 256>>>(
        Qp, KVp, skipp, (float*)d_out, wc, bc, 1, N, E);
}

// round 11
// speedup vs baseline: 4.7368x; 1.0047x over previous
#include <cuda_runtime.h>
#include <cuda_fp16.h>
#include <math_constants.h>
#include <cstdint>

// ---------------------------------------------------------------------------
// GraphTransformerModel: 2x TransformerConv (H=4, C=32, concat=False) + Linear
// N=50000, E=800000, D=128, HID=32, OUT=40
// Round 11: fp16 Q, chunked attn1/gemm2 overlap, sampled dtype detect.
// KV row layout (256 halves): lane l owns halves [l*8, l*8+8):
//   [l*8 .. l*8+3] = K channels l*4..l*4+3,  [l*8+4 .. l*8+7] = V channels.
// ---------------------------------------------------------------------------

#define NMAX 50000
#define EMAX 800000
#define HEADS 4
#define CPH 32
#define FDIM 128
#define OUTC 40
#define SCAN_B 256

// ---- static device scratch ----
__device__ __half g_Q[NMAX * FDIM];
__device__ __half g_KV[(size_t)NMAX * 256];
__device__ float  g_skip[NMAX * CPH];
__device__ float  g_h1[NMAX * CPH];
__device__ int    g_csr_src[EMAX];
__device__ int    g_deg[NMAX];
__device__ int    g_off[NMAX];
__device__ int    g_cur[NMAX];
__device__ int    g_bsum[SCAN_B];
__device__ int    g_boff[SCAN_B];
__device__ int    g_is32;

// ---------------------------------------------------------------------------
// Fused QKV+skip HMMA GEMM, double-buffered B staging. rowbase for chunking.
// ---------------------------------------------------------------------------
#define LDH 24   // B smem row halves (16 data + 8 pad) -> 12 u32

__device__ __forceinline__ void mma16816(float* d, const uint32_t* a,
                                         const uint32_t* b) {
    asm volatile(
        "mma.sync.aligned.m16n8k16.row.col.f32.f16.f16.f32 "
        "{%0,%1,%2,%3}, {%4,%5,%6,%7}, {%8,%9}, {%0,%1,%2,%3};"
        : "+f"(d[0]), "+f"(d[1]), "+f"(d[2]), "+f"(d[3])
        : "r"(a[0]), "r"(a[1]), "r"(a[2]), "r"(a[3]), "r"(b[0]), "r"(b[1]));
}

__global__ __launch_bounds__(256)
void hmma_qkvs_kernel(const float* __restrict__ A,
                      const float* __restrict__ Wq, const float* __restrict__ Wk,
                      const float* __restrict__ Wv, const float* __restrict__ Ws,
                      const float* __restrict__ bq, const float* __restrict__ bk,
                      const float* __restrict__ bv, const float* __restrict__ bs,
                      __half* __restrict__ Cq, __half* __restrict__ CKV,
                      float* __restrict__ Cs,
                      int rowbase, int N, int Kdim) {
    __shared__ __half sA[128 * 136];        // Kdim<=128 (+8 pad)
    __shared__ __half sB[2][128 * LDH];

    const int tid  = threadIdx.x;
    const int wid  = tid >> 5;
    const int lane = tid & 31;
    const int wm   = wid >> 2;
    const int wn   = wid & 3;
    const int row0 = rowbase + blockIdx.x * 128;
    const int lr   = lane >> 2;
    const int lc   = lane & 3;

    const int ldwh  = Kdim + 8;
    const int ldw32 = ldwh >> 1;
    const uint32_t* sA32 = (const uint32_t*)sA;

    // stage FULL A tile once: 128 rows x Kdim, fp32 -> fp16
    {
        const int kd4 = Kdim >> 2;
        for (int idx = tid; idx < 128 * kd4; idx += 256) {
            int r  = idx / kd4;
            int c4 = idx - r * kd4;
            int gr = min(row0 + r, N - 1);
            float4 a = *(const float4*)(A + (size_t)gr * Kdim + c4 * 4);
            __half2* dst = (__half2*)(sA + r * ldwh) + c4 * 2;
            dst[0] = __floats2half2_rn(a.x, a.y);
            dst[1] = __floats2half2_rn(a.z, a.w);
        }
    }

    const int nsteps = Kdim >> 4;

    #pragma unroll 1
    for (int m = 0; m < 4; m++) {
        const float* W;
        const float* bias;
        int Mcols;
        if (m == 0)      { W = Wq; bias = bq; Mcols = 128; }
        else if (m == 1) { W = Wk; bias = bk; Mcols = 128; }
        else if (m == 2) { W = Wv; bias = bv; Mcols = 128; }
        else             { W = Ws; bias = bs; Mcols = 32;  }

        float acc[4][4][4] = {};
        const int nb4   = Mcols * 4;
        const int mc4   = Mcols >> 2;

        __syncthreads();
        for (int idx = tid; idx < nb4; idx += 256) {
            int kk = idx / mc4;
            int n4 = idx - kk * mc4;
            float4 w = *(const float4*)(W + (size_t)kk * Mcols + n4 * 4);
            __half* d = sB[0];
            d[(n4 * 4 + 0) * LDH + kk] = __float2half_rn(w.x);
            d[(n4 * 4 + 1) * LDH + kk] = __float2half_rn(w.y);
            d[(n4 * 4 + 2) * LDH + kk] = __float2half_rn(w.z);
            d[(n4 * 4 + 3) * LDH + kk] = __float2half_rn(w.w);
        }
        __syncthreads();

        int cur = 0;
        for (int step = 0; step < nsteps; step++) {
            const int kw0 = step << 3;
            float4 wreg[2];
            int pk[2], pn[2], npre = 0;
            if (step + 1 < nsteps) {
                const int k0n = (step + 1) << 4;
                for (int idx = tid; idx < nb4; idx += 256) {
                    int kk = idx / mc4;
                    int n4 = idx - kk * mc4;
                    wreg[npre] = *(const float4*)(W + (size_t)(k0n + kk) * Mcols + n4 * 4);
                    pk[npre] = kk; pn[npre] = n4;
                    npre++;
                }
            }

            const uint32_t* sBc = (const uint32_t*)sB[cur];
            if (m < 3) {
                uint32_t af[4][4], bf[4][2];
                #pragma unroll
                for (int mt = 0; mt < 4; mt++) {
                    int rm = wm * 64 + mt * 16;
                    #pragma unroll
                    for (int j = 0; j < 4; j++)
                        af[mt][j] = sA32[(rm + lr + (j & 1) * 8) * ldw32 +
                                         kw0 + lc + (j >> 1) * 4];
                }
                #pragma unroll
                for (int nt = 0; nt < 4; nt++) {
                    int cn = wn * 32 + nt * 8;
                    bf[nt][0] = sBc[(cn + lr) * 12 + lc];
                    bf[nt][1] = sBc[(cn + lr) * 12 + lc + 4];
                }
                #pragma unroll
                for (int mt = 0; mt < 4; mt++)
                    #pragma unroll
                    for (int nt = 0; nt < 4; nt++)
                        mma16816(acc[mt][nt], af[mt], bf[nt]);
            } else {
                uint32_t af[4], bf[4][2];
                int rm = wid * 16;
                #pragma unroll
                for (int j = 0; j < 4; j++)
                    af[j] = sA32[(rm + lr + (j & 1) * 8) * ldw32 +
                                 kw0 + lc + (j >> 1) * 4];
                #pragma unroll
                for (int nt = 0; nt < 4; nt++) {
                    int cn = nt * 8;
                    bf[nt][0] = sBc[(cn + lr) * 12 + lc];
                    bf[nt][1] = sBc[(cn + lr) * 12 + lc + 4];
                }
                #pragma unroll
                for (int nt = 0; nt < 4; nt++)
                    mma16816(acc[0][nt], af, bf[nt]);
            }

            if (step + 1 < nsteps) {
                __half* d = sB[cur ^ 1];
                for (int p = 0; p < npre; p++) {
                    d[(pn[p] * 4 + 0) * LDH + pk[p]] = __float2half_rn(wreg[p].x);
                    d[(pn[p] * 4 + 1) * LDH + pk[p]] = __float2half_rn(wreg[p].y);
                    d[(pn[p] * 4 + 2) * LDH + pk[p]] = __float2half_rn(wreg[p].z);
                    d[(pn[p] * 4 + 3) * LDH + pk[p]] = __float2half_rn(wreg[p].w);
                }
                __syncthreads();
                cur ^= 1;
            }
        }

        // ---- epilogue ----
        if (m == 0) {
            #pragma unroll
            for (int mt = 0; mt < 4; mt++) {
                int r0 = row0 + wm * 64 + mt * 16 + lr;
                #pragma unroll
                for (int nt = 0; nt < 4; nt++) {
                    int gc = wn * 32 + nt * 8 + lc * 2;
                    float bx = bias[gc], by = bias[gc + 1];
                    if (r0 < N)
                        *(__half2*)(Cq + (size_t)r0 * 128 + gc) =
                            __floats2half2_rn(acc[mt][nt][0] + bx, acc[mt][nt][1] + by);
                    if (r0 + 8 < N)
                        *(__half2*)(Cq + (size_t)(r0 + 8) * 128 + gc) =
                            __floats2half2_rn(acc[mt][nt][2] + bx, acc[mt][nt][3] + by);
                }
            }
        } else if (m < 3) {
            // interleaved KV layout: channel c -> (c>>2)*8 + (c&3) (+4 for V)
            const int voff = (m == 2) ? 4 : 0;
            #pragma unroll
            for (int mt = 0; mt < 4; mt++) {
                int r0 = row0 + wm * 64 + mt * 16 + lr;
                #pragma unroll
                for (int nt = 0; nt < 4; nt++) {
                    int gc = wn * 32 + nt * 8 + lc * 2;
                    int ioff = ((gc >> 2) << 3) + (gc & 3) + voff;
                    float bx = bias[gc], by = bias[gc + 1];
                    if (r0 < N)
                        *(__half2*)(CKV + (size_t)r0 * 256 + ioff) =
                            __floats2half2_rn(acc[mt][nt][0] + bx, acc[mt][nt][1] + by);
                    if (r0 + 8 < N)
                        *(__half2*)(CKV + (size_t)(r0 + 8) * 256 + ioff) =
                            __floats2half2_rn(acc[mt][nt][2] + bx, acc[mt][nt][3] + by);
                }
            }
        } else {
            int r0 = row0 + wid * 16 + lr;
            #pragma unroll
            for (int nt = 0; nt < 4; nt++) {
                int gc = nt * 8 + lc * 2;
                float bx = bias[gc], by = bias[gc + 1];
                if (r0 < N)
                    *(float2*)(Cs + (size_t)r0 * 32 + gc) =
                        make_float2(acc[0][nt][0] + bx, acc[0][nt][1] + by);
                if (r0 + 8 < N)
                    *(float2*)(Cs + (size_t)(r0 + 8) * 32 + gc) =
                        make_float2(acc[0][nt][2] + bx, acc[0][nt][3] + by);
            }
        }
    }
}

// ---------------------------------------------------------------------------
// Preprocessing
// ---------------------------------------------------------------------------
__global__ void init_pre_kernel(int N) {
    int i = blockIdx.x * blockDim.x + threadIdx.x;
    if (i == 0) g_is32 = 0;
    if (i < N) g_deg[i] = 0;
}

// sampled detect: int64 little-endian hi-words are 0 (ids < 50000); with int32
// data the odd words are random node ids — 64Ki of them all zero is impossible.
__global__ void detect_dtype_kernel(const uint2* __restrict__ w, int npairs) {
    int i = blockIdx.x * blockDim.x + threadIdx.x;
    if (i < npairs && w[i].y != 0u) g_is32 = 1;
}

__global__ void hist_kernel(const void* __restrict__ ei, int E) {
    int e = blockIdx.x * blockDim.x + threadIdx.x;
    if (e >= E) return;
    int d;
    if (g_is32) d = ((const int*)ei)[E + e];
    else        d = (int)((const long long*)ei)[E + e];
    atomicAdd(&g_deg[d], 1);
}

__global__ __launch_bounds__(SCAN_B)
void scan_p1_kernel(int N) {
    __shared__ int sh[SCAN_B];
    int t = threadIdx.x;
    int i = blockIdx.x * SCAN_B + t;
    int v = (i < N) ? g_deg[i] : 0;
    sh[t] = v;
    __syncthreads();
    #pragma unroll
    for (int s = SCAN_B / 2; s > 0; s >>= 1) {
        if (t < s) sh[t] += sh[t + s];
        __syncthreads();
    }
    if (t == 0) g_bsum[blockIdx.x] = sh[0];
}

__global__ __launch_bounds__(SCAN_B)
void scan_p2_kernel(int NB) {
    __shared__ int sh[SCAN_B];
    int t = threadIdx.x;
    int v = (t < NB) ? g_bsum[t] : 0;
    sh[t] = v;
    __syncthreads();
    #pragma unroll
    for (int d = 1; d < SCAN_B; d <<= 1) {
        int u = (t >= d) ? sh[t - d] : 0;
        __syncthreads();
        sh[t] += u;
        __syncthreads();
    }
    if (t < NB) g_boff[t] = sh[t] - v;
}

__global__ __launch_bounds__(SCAN_B)
void scan_p3_kernel(int N) {
    __shared__ int sh[SCAN_B];
    int t = threadIdx.x;
    int i = blockIdx.x * SCAN_B + t;
    int v = (i < N) ? g_deg[i] : 0;
    sh[t] = v;
    __syncthreads();
    #pragma unroll
    for (int d = 1; d < SCAN_B; d <<= 1) {
        int u = (t >= d) ? sh[t - d] : 0;
        __syncthreads();
        sh[t] += u;
        __syncthreads();
    }
    if (i < N) {
        int excl = sh[t] - v + g_boff[blockIdx.x];
        g_off[i] = excl;
        g_cur[i] = excl;
    }
}

__global__ void scatter_kernel(const void* __restrict__ ei, int E) {
    int e = blockIdx.x * blockDim.x + threadIdx.x;
    if (e >= E) return;
    int s, d;
    if (g_is32) {
        const int* p = (const int*)ei;
        s = p[e];
        d = p[E + e];
    } else {
        const long long* p = (const long long*)ei;
        s = (int)p[e];
        d = (int)p[E + e];
    }
    int pidx = atomicAdd(&g_cur[d], 1);
    g_csr_src[pidx] = s;
}

// ---------------------------------------------------------------------------
// Single-pass fused attention, fp16 Q + interleaved fp16 KV (1 LDG.128/edge).
// Node range [nbase, nend). do_cls=1: classifier fused into epilogue.
// ---------------------------------------------------------------------------
__device__ __forceinline__ float4 unpack_lo(const uint4& r) {
    float2 a = __half22float2(*(const __half2*)&r.x);
    float2 b = __half22float2(*(const __half2*)&r.y);
    return make_float4(a.x, a.y, b.x, b.y);
}
__device__ __forceinline__ float4 unpack_hi(const uint4& r) {
    float2 a = __half22float2(*(const __half2*)&r.z);
    float2 b = __half22float2(*(const __half2*)&r.w);
    return make_float4(a.x, a.y, b.x, b.y);
}

__global__ __launch_bounds__(256)
void attn_fused_kernel(const __half* __restrict__ Q, const __half* __restrict__ KV,
                       const float* __restrict__ skip,
                       float* __restrict__ out,
                       const float* __restrict__ wc, const float* __restrict__ bc,
                       int do_cls, int nbase, int nend, int N, int E) {
    __shared__ float s_wc[CPH * OUTC];
    __shared__ float s_bc[OUTC];
    __shared__ float s_h[8][CPH];

    const int tid  = threadIdx.x;
    const int wid  = tid >> 5;
    const int lane = tid & 31;

    if (do_cls) {
        for (int i = tid; i < CPH * OUTC; i += 256) s_wc[i] = wc[i];
        if (tid < OUTC) s_bc[tid] = bc[tid];
        __syncthreads();
    }

    int n = nbase + ((blockIdx.x * blockDim.x + tid) >> 5);
    if (n >= nend) return;
    const int beg = g_off[n];
    const int end = (n + 1 < N) ? g_off[n + 1] : E;

    // fp16 Q: 4 halves per lane
    float4 q;
    {
        uint2 u = *(const uint2*)(Q + (size_t)n * FDIM + lane * 4);
        float2 f0 = __half22float2(*(const __half2*)&u.x);
        float2 f1 = __half22float2(*(const __half2*)&u.y);
        q = make_float4(f0.x, f0.y, f1.x, f1.y);
    }

    float den = 0.f;
    float a0 = 0.f, a1 = 0.f, a2 = 0.f, a3 = 0.f;
    const float scale = 0.17677669529663687f;  // 1/sqrt(32)

    for (int base = beg; base < end; base += 32) {
        int myidx = (base + lane < end) ? g_csr_src[base + lane] : 0;
        int rem = end - base;
        int cnt = rem < 32 ? rem : 32;
        int j = 0;
        for (; j + 3 < cnt; j += 4) {
            int s0 = __shfl_sync(0xffffffffu, myidx, j);
            int s1 = __shfl_sync(0xffffffffu, myidx, j + 1);
            int s2 = __shfl_sync(0xffffffffu, myidx, j + 2);
            int s3 = __shfl_sync(0xffffffffu, myidx, j + 3);
            uint4 r0 = *(const uint4*)(KV + (size_t)s0 * 256 + lane * 8);
            uint4 r1 = *(const uint4*)(KV + (size_t)s1 * 256 + lane * 8);
            uint4 r2 = *(const uint4*)(KV + (size_t)s2 * 256 + lane * 8);
            uint4 r3 = *(const uint4*)(KV + (size_t)s3 * 256 + lane * 8);
            float4 k0 = unpack_lo(r0), k1 = unpack_lo(r1);
            float4 k2 = unpack_lo(r2), k3 = unpack_lo(r3);
            float d0 = q.x * k0.x + q.y * k0.y + q.z * k0.z + q.w * k0.w;
            float d1 = q.x * k1.x + q.y * k1.y + q.z * k1.z + q.w * k1.w;
            float d2 = q.x * k2.x + q.y * k2.y + q.z * k2.z + q.w * k2.w;
            float d3 = q.x * k3.x + q.y * k3.y + q.z * k3.z + q.w * k3.w;
            d0 += __shfl_xor_sync(0xffffffffu, d0, 4);
            d1 += __shfl_xor_sync(0xffffffffu, d1, 4);
            d2 += __shfl_xor_sync(0xffffffffu, d2, 4);
            d3 += __shfl_xor_sync(0xffffffffu, d3, 4);
            d0 += __shfl_xor_sync(0xffffffffu, d0, 2);
            d1 += __shfl_xor_sync(0xffffffffu, d1, 2);
            d2 += __shfl_xor_sync(0xffffffffu, d2, 2);
            d3 += __shfl_xor_sync(0xffffffffu, d3, 2);
            d0 += __shfl_xor_sync(0xffffffffu, d0, 1);
            d1 += __shfl_xor_sync(0xffffffffu, d1, 1);
            d2 += __shfl_xor_sync(0xffffffffu, d2, 1);
            d3 += __shfl_xor_sync(0xffffffffu, d3, 1);
            float w0 = __expf(d0 * scale);
            float w1 = __expf(d1 * scale);
            float w2 = __expf(d2 * scale);
            float w3 = __expf(d3 * scale);
            den += (w0 + w1) + (w2 + w3);
            float4 v0 = unpack_hi(r0), v1 = unpack_hi(r1);
            float4 v2 = unpack_hi(r2), v3 = unpack_hi(r3);
            a0 = fmaf(w0, v0.x, fmaf(w1, v1.x, fmaf(w2, v2.x, fmaf(w3, v3.x, a0))));
            a1 = fmaf(w0, v0.y, fmaf(w1, v1.y, fmaf(w2, v2.y, fmaf(w3, v3.y, a1))));
            a2 = fmaf(w0, v0.z, fmaf(w1, v1.z, fmaf(w2, v2.z, fmaf(w3, v3.z, a2))));
            a3 = fmaf(w0, v0.w, fmaf(w1, v1.w, fmaf(w2, v2.w, fmaf(w3, v3.w, a3))));
        }
        for (; j < cnt; j++) {
            int s0 = __shfl_sync(0xffffffffu, myidx, j);
            uint4 r0 = *(const uint4*)(KV + (size_t)s0 * 256 + lane * 8);
            float4 k0 = unpack_lo(r0);
            float4 v0 = unpack_hi(r0);
            float d0 = q.x * k0.x + q.y * k0.y + q.z * k0.z + q.w * k0.w;
            d0 += __shfl_xor_sync(0xffffffffu, d0, 4);
            d0 += __shfl_xor_sync(0xffffffffu, d0, 2);
            d0 += __shfl_xor_sync(0xffffffffu, d0, 1);
            float w0 = __expf(d0 * scale);
            den += w0;
            a0 = fmaf(w0, v0.x, a0);
            a1 = fmaf(w0, v0.y, a1);
            a2 = fmaf(w0, v0.z, a2);
            a3 = fmaf(w0, v0.w, a3);
        }
    }

    const float rden = 1.f / (den + 1e-16f);
    a0 *= rden; a1 *= rden; a2 *= rden; a3 *= rden;

    // head mean: sum over 4 heads (lanes l, l^8, l^16, l^24 share channels)
    #pragma unroll
    for (int dd = 8; dd <= 16; dd <<= 1) {
        a0 += __shfl_xor_sync(0xffffffffu, a0, dd);
        a1 += __shfl_xor_sync(0xffffffffu, a1, dd);
        a2 += __shfl_xor_sync(0xffffffffu, a2, dd);
        a3 += __shfl_xor_sync(0xffffffffu, a3, dd);
    }

    if (lane < 8) {
        float4 sk = *(const float4*)(skip + (size_t)n * CPH + lane * 4);
        float4 o;
        o.x = fmaxf(a0 * 0.25f + sk.x, 0.f);
        o.y = fmaxf(a1 * 0.25f + sk.y, 0.f);
        o.z = fmaxf(a2 * 0.25f + sk.z, 0.f);
        o.w = fmaxf(a3 * 0.25f + sk.w, 0.f);
        if (!do_cls) {
            *(float4*)(out + (size_t)n * CPH + lane * 4) = o;
        } else {
            *(float4*)&s_h[wid][lane * 4] = o;
        }
    }

    if (do_cls) {
        __syncwarp();
        const float* h = s_h[wid];
        int c2 = 32 + (lane & 7);
        float acc1 = s_bc[lane];
        float acc2 = s_bc[c2];
        #pragma unroll 8
        for (int j = 0; j < CPH; j++) {
            float hv = h[j];
            acc1 = fmaf(hv, s_wc[j * OUTC + lane], acc1);
            acc2 = fmaf(hv, s_wc[j * OUTC + c2], acc2);
        }
        out[(size_t)n * OUTC + lane] = acc1;
        if (lane < 8) out[(size_t)n * OUTC + c2] = acc2;
    }
}

// ---------------------------------------------------------------------------
// Host orchestration
// ---------------------------------------------------------------------------
static inline unsigned int ceil_div(unsigned int a, unsigned int b) { return (a + b - 1) / b; }

extern "C" void kernel_launch(void* const* d_in, const int* in_sizes, int n_in,
                              void* d_out, int out_size) {
    const float* x   = (const float*)d_in[0];
    const void*  ei  = d_in[1];
    const float* wq1 = (const float*)d_in[2];
    const float* bq1 = (const float*)d_in[3];
    const float* wk1 = (const float*)d_in[4];
    const float* bk1 = (const float*)d_in[5];
    const float* wv1 = (const float*)d_in[6];
    const float* bv1 = (const float*)d_in[7];
    const float* ws1 = (const float*)d_in[8];
    const float* bs1 = (const float*)d_in[9];
    const float* wq2 = (const float*)d_in[10];
    const float* bq2 = (const float*)d_in[11];
    const float* wk2 = (const float*)d_in[12];
    const float* bk2 = (const float*)d_in[13];
    const float* wv2 = (const float*)d_in[14];
    const float* bv2 = (const float*)d_in[15];
    const float* ws2 = (const float*)d_in[16];
    const float* bs2 = (const float*)d_in[17];
    const float* wc  = (const float*)d_in[18];
    const float* bc  = (const float*)d_in[19];

    const int N = in_sizes[0] / FDIM;   // x is [N,128]
    const int E = in_sizes[1] / 2;      // edge_index is [2,E]

    float  *skipp, *h1p;
    __half *Qp, *KVp;
    cudaGetSymbolAddress((void**)&Qp,    g_Q);
    cudaGetSymbolAddress((void**)&KVp,   g_KV);
    cudaGetSymbolAddress((void**)&skipp, g_skip);
    cudaGetSymbolAddress((void**)&h1p,   g_h1);

    // one-time stream/event creation (resource init only)
    static cudaStream_t s_pre = nullptr;
    static cudaEvent_t  ev_fork = nullptr, ev_join = nullptr;
    static cudaEvent_t  ev_a0 = nullptr, ev_g0 = nullptr;
    if (s_pre == nullptr) {
        cudaStreamCreate(&s_pre);
        cudaEventCreateWithFlags(&ev_fork, cudaEventDisableTiming);
        cudaEventCreateWithFlags(&ev_join, cudaEventDisableTiming);
        cudaEventCreateWithFlags(&ev_a0, cudaEventDisableTiming);
        cudaEventCreateWithFlags(&ev_g0, cudaEventDisableTiming);
    }

    const int NB = (N + SCAN_B - 1) / SCAN_B;
    // chunk boundary (multiple of 128 rows)
    int Nh = ((N / 2 + 127) / 128) * 128;
    if (Nh > N) Nh = N;
    const int detect_pairs = (E < 65536) ? E : 65536;

    // fork: CSR build on s_pre, concurrent with layer-1 GEMM on default stream
    cudaEventRecord(ev_fork, 0);
    cudaStreamWaitEvent(s_pre, ev_fork, 0);
    init_pre_kernel<<<ceil_div((unsigned)N, 256u), 256, 0, s_pre>>>(N);
    detect_dtype_kernel<<<ceil_div((unsigned)detect_pairs, 256u), 256, 0, s_pre>>>(
        (const uint2*)ei, detect_pairs);
    hist_kernel<<<ceil_div((unsigned)E, 256u), 256, 0, s_pre>>>(ei, E);
    scan_p1_kernel<<<NB, SCAN_B, 0, s_pre>>>(N);
    scan_p2_kernel<<<1, SCAN_B, 0, s_pre>>>(NB);
    scan_p3_kernel<<<NB, SCAN_B, 0, s_pre>>>(N);
    scatter_kernel<<<ceil_div((unsigned)E, 256u), 256, 0, s_pre>>>(ei, E);
    cudaEventRecord(ev_join, s_pre);

    // layer-1 projections (no CSR dependency) overlap with prepro
    hmma_qkvs_kernel<<<ceil_div((unsigned)N, 128u), 256>>>(
        x, wq1, wk1, wv1, ws1, bq1, bk1, bv1, bs1, Qp, KVp, skipp, 0, N, FDIM);

    // join before attention needs the CSR
    cudaStreamWaitEvent(0, ev_join, 0);

    // layer-1 attention, chunk 0 then chunk 1; gemm2(chunk0) overlaps attn1(chunk1)
    attn_fused_kernel<<<ceil_div((unsigned)Nh, 8u), 256>>>(
        Qp, KVp, skipp, h1p, wc, bc, 0, 0, Nh, N, E);
    cudaEventRecord(ev_a0, 0);

    // gemm2 chunk 0 on s_pre (depends only on h1 rows [0,Nh))
    cudaStreamWaitEvent(s_pre, ev_a0, 0);
    hmma_qkvs_kernel<<<ceil_div((unsigned)Nh, 128u), 256, 0, s_pre>>>(
        h1p, wq2, wk2, wv2, ws2, bq2, bk2, bv2, bs2, Qp, KVp, skipp, 0, N, CPH);
    cudaEventRecord(ev_g0, s_pre);

    // attn1 chunk 1 concurrent with gemm2 chunk 0
    if (Nh < N)
        attn_fused_kernel<<<ceil_div((unsigned)(N - Nh), 8u), 256>>>(
            Qp, KVp, skipp, h1p, wc, bc, 0, Nh, N, N, E);

    // gemm2 chunk 1 (after attn1 chunk 1 in stream order)
    if (Nh < N)
        hmma_qkvs_kernel<<<ceil_div((unsigned)(N - Nh), 128u), 256>>>(
            h1p, wq2, wk2, wv2, ws2, bq2, bk2, bv2, bs2, Qp, KVp, skipp, Nh, N, CPH);

    // layer-2 attention (needs full KV => both gemm2 chunks)
    cudaStreamWaitEvent(0, ev_g0, 0);
    attn_fused_kernel<<<ceil_div((unsigned)N, 8u), 256>>>(
        Qp, KVp, skipp, (float*)d_out, wc, bc, 1, 0, N, N, E);
}